// round 2
// baseline (speedup 1.0000x reference)
#include <cuda_runtime.h>
#include <math.h>

#define SEQT 1024
#define NB   256
#define NIN  256
#define NH   512
#define NSW  128
#define NSD  64
#define NG   2048           // 4*NH
#define KZ   768            // NH + NIN
#define NTOT 2179           // 2048 gates + 128 d + 3 ctrl
#define NTOTP 2240          // padded to 35*64
#define NBLK 140            // persistent grid: 35 N-tiles x 4 M-tiles

// ---------------- device scratch (static, no allocation) ----------------
__device__ float g_Wz[NTOTP * KZ];     // combined [W_hh|W_x ; D_w|0 ; A_w|0]
__device__ float g_bz[NTOTP];          // combined biases
__device__ float g_G1[NB * NG];        // gate preacts from h,x (phase A)
__device__ float g_dv[NB * NSW];       // d = tanh(h D_w^T + D_b)
__device__ float g_ctrl[NB * 3];       // raw control logits
__device__ float g_c[NB * NH];         // LSTM cell state
__device__ float g_stk[2][NB * NSD * NSW];  // stack double buffer
__device__ unsigned g_bar[2];          // [0]=arrival counter, [1]=generation

// ---------------- packed f32x2 helpers ----------------
__device__ __forceinline__ void fma2(unsigned long long& d,
                                     const unsigned long long a,
                                     const unsigned long long b) {
    asm("fma.rn.f32x2 %0, %1, %2, %0;" : "+l"(d) : "l"(a), "l"(b));
}
__device__ __forceinline__ unsigned long long pk2(float x) {
    unsigned long long r;
    asm("mov.b64 %0, {%1, %1};" : "=l"(r) : "f"(x));
    return r;
}
__device__ __forceinline__ float2 up2(unsigned long long v) {
    float2 f;
    asm("mov.b64 {%0, %1}, %2;" : "=f"(f.x), "=f"(f.y) : "l"(v));
    return f;
}
__device__ __forceinline__ float sigf(float x) { return 1.f / (1.f + expf(-x)); }

// ---------------- software grid barrier (all NBLK blocks co-resident) ----
__device__ __forceinline__ void grid_bar(int epoch) {
    __syncthreads();
    if (threadIdx.x == 0) {
        unsigned tgt = (unsigned)(epoch + 1) * NBLK;
        unsigned old;
        asm volatile("atom.add.acq_rel.gpu.u32 %0, [%1], %2;"
                     : "=r"(old) : "l"(&g_bar[0]), "r"(1u) : "memory");
        if (old == tgt - 1u) {
            asm volatile("st.release.gpu.u32 [%0], %1;"
                         :: "l"(&g_bar[1]), "r"(tgt) : "memory");
        } else {
            unsigned g;
            do {
                asm volatile("ld.acquire.gpu.u32 %0, [%1];"
                             : "=r"(g) : "l"(&g_bar[1]) : "memory");
            } while (g < tgt);
        }
    }
    __syncthreads();
}

// ---------------- build combined weights/biases ----------------
__global__ void build_wz(const float* __restrict__ Whh, const float* __restrict__ Wih,
                         const float* __restrict__ Dw,  const float* __restrict__ Aw,
                         const float* __restrict__ bih, const float* __restrict__ bhh,
                         const float* __restrict__ Db,  const float* __restrict__ Ab) {
    const int stride = gridDim.x * blockDim.x;
    for (int i = blockIdx.x * blockDim.x + threadIdx.x; i < NTOTP * KZ; i += stride) {
        int n = i / KZ, k = i - n * KZ;
        float v = 0.f;
        if (n < NG)            v = (k < NH) ? Whh[n * NH + k] : Wih[n * (NIN + NSW) + (k - NH)];
        else if (n < NG + NSW) v = (k < NH) ? Dw[(n - NG) * NH + k] : 0.f;
        else if (n < NTOT)     v = (k < NH) ? Aw[(n - NG - NSW) * NH + k] : 0.f;
        g_Wz[i] = v;
    }
    int n = blockIdx.x * blockDim.x + threadIdx.x;
    if (n < NTOTP) {
        float b = 0.f;
        if (n < NG)            b = bih[n] + bhh[n];
        else if (n < NG + NSW) b = Db[n - NG];
        else if (n < NTOT)     b = Ab[n - NG - NSW];
        g_bz[n] = b;
    }
}

__device__ __forceinline__ void softmax3(int b, float& a_push, float& a_pop, float& a_noop) {
    float l0 = g_ctrl[b * 3 + 0], l1 = g_ctrl[b * 3 + 1], l2 = g_ctrl[b * 3 + 2];
    float mx = fmaxf(l0, fmaxf(l1, l2));
    float e0 = expf(l0 - mx), e1 = expf(l1 - mx), e2 = expf(l2 - mx);
    float inv = 1.f / (e0 + e1 + e2);
    a_push = e0 * inv; a_pop = e1 * inv; a_noop = e2 * inv;
}

// ---------------- shared memory union ----------------
struct SmA { float As[2][16][72]; float Bs[2][16][72]; };                 // 18432 B
struct SmB { float StopT[NSW][72]; float Bsh[16][72]; float cf[3][64]; }; // 42240 B

// ---------------- persistent kernel: all 1024 steps ----------------
__global__ void __launch_bounds__(256, 1) rnn_persist(
    const float* __restrict__ x, const float* __restrict__ h0,
    float* __restrict__ outs, const float* __restrict__ Wih) {
    __shared__ __align__(16) unsigned char SMRAW[sizeof(SmB)];
    SmA* sa = (SmA*)SMRAW;
    SmB* sb = (SmB*)SMRAW;

    const int tid = threadIdx.x;
    const int bx  = blockIdx.x;
    // phase A tile: 64x64, 4x4 micro per thread
    const int nT = bx % 35, mT = bx / 35;
    const int n0 = nT << 6, m0a = mT << 6;
    const int tm = tid >> 4, tn = tid & 15;
    const int lr = tid >> 2, lk = (tid & 3) << 2;
    const int mrow = m0a + lr;
    const float* __restrict__ wrow = &g_Wz[(n0 + lr) * KZ];

    int ep = 0;
    for (int t = 0; t < SEQT; t++) {
        const float* __restrict__ hprev = t ? outs + (size_t)(t - 1) * NB * NH : h0;
        const float* __restrict__ xt = x + (size_t)t * NB * NIN;

        // ======== phase A: [G1 | d | ctrl] = [h|x] @ Wz^T + bz ========
        {
            unsigned long long acc[4][2];
#pragma unroll
            for (int i = 0; i < 4; i++) { acc[i][0] = 0ull; acc[i][1] = 0ull; }

            float4 av, bv;
#define LDTILE(kt) { int k = ((kt) << 4) + lk;                                      \
        av = (k < NH) ? *(const float4*)&hprev[mrow * NH + k]                       \
                      : *(const float4*)&xt[mrow * NIN + (k - NH)];                 \
        bv = *(const float4*)&wrow[k]; }
#define STTILE(bf) { sa->As[bf][lk+0][lr]=av.x; sa->As[bf][lk+1][lr]=av.y;          \
                     sa->As[bf][lk+2][lr]=av.z; sa->As[bf][lk+3][lr]=av.w;          \
                     sa->Bs[bf][lk+0][lr]=bv.x; sa->Bs[bf][lk+1][lr]=bv.y;          \
                     sa->Bs[bf][lk+2][lr]=bv.z; sa->Bs[bf][lk+3][lr]=bv.w; }

            LDTILE(0); STTILE(0);
            __syncthreads();
            int buf = 0;
            const int NKT = KZ / 16;
            for (int kt = 0; kt < NKT; kt++) {
                if (kt + 1 < NKT) LDTILE(kt + 1);
#pragma unroll
                for (int kk = 0; kk < 16; kk++) {
                    float4 a = *(const float4*)&sa->As[buf][kk][tm << 2];
                    ulonglong2 b2 = *(const ulonglong2*)&sa->Bs[buf][kk][tn << 2];
                    unsigned long long pa;
                    pa = pk2(a.x); fma2(acc[0][0], pa, b2.x); fma2(acc[0][1], pa, b2.y);
                    pa = pk2(a.y); fma2(acc[1][0], pa, b2.x); fma2(acc[1][1], pa, b2.y);
                    pa = pk2(a.z); fma2(acc[2][0], pa, b2.x); fma2(acc[2][1], pa, b2.y);
                    pa = pk2(a.w); fma2(acc[3][0], pa, b2.x); fma2(acc[3][1], pa, b2.y);
                }
                __syncthreads();
                if (kt + 1 < NKT) { STTILE(buf ^ 1); }
                __syncthreads();
                buf ^= 1;
            }
#undef LDTILE
#undef STTILE

#pragma unroll
            for (int i = 0; i < 4; i++) {
                int m = m0a + (tm << 2) + i;
#pragma unroll
                for (int p = 0; p < 2; p++) {
                    float2 v = up2(acc[i][p]);
#pragma unroll
                    for (int q = 0; q < 2; q++) {
                        int n = n0 + (tn << 2) + (p << 1) + q;
                        float val = ((q == 0) ? v.x : v.y) + g_bz[n];
                        if (n < NG)            g_G1[m * NG + n] = val;
                        else if (n < NG + NSW) g_dv[m * NSW + (n - NG)] = tanhf(val);
                        else if (n < NTOT)     g_ctrl[m * 3 + (n - NG - NSW)] = val;
                    }
                }
            }
        }
        grid_bar(ep); ep++;

        // ======== phase B: gates + LSTM (bx<128) + stack blend (all) ========
        const float* __restrict__ sold = g_stk[t & 1];
        float* __restrict__ snew = g_stk[(t + 1) & 1];
        float* __restrict__ ht = outs + (size_t)t * NB * NH;

        if (bx < 128) {
            const int m0 = (bx >> 5) << 6;
            const int u0 = (bx & 31) << 4;
            if (tid < 64) {
                float pu, po, no; softmax3(m0 + tid, pu, po, no);
                sb->cf[0][tid] = pu; sb->cf[1][tid] = po; sb->cf[2][tid] = no;
            }
            __syncthreads();
            for (int idx = tid; idx < 64 * NSW; idx += 256) {
                int bl = idx >> 7, k = idx & 127;
                int b = m0 + bl;
                float s0 = sold[(b * NSD + 0) * NSW + k];
                float s1 = sold[(b * NSD + 1) * NSW + k];
                float dd = g_dv[b * NSW + k];
                sb->StopT[k][bl] = sb->cf[2][bl] * s0 + sb->cf[0][bl] * dd + sb->cf[1][bl] * s1;
            }
            __syncthreads();

            // col = lr: uu = lr>>2, gate g = lr&3 -> W row g*NH + u0 + uu
            const int jrow = (lr & 3) * NH + u0 + (lr >> 2);
            const float* __restrict__ wr = &Wih[jrow * (NIN + NSW) + NIN];

            unsigned long long acc[4][2];
#pragma unroll
            for (int i = 0; i < 4; i++) { acc[i][0] = 0ull; acc[i][1] = 0ull; }

            for (int k0 = 0; k0 < NSW; k0 += 16) {
                float4 bv = *(const float4*)&wr[k0 + lk];
                sb->Bsh[lk + 0][lr] = bv.x; sb->Bsh[lk + 1][lr] = bv.y;
                sb->Bsh[lk + 2][lr] = bv.z; sb->Bsh[lk + 3][lr] = bv.w;
                __syncthreads();
#pragma unroll
                for (int kk = 0; kk < 16; kk++) {
                    float4 a = *(const float4*)&sb->StopT[k0 + kk][tm << 2];
                    ulonglong2 b2 = *(const ulonglong2*)&sb->Bsh[kk][tn << 2];
                    unsigned long long pa;
                    pa = pk2(a.x); fma2(acc[0][0], pa, b2.x); fma2(acc[0][1], pa, b2.y);
                    pa = pk2(a.y); fma2(acc[1][0], pa, b2.x); fma2(acc[1][1], pa, b2.y);
                    pa = pk2(a.z); fma2(acc[2][0], pa, b2.x); fma2(acc[2][1], pa, b2.y);
                    pa = pk2(a.w); fma2(acc[3][0], pa, b2.x); fma2(acc[3][1], pa, b2.y);
                }
                __syncthreads();
            }

            const int u = u0 + tn;
#pragma unroll
            for (int i = 0; i < 4; i++) {
                int b = m0 + (tm << 2) + i;
                float2 vif = up2(acc[i][0]);   // (i, f)
                float2 vgo = up2(acc[i][1]);   // (g, o)
                float gi = vif.x + g_G1[b * NG + u];
                float gf = vif.y + g_G1[b * NG + NH + u];
                float gg = vgo.x + g_G1[b * NG + 2 * NH + u];
                float go = vgo.y + g_G1[b * NG + 3 * NH + u];
                float cn = sigf(gf) * g_c[b * NH + u] + sigf(gi) * tanhf(gg);
                float hh = sigf(go) * tanhf(cn);
                g_c[b * NH + u] = cn;
                ht[b * NH + u] = hh;
            }
        }

        // stack blend: flat float4 partition over all NBLK blocks
        {
            const long long TOTF4 = (long long)NB * NSD * (NSW / 4);  // 524288
            int lo = (int)((long long)bx * TOTF4 / NBLK);
            int hi = (int)((long long)(bx + 1) * TOTF4 / NBLK);
            const float4 z4 = make_float4(0.f, 0.f, 0.f, 0.f);
            for (int idx = lo + tid; idx < hi; idx += 256) {
                int b = idx >> 11;              // 2048 float4 per batch
                int rem = idx & 2047;
                int s = rem >> 5, w = (rem & 31) << 2;
                float pu, po, no; softmax3(b, pu, po, no);
                const float* base = &sold[(b * NSD + s) * NSW + w];
                float4 cur = *(const float4*)base;
                float4 up  = s ? *(const float4*)(base - NSW)
                               : *(const float4*)&g_dv[b * NSW + w];
                float4 dn  = (s < NSD - 1) ? *(const float4*)(base + NSW) : z4;
                float4 o;
                o.x = no * cur.x + pu * up.x + po * dn.x;
                o.y = no * cur.y + pu * up.y + po * dn.y;
                o.z = no * cur.z + pu * up.z + po * dn.z;
                o.w = no * cur.w + pu * up.w + po * dn.w;
                *(float4*)&snew[(b * NSD + s) * NSW + w] = o;
            }
        }
        grid_bar(ep); ep++;
    }
}

// ---------------- host ----------------
extern "C" void kernel_launch(void* const* d_in, const int* in_sizes, int n_in,
                              void* d_out, int out_size) {
    const float* x   = (const float*)d_in[0];
    const float* h0  = (const float*)d_in[1];
    const float* c0  = (const float*)d_in[2];
    const float* st0 = (const float*)d_in[3];
    const float* Aw  = (const float*)d_in[4];
    const float* Ab  = (const float*)d_in[5];
    const float* Dw  = (const float*)d_in[6];
    const float* Db  = (const float*)d_in[7];
    const float* Wih = (const float*)d_in[8];
    const float* Whh = (const float*)d_in[9];
    const float* bih = (const float*)d_in[10];
    const float* bhh = (const float*)d_in[11];

    float* outs  = (float*)d_out;                       // (SEQ, B, H)
    float* h_out = outs + (size_t)SEQT * NB * NH;       // (1, B, H)
    float* c_out = h_out + (size_t)NB * NH;             // (1, B, H)
    float* s_out = c_out + (size_t)NB * NH;             // (B, SD, SW)

    float* cbuf;  cudaGetSymbolAddress((void**)&cbuf, g_c);
    float* stbuf; cudaGetSymbolAddress((void**)&stbuf, g_stk);
    unsigned* barbuf; cudaGetSymbolAddress((void**)&barbuf, g_bar);

    build_wz<<<512, 256>>>(Whh, Wih, Dw, Aw, bih, bhh, Db, Ab);
    cudaMemcpyAsync(cbuf,  c0,  (size_t)NB * NH * sizeof(float),        cudaMemcpyDeviceToDevice);
    cudaMemcpyAsync(stbuf, st0, (size_t)NB * NSD * NSW * sizeof(float), cudaMemcpyDeviceToDevice);
    cudaMemsetAsync(barbuf, 0, 2 * sizeof(unsigned));

    rnn_persist<<<NBLK, 256>>>(x, h0, outs, Wih);

    const size_t SSZ = (size_t)NB * NSD * NSW;
    cudaMemcpyAsync(h_out, outs + (size_t)(SEQT - 1) * NB * NH,
                    (size_t)NB * NH * sizeof(float), cudaMemcpyDeviceToDevice);
    cudaMemcpyAsync(c_out, cbuf, (size_t)NB * NH * sizeof(float), cudaMemcpyDeviceToDevice);
    cudaMemcpyAsync(s_out, stbuf, SSZ * sizeof(float), cudaMemcpyDeviceToDevice);
}

// round 4
// speedup vs baseline: 1.7794x; 1.7794x over previous
#include <cuda_runtime.h>
#include <cuda_bf16.h>
#include <math.h>
#include <stdint.h>

#define SEQT 1024
#define NB   256
#define NIN  256
#define NH   512
#define NSW  128
#define NSD  64
#define NG   2048            // 4*NH
#define KZ   768             // NH + NIN
#define NROWS 2240           // 70*32 (2048 gates + 128 d + 3 ctrl + pad)
#define NTOT 2179
#define NBLK 140             // 70 N-tiles x 2 M-halves
#define NKC  48              // 768 / 16 k-chunks

// W fragment slice: per nT: [hl(2)][kc(48)][nt(4)][lane(32)][4 halfs] = 49152 halfs = 98304 B
#define WSLICE_H 49152
// Z fragment: [hl(2)][kc(48)][mtile(16)][lane(32)][8 halfs] = 393216 halfs
#define ZKC_H   4096          // halfs per kc   (16*32*8)
#define ZLO_H   196608        // hl=1 offset in halfs (48*4096)

// dynamic smem layout (bytes)
#define SMW     0             // 98304: resident W fragments
#define SMSTOP  98304         // float[128][72]
#define SMBSH   135168        // float[16][72]
#define SMCF    139776        // float[3][64]
#define SMTOTAL 140544

// ---- device scratch ----
__device__ __nv_bfloat16 g_Wfrag[70 * WSLICE_H];
__device__ __nv_bfloat16 g_Zfrag[2 * ZLO_H];
__device__ float g_bz[NROWS];
__device__ float g_G1[NB * NG];
__device__ float g_dv[NB * NSW];
__device__ float g_ctrl[NB * 3];
__device__ float g_c[NB * NH];
__device__ float g_stk[2][NB * NSD * NSW];
__device__ unsigned g_bar[2];

// ---- helpers ----
__device__ __forceinline__ float sigf(float x) { return 1.f / (1.f + expf(-x)); }
__device__ __forceinline__ void split_bf(float v, __nv_bfloat16& hi, __nv_bfloat16& lo) {
    hi = __float2bfloat16(v);
    lo = __float2bfloat16(v - __bfloat162float(hi));
}
__device__ __forceinline__ void fma2(unsigned long long& d, unsigned long long a, unsigned long long b) {
    asm("fma.rn.f32x2 %0, %1, %2, %0;" : "+l"(d) : "l"(a), "l"(b));
}
__device__ __forceinline__ unsigned long long pk2(float x) {
    unsigned long long r; asm("mov.b64 %0, {%1, %1};" : "=l"(r) : "f"(x)); return r;
}
__device__ __forceinline__ float2 up2(unsigned long long v) {
    float2 f; asm("mov.b64 {%0, %1}, %2;" : "=f"(f.x), "=f"(f.y) : "l"(v)); return f;
}
__device__ __forceinline__ void softmax3(int b, float& pu, float& po, float& no) {
    float l0 = __ldcg(&g_ctrl[b*3+0]), l1 = __ldcg(&g_ctrl[b*3+1]), l2 = __ldcg(&g_ctrl[b*3+2]);
    float mx = fmaxf(l0, fmaxf(l1, l2));
    float e0 = expf(l0-mx), e1 = expf(l1-mx), e2 = expf(l2-mx);
    float inv = 1.f / (e0+e1+e2);
    pu = e0*inv; po = e1*inv; no = e2*inv;
}
// write one fp32 value into hi/lo Z fragments at (batch b, k-index kk)
__device__ __forceinline__ void store_zfrag(int b, int kk, float v) {
    int kc = kk >> 4, ko = kk & 15;
    int t   = ((b & 7) << 2) | ((ko & 7) >> 1);
    int reg = ((b >> 3) & 1) | (((ko >> 3) & 1) << 1);
    int idx = ((kc * 16 + (b >> 4)) * 32 + t) * 8 + reg * 2 + (ko & 1);
    __nv_bfloat16 hi, lo; split_bf(v, hi, lo);
    g_Zfrag[idx] = hi;
    g_Zfrag[ZLO_H + idx] = lo;
}

#define MMA_BF16(acc, A, b0, b1) asm volatile( \
    "mma.sync.aligned.m16n8k16.row.col.f32.bf16.bf16.f32 " \
    "{%0,%1,%2,%3},{%4,%5,%6,%7},{%8,%9},{%0,%1,%2,%3};" \
    : "+f"(acc[0]), "+f"(acc[1]), "+f"(acc[2]), "+f"(acc[3]) \
    : "r"(A.x), "r"(A.y), "r"(A.z), "r"(A.w), "r"(b0), "r"(b1))

// ---- software grid barrier ----
__device__ __forceinline__ void grid_bar(int epoch) {
    __syncthreads();
    if (threadIdx.x == 0) {
        unsigned tgt = (unsigned)(epoch + 1) * NBLK, old;
        asm volatile("atom.add.acq_rel.gpu.u32 %0, [%1], %2;" : "=r"(old) : "l"(&g_bar[0]), "r"(1u) : "memory");
        if (old == tgt - 1u) {
            asm volatile("st.release.gpu.u32 [%0], %1;" :: "l"(&g_bar[1]), "r"(tgt) : "memory");
        } else {
            unsigned g;
            do { asm volatile("ld.acquire.gpu.u32 %0, [%1];" : "=r"(g) : "l"(&g_bar[1]) : "memory"); } while (g < tgt);
        }
    }
    __syncthreads();
}

// ================= setup =================
__device__ __forceinline__ float wval(int n, int k,
        const float* Whh, const float* Wih, const float* Dw, const float* Aw) {
    if (n < NG)        return (k < NH) ? Whh[n*NH + k] : Wih[n*(NIN+NSW) + (k-NH)];
    if (n < NG + NSW)  return (k < NH) ? Dw[(n-NG)*NH + k] : 0.f;
    if (n < NTOT)      return (k < NH) ? Aw[(n-NG-NSW)*NH + k] : 0.f;
    return 0.f;
}

__global__ void build_w(const float* __restrict__ Whh, const float* __restrict__ Wih,
                        const float* __restrict__ Dw,  const float* __restrict__ Aw,
                        const float* __restrict__ bih, const float* __restrict__ bhh,
                        const float* __restrict__ Db,  const float* __restrict__ Ab) {
    const long long TOT = 70LL * WSLICE_H;
    const int stride = gridDim.x * blockDim.x;
    for (long long i = blockIdx.x * blockDim.x + threadIdx.x; i < TOT; i += stride) {
        int s = (int)(i / WSLICE_H);
        int j = (int)(i - (long long)s * WSLICE_H);
        int half = j & 1, reg = (j >> 1) & 1;
        int t = (j >> 2) & 31;
        int nt = (j >> 7) & 3;
        int q = j >> 9;             // hl*48 + kc
        int kc = q % NKC, hl = q / NKC;
        int nrow = s * 32 + nt * 8 + (t >> 2);
        int kk = kc * 16 + (t & 3) * 2 + reg * 8 + half;
        float v = wval(nrow, kk, Whh, Wih, Dw, Aw);
        __nv_bfloat16 hi, lo; split_bf(v, hi, lo);
        g_Wfrag[i] = hl ? lo : hi;
    }
    int n = blockIdx.x * blockDim.x + threadIdx.x;
    if (n < NROWS) {
        float b = 0.f;
        if (n < NG)          b = bih[n] + bhh[n];
        else if (n < NG+NSW) b = Db[n-NG];
        else if (n < NTOT)   b = Ab[n-NG-NSW];
        g_bz[n] = b;
    }
}

__global__ void init_z(const float* __restrict__ h0, const float* __restrict__ x0) {
    const int stride = gridDim.x * blockDim.x;
    for (int i = blockIdx.x * blockDim.x + threadIdx.x; i < NB * NH; i += stride)
        store_zfrag(i >> 9, i & 511, h0[i]);
    for (int i = blockIdx.x * blockDim.x + threadIdx.x; i < NB * NIN; i += stride)
        store_zfrag(i >> 8, 512 + (i & 255), x0[i]);
}

// ================= persistent kernel =================
__global__ void __launch_bounds__(256, 1) rnn_persist(
    const float* __restrict__ x, float* __restrict__ outs, const float* __restrict__ Wih) {
    extern __shared__ char smem[];
    const int tid = threadIdx.x, bx = blockIdx.x;
    const int lane = tid & 31, w = tid >> 5;

    const int nT = bx % 70, mT = bx / 70;
    const int n0 = nT * 32;
    const int mtile = mT * 8 + w;

    // load resident W fragment slice (contiguous copy)
    {
        const uint4* src = (const uint4*)(g_Wfrag + (size_t)nT * WSLICE_H);
        uint4* dst = (uint4*)(smem + SMW);
#pragma unroll
        for (int i = 0; i < 24; i++) dst[tid + i * 256] = src[tid + i * 256];
    }
    __syncthreads();

    const char* pB = smem + SMW + lane * 8;
    const char* pA = (const char*)g_Zfrag + mtile * 512 + lane * 16;
    float* StopT = (float*)(smem + SMSTOP);
    float* Bsh   = (float*)(smem + SMBSH);
    float* cfA   = (float*)(smem + SMCF);

    const int tm = tid >> 4, tn = tid & 15;
    const int lr = tid >> 2, lk = (tid & 3) << 2;

    // epilogue constants
    const int er = lane >> 2, ec2 = (lane & 3) << 1;
    const int eb0 = mT * 128 + w * 16 + er;       // batch row (and +8)
    float bzv[4][2];
#pragma unroll
    for (int nt = 0; nt < 4; nt++) {
        int col = n0 + nt * 8 + ec2;
        bzv[nt][0] = g_bz[col]; bzv[nt][1] = g_bz[col + 1];
    }

    int ep = 0;
    for (int t = 0; t < SEQT; t++) {
        // ======== phase A: Y = Zhi*Whi + Zlo*Whi + Zhi*Wlo (mma.sync) ========
        {
            float acc[4][4];
#pragma unroll
            for (int nt = 0; nt < 4; nt++)
#pragma unroll
                for (int q = 0; q < 4; q++) acc[nt][q] = 0.f;

            uint4 abh[2], abl[2];
            abh[0] = __ldcg((const uint4*)(pA));
            abl[0] = __ldcg((const uint4*)(pA + ZLO_H * 2));
            abh[1] = __ldcg((const uint4*)(pA + 8192));
            abl[1] = __ldcg((const uint4*)(pA + ZLO_H * 2 + 8192));

            for (int kc = 0; kc < NKC; kc++) {
                uint4 Ah = abh[kc & 1], Al = abl[kc & 1];
                if (kc < NKC - 2) {
                    abh[kc & 1] = __ldcg((const uint4*)(pA + (kc + 2) * 8192));
                    abl[kc & 1] = __ldcg((const uint4*)(pA + ZLO_H * 2 + (kc + 2) * 8192));
                }
#pragma unroll
                for (int nt = 0; nt < 4; nt++) {
                    uint2 bh = *(const uint2*)(pB + ((kc * 4 + nt) << 8));
                    uint2 bl = *(const uint2*)(pB + 49152 + ((kc * 4 + nt) << 8));
                    MMA_BF16(acc[nt], Ah, bh.x, bh.y);
                    MMA_BF16(acc[nt], Al, bh.x, bh.y);
                    MMA_BF16(acc[nt], Ah, bl.x, bl.y);
                }
            }

            // ---- epilogue ----
            if (nT < 64) {
#pragma unroll
                for (int nt = 0; nt < 4; nt++) {
                    int col = n0 + nt * 8 + ec2;
                    float2 v0 = make_float2(acc[nt][0] + bzv[nt][0], acc[nt][1] + bzv[nt][1]);
                    float2 v1 = make_float2(acc[nt][2] + bzv[nt][0], acc[nt][3] + bzv[nt][1]);
                    *(float2*)&g_G1[(size_t)eb0 * NG + col] = v0;
                    *(float2*)&g_G1[(size_t)(eb0 + 8) * NG + col] = v1;
                }
            } else if (nT < 68) {
#pragma unroll
                for (int nt = 0; nt < 4; nt++) {
                    int dcol = n0 - NG + nt * 8 + ec2;
                    g_dv[eb0 * NSW + dcol]         = tanhf(acc[nt][0] + bzv[nt][0]);
                    g_dv[eb0 * NSW + dcol + 1]     = tanhf(acc[nt][1] + bzv[nt][1]);
                    g_dv[(eb0 + 8) * NSW + dcol]   = tanhf(acc[nt][2] + bzv[nt][0]);
                    g_dv[(eb0 + 8) * NSW + dcol + 1] = tanhf(acc[nt][3] + bzv[nt][1]);
                }
            } else if (nT == 68) {
                if (ec2 < 3) {
                    g_ctrl[eb0 * 3 + ec2]       = acc[0][0] + bzv[0][0];
                    g_ctrl[(eb0 + 8) * 3 + ec2] = acc[0][2] + bzv[0][0];
                }
                if (ec2 + 1 < 3) {
                    g_ctrl[eb0 * 3 + ec2 + 1]       = acc[0][1] + bzv[0][1];
                    g_ctrl[(eb0 + 8) * 3 + ec2 + 1] = acc[0][3] + bzv[0][1];
                }
            }
        }
        grid_bar(ep); ep++;

        // ======== phase B ========
        const float* __restrict__ sold = g_stk[t & 1];
        float* __restrict__ snew = g_stk[(t + 1) & 1];
        float* __restrict__ ht = outs + (size_t)t * NB * NH;

        if (bx < 128) {
            const int mb0 = (bx >> 5) << 6;
            const int u0  = (bx & 31) << 4;
            if (tid < 64) {
                float pu, po, no; softmax3(mb0 + tid, pu, po, no);
                cfA[0*64 + tid] = pu; cfA[1*64 + tid] = po; cfA[2*64 + tid] = no;
            }
            __syncthreads();
            for (int idx = tid; idx < 64 * NSW; idx += 256) {
                int bl = idx >> 7, k = idx & 127;
                int b = mb0 + bl;
                float s0 = __ldcg(&sold[(b * NSD + 0) * NSW + k]);
                float s1 = __ldcg(&sold[(b * NSD + 1) * NSW + k]);
                float dd = __ldcg(&g_dv[b * NSW + k]);
                StopT[k * 72 + bl] = cfA[2*64+bl] * s0 + cfA[0*64+bl] * dd + cfA[1*64+bl] * s1;
            }
            __syncthreads();

            const int jrow = (lr & 3) * NH + u0 + (lr >> 2);
            const float* __restrict__ wr = &Wih[jrow * (NIN + NSW) + NIN];

            unsigned long long acc[4][2];
#pragma unroll
            for (int i = 0; i < 4; i++) { acc[i][0] = 0ull; acc[i][1] = 0ull; }

            for (int k0 = 0; k0 < NSW; k0 += 16) {
                float4 bv = *(const float4*)&wr[k0 + lk];
                Bsh[(lk+0)*72 + lr] = bv.x; Bsh[(lk+1)*72 + lr] = bv.y;
                Bsh[(lk+2)*72 + lr] = bv.z; Bsh[(lk+3)*72 + lr] = bv.w;
                __syncthreads();
#pragma unroll
                for (int kk = 0; kk < 16; kk++) {
                    float4 a = *(const float4*)&StopT[(k0+kk)*72 + (tm << 2)];
                    ulonglong2 b2 = *(const ulonglong2*)&Bsh[kk*72 + (tn << 2)];
                    unsigned long long pa;
                    pa = pk2(a.x); fma2(acc[0][0], pa, b2.x); fma2(acc[0][1], pa, b2.y);
                    pa = pk2(a.y); fma2(acc[1][0], pa, b2.x); fma2(acc[1][1], pa, b2.y);
                    pa = pk2(a.z); fma2(acc[2][0], pa, b2.x); fma2(acc[2][1], pa, b2.y);
                    pa = pk2(a.w); fma2(acc[3][0], pa, b2.x); fma2(acc[3][1], pa, b2.y);
                }
                __syncthreads();
            }

            const int u = u0 + tn;
#pragma unroll
            for (int i = 0; i < 4; i++) {
                int b = mb0 + (tm << 2) + i;
                float2 vif = up2(acc[i][0]);
                float2 vgo = up2(acc[i][1]);
                float gi = vif.x + __ldcg(&g_G1[(size_t)b * NG + u]);
                float gf = vif.y + __ldcg(&g_G1[(size_t)b * NG + NH + u]);
                float gg = vgo.x + __ldcg(&g_G1[(size_t)b * NG + 2 * NH + u]);
                float go = vgo.y + __ldcg(&g_G1[(size_t)b * NG + 3 * NH + u]);
                float cn = sigf(gf) * g_c[b * NH + u] + sigf(gi) * tanhf(gg);
                float hh = sigf(go) * tanhf(cn);
                g_c[b * NH + u] = cn;
                ht[b * NH + u] = hh;
                store_zfrag(b, u, hh);
            }
        } else {
            // x conversion for t+1
            if (t + 1 < SEQT) {
                const float* __restrict__ xn = x + (size_t)(t + 1) * NB * NIN;
                for (int idx = (bx - 128) * 256 + tid; idx < NB * NIN; idx += 12 * 256) {
                    store_zfrag(idx >> 8, 512 + (idx & 255), xn[idx]);
                }
            }
        }

        // stack blend: flat float4 partition over all blocks
        {
            const long long TOTF4 = (long long)NB * NSD * (NSW / 4);
            int lo_ = (int)((long long)bx * TOTF4 / NBLK);
            int hi_ = (int)((long long)(bx + 1) * TOTF4 / NBLK);
            const float4 z4 = make_float4(0.f, 0.f, 0.f, 0.f);
            for (int idx = lo_ + tid; idx < hi_; idx += 256) {
                int b = idx >> 11;
                int rem = idx & 2047;
                int s = rem >> 5, ww = (rem & 31) << 2;
                float pu, po, no; softmax3(b, pu, po, no);
                const float* base = &sold[(b * NSD + s) * NSW + ww];
                float4 cur = __ldcg((const float4*)base);
                float4 up  = s ? __ldcg((const float4*)(base - NSW))
                               : __ldcg((const float4*)&g_dv[b * NSW + ww]);
                float4 dn  = (s < NSD - 1) ? __ldcg((const float4*)(base + NSW)) : z4;
                float4 o;
                o.x = no * cur.x + pu * up.x + po * dn.x;
                o.y = no * cur.y + pu * up.y + po * dn.y;
                o.z = no * cur.z + pu * up.z + po * dn.z;
                o.w = no * cur.w + pu * up.w + po * dn.w;
                *(float4*)&snew[(b * NSD + s) * NSW + ww] = o;
            }
        }
        grid_bar(ep); ep++;
    }
}

// ================= host =================
extern "C" void kernel_launch(void* const* d_in, const int* in_sizes, int n_in,
                              void* d_out, int out_size) {
    const float* x   = (const float*)d_in[0];
    const float* h0  = (const float*)d_in[1];
    const float* c0  = (const float*)d_in[2];
    const float* st0 = (const float*)d_in[3];
    const float* Aw  = (const float*)d_in[4];
    const float* Ab  = (const float*)d_in[5];
    const float* Dw  = (const float*)d_in[6];
    const float* Db  = (const float*)d_in[7];
    const float* Wih = (const float*)d_in[8];
    const float* Whh = (const float*)d_in[9];
    const float* bih = (const float*)d_in[10];
    const float* bhh = (const float*)d_in[11];

    float* outs  = (float*)d_out;
    float* h_out = outs + (size_t)SEQT * NB * NH;
    float* c_out = h_out + (size_t)NB * NH;
    float* s_out = c_out + (size_t)NB * NH;

    float* cbuf;  cudaGetSymbolAddress((void**)&cbuf, g_c);
    float* stbuf; cudaGetSymbolAddress((void**)&stbuf, g_stk);
    unsigned* barbuf; cudaGetSymbolAddress((void**)&barbuf, g_bar);

    cudaFuncSetAttribute(rnn_persist, cudaFuncAttributeMaxDynamicSharedMemorySize, SMTOTAL);

    build_w<<<1024, 256>>>(Whh, Wih, Dw, Aw, bih, bhh, Db, Ab);
    init_z<<<512, 256>>>(h0, x);
    cudaMemcpyAsync(cbuf,  c0,  (size_t)NB * NH * sizeof(float),        cudaMemcpyDeviceToDevice);
    cudaMemcpyAsync(stbuf, st0, (size_t)NB * NSD * NSW * sizeof(float), cudaMemcpyDeviceToDevice);
    cudaMemsetAsync(barbuf, 0, 2 * sizeof(unsigned));

    rnn_persist<<<NBLK, 256, SMTOTAL>>>(x, outs, Wih);

    const size_t SSZ = (size_t)NB * NSD * NSW;
    cudaMemcpyAsync(h_out, outs + (size_t)(SEQT - 1) * NB * NH,
                    (size_t)NB * NH * sizeof(float), cudaMemcpyDeviceToDevice);
    cudaMemcpyAsync(c_out, cbuf, (size_t)NB * NH * sizeof(float), cudaMemcpyDeviceToDevice);
    cudaMemcpyAsync(s_out, stbuf, SSZ * sizeof(float), cudaMemcpyDeviceToDevice);
}

// round 5
// speedup vs baseline: 1.9066x; 1.0715x over previous
#include <cuda_runtime.h>
#include <cuda_fp16.h>
#include <math.h>
#include <stdint.h>

#define SEQT 1024
#define NB   256
#define NIN  256
#define NH   512
#define NSW  128
#define NSD  64
#define NG   2048            // 4*NH
#define KZ   768             // NH + NIN
#define NROWS 2240           // 70*32 (2048 gates + 128 d + 3 ctrl + pad)
#define NTOT 2179
#define NBLK 140             // 70 N-tiles x 2 M-halves
#define NKC  48              // 768 / 16 k-chunks

// W fragment slice per nT: [hl(2)][kc(48)][nt(4)][lane(32)][4 halfs] = 49152 halfs = 98304 B
#define WSLICE_H 49152
// Z fragment (single fp16): [kc(48)][mtile(16)][lane(32)][8 halfs] = 196608 halfs
#define ZTOT_H  196608

// dynamic smem layout (bytes)
#define SMW     0             // 98304: resident W fragments
#define SMSTOP  98304         // float[128][72]
#define SMBSH   135168        // float[16][72]
#define SMCF    139776        // float[3][64]
#define SMTOTAL 140544

// ---- device scratch ----
__device__ __half g_Wfrag[70 * WSLICE_H];
__device__ __half g_Zfrag[ZTOT_H];
__device__ float g_bz[NROWS];
__device__ float g_G1[NB * NG];
__device__ float g_dv[NB * NSW];
__device__ float g_ctrl[NB * 3];
__device__ float g_c[NB * NH];
__device__ float g_stk[2][NB * NSD * NSW];
__device__ unsigned g_bar[2];

// ---- helpers ----
__device__ __forceinline__ float sigf(float x) { return 1.f / (1.f + expf(-x)); }
__device__ __forceinline__ void split_h(float v, __half& hi, __half& lo) {
    hi = __float2half(v);
    lo = __float2half(v - __half2float(hi));
}
__device__ __forceinline__ void fma2(unsigned long long& d, unsigned long long a, unsigned long long b) {
    asm("fma.rn.f32x2 %0, %1, %2, %0;" : "+l"(d) : "l"(a), "l"(b));
}
__device__ __forceinline__ unsigned long long pk2(float x) {
    unsigned long long r; asm("mov.b64 %0, {%1, %1};" : "=l"(r) : "f"(x)); return r;
}
__device__ __forceinline__ float2 up2(unsigned long long v) {
    float2 f; asm("mov.b64 {%0, %1}, %2;" : "=f"(f.x), "=f"(f.y) : "l"(v)); return f;
}
__device__ __forceinline__ void softmax3(int b, float& pu, float& po, float& no) {
    float l0 = __ldcg(&g_ctrl[b*3+0]), l1 = __ldcg(&g_ctrl[b*3+1]), l2 = __ldcg(&g_ctrl[b*3+2]);
    float mx = fmaxf(l0, fmaxf(l1, l2));
    float e0 = expf(l0-mx), e1 = expf(l1-mx), e2 = expf(l2-mx);
    float inv = 1.f / (e0+e1+e2);
    pu = e0*inv; po = e1*inv; no = e2*inv;
}
// write one fp32 value into the Z fragment at (batch b, k-index kk)
__device__ __forceinline__ void store_zfrag(int b, int kk, float v) {
    int kc = kk >> 4, ko = kk & 15;
    int t   = ((b & 7) << 2) | ((ko & 7) >> 1);
    int reg = ((b >> 3) & 1) | (((ko >> 3) & 1) << 1);
    int idx = ((kc * 16 + (b >> 4)) * 32 + t) * 8 + reg * 2 + (ko & 1);
    g_Zfrag[idx] = __float2half(v);
}

#define MMA_F16(acc, A, b0, b1) asm volatile( \
    "mma.sync.aligned.m16n8k16.row.col.f32.f16.f16.f32 " \
    "{%0,%1,%2,%3},{%4,%5,%6,%7},{%8,%9},{%0,%1,%2,%3};" \
    : "+f"(acc[0]), "+f"(acc[1]), "+f"(acc[2]), "+f"(acc[3]) \
    : "r"(A.x), "r"(A.y), "r"(A.z), "r"(A.w), "r"(b0), "r"(b1))

// ---- software grid barrier ----
__device__ __forceinline__ void grid_bar(int epoch) {
    __syncthreads();
    if (threadIdx.x == 0) {
        unsigned tgt = (unsigned)(epoch + 1) * NBLK, old;
        asm volatile("atom.add.acq_rel.gpu.u32 %0, [%1], %2;" : "=r"(old) : "l"(&g_bar[0]), "r"(1u) : "memory");
        if (old == tgt - 1u) {
            asm volatile("st.release.gpu.u32 [%0], %1;" :: "l"(&g_bar[1]), "r"(tgt) : "memory");
        } else {
            unsigned g;
            do { asm volatile("ld.acquire.gpu.u32 %0, [%1];" : "=r"(g) : "l"(&g_bar[1]) : "memory"); } while (g < tgt);
        }
    }
    __syncthreads();
}

// ================= setup =================
__device__ __forceinline__ float wval(int n, int k,
        const float* Whh, const float* Wih, const float* Dw, const float* Aw) {
    if (n < NG)        return (k < NH) ? Whh[n*NH + k] : Wih[n*(NIN+NSW) + (k-NH)];
    if (n < NG + NSW)  return (k < NH) ? Dw[(n-NG)*NH + k] : 0.f;
    if (n < NTOT)      return (k < NH) ? Aw[(n-NG-NSW)*NH + k] : 0.f;
    return 0.f;
}

__global__ void build_w(const float* __restrict__ Whh, const float* __restrict__ Wih,
                        const float* __restrict__ Dw,  const float* __restrict__ Aw,
                        const float* __restrict__ bih, const float* __restrict__ bhh,
                        const float* __restrict__ Db,  const float* __restrict__ Ab) {
    const long long TOT = 70LL * WSLICE_H;
    const int stride = gridDim.x * blockDim.x;
    for (long long i = blockIdx.x * blockDim.x + threadIdx.x; i < TOT; i += stride) {
        int s = (int)(i / WSLICE_H);
        int j = (int)(i - (long long)s * WSLICE_H);
        int half = j & 1, reg = (j >> 1) & 1;
        int t = (j >> 2) & 31;
        int nt = (j >> 7) & 3;
        int q = j >> 9;             // hl*48 + kc
        int kc = q % NKC, hl = q / NKC;
        int nrow = s * 32 + nt * 8 + (t >> 2);
        int kk = kc * 16 + (t & 3) * 2 + reg * 8 + half;
        float v = wval(nrow, kk, Whh, Wih, Dw, Aw);
        __half hi, lo; split_h(v, hi, lo);
        g_Wfrag[i] = hl ? lo : hi;
    }
    int n = blockIdx.x * blockDim.x + threadIdx.x;
    if (n < NROWS) {
        float b = 0.f;
        if (n < NG)          b = bih[n] + bhh[n];
        else if (n < NG+NSW) b = Db[n-NG];
        else if (n < NTOT)   b = Ab[n-NG-NSW];
        g_bz[n] = b;
    }
}

__global__ void init_z(const float* __restrict__ h0, const float* __restrict__ x0) {
    const int stride = gridDim.x * blockDim.x;
    for (int i = blockIdx.x * blockDim.x + threadIdx.x; i < NB * NH; i += stride)
        store_zfrag(i >> 9, i & 511, h0[i]);
    for (int i = blockIdx.x * blockDim.x + threadIdx.x; i < NB * NIN; i += stride)
        store_zfrag(i >> 8, 512 + (i & 255), x0[i]);
}

// ================= persistent kernel =================
__global__ void __launch_bounds__(256, 1) rnn_persist(
    const float* __restrict__ x, float* __restrict__ outs, const float* __restrict__ Wih) {
    extern __shared__ char smem[];
    const int tid = threadIdx.x, bx = blockIdx.x;
    const int lane = tid & 31, w = tid >> 5;

    const int nT = bx % 70, mT = bx / 70;
    const int n0 = nT * 32;
    const int mtile = mT * 8 + w;

    // load resident W fragment slice (contiguous copy)
    {
        const uint4* src = (const uint4*)(g_Wfrag + (size_t)nT * WSLICE_H);
        uint4* dst = (uint4*)(smem + SMW);
#pragma unroll
        for (int i = 0; i < 24; i++) dst[tid + i * 256] = src[tid + i * 256];
    }
    __syncthreads();

    const char* pB = smem + SMW + lane * 8;
    const char* pA = (const char*)g_Zfrag + mtile * 512 + lane * 16;
    float* StopT = (float*)(smem + SMSTOP);
    float* Bsh   = (float*)(smem + SMBSH);
    float* cfA   = (float*)(smem + SMCF);

    const int tm = tid >> 4, tn = tid & 15;
    const int lr = tid >> 2, lk = (tid & 3) << 2;

    // epilogue constants
    const int er = lane >> 2, ec2 = (lane & 3) << 1;
    const int eb0 = mT * 128 + w * 16 + er;       // batch row (and +8)
    float bzv[4][2];
#pragma unroll
    for (int nt = 0; nt < 4; nt++) {
        int col = n0 + nt * 8 + ec2;
        bzv[nt][0] = g_bz[col]; bzv[nt][1] = g_bz[col + 1];
    }

    int ep = 0;
    for (int t = 0; t < SEQT; t++) {
        // ======== phase A: Y = Z*Whi + Z*Wlo (fp16 mma.sync, shared A) ========
        {
            float acc[4][4];
#pragma unroll
            for (int nt = 0; nt < 4; nt++)
#pragma unroll
                for (int q = 0; q < 4; q++) acc[nt][q] = 0.f;

            uint4 ab[4];
#pragma unroll
            for (int p = 0; p < 4; p++)
                ab[p] = __ldcg((const uint4*)(pA + p * 8192));

            for (int kc = 0; kc < NKC; kc++) {
                uint4 A = ab[kc & 3];
                if (kc < NKC - 4)
                    ab[kc & 3] = __ldcg((const uint4*)(pA + (kc + 4) * 8192));
#pragma unroll
                for (int nt = 0; nt < 4; nt++) {
                    uint2 bh = *(const uint2*)(pB + ((kc * 4 + nt) << 8));
                    uint2 bl = *(const uint2*)(pB + 49152 + ((kc * 4 + nt) << 8));
                    MMA_F16(acc[nt], A, bh.x, bh.y);
                    MMA_F16(acc[nt], A, bl.x, bl.y);
                }
            }

            // ---- epilogue ----
            if (nT < 64) {
#pragma unroll
                for (int nt = 0; nt < 4; nt++) {
                    int col = n0 + nt * 8 + ec2;
                    float2 v0 = make_float2(acc[nt][0] + bzv[nt][0], acc[nt][1] + bzv[nt][1]);
                    float2 v1 = make_float2(acc[nt][2] + bzv[nt][0], acc[nt][3] + bzv[nt][1]);
                    *(float2*)&g_G1[(size_t)eb0 * NG + col] = v0;
                    *(float2*)&g_G1[(size_t)(eb0 + 8) * NG + col] = v1;
                }
            } else if (nT < 68) {
#pragma unroll
                for (int nt = 0; nt < 4; nt++) {
                    int dcol = n0 - NG + nt * 8 + ec2;
                    g_dv[eb0 * NSW + dcol]           = tanhf(acc[nt][0] + bzv[nt][0]);
                    g_dv[eb0 * NSW + dcol + 1]       = tanhf(acc[nt][1] + bzv[nt][1]);
                    g_dv[(eb0 + 8) * NSW + dcol]     = tanhf(acc[nt][2] + bzv[nt][0]);
                    g_dv[(eb0 + 8) * NSW + dcol + 1] = tanhf(acc[nt][3] + bzv[nt][1]);
                }
            } else if (nT == 68) {
                if (ec2 < 3) {
                    g_ctrl[eb0 * 3 + ec2]       = acc[0][0] + bzv[0][0];
                    g_ctrl[(eb0 + 8) * 3 + ec2] = acc[0][2] + bzv[0][0];
                }
                if (ec2 + 1 < 3) {
                    g_ctrl[eb0 * 3 + ec2 + 1]       = acc[0][1] + bzv[0][1];
                    g_ctrl[(eb0 + 8) * 3 + ec2 + 1] = acc[0][3] + bzv[0][1];
                }
            }
        }
        grid_bar(ep); ep++;

        // ======== phase B ========
        const float* __restrict__ sold = g_stk[t & 1];
        float* __restrict__ snew = g_stk[(t + 1) & 1];
        float* __restrict__ ht = outs + (size_t)t * NB * NH;

        if (bx < 128) {
            const int mb0 = (bx >> 5) << 6;
            const int u0  = (bx & 31) << 4;
            if (tid < 64) {
                float pu, po, no; softmax3(mb0 + tid, pu, po, no);
                cfA[0*64 + tid] = pu; cfA[1*64 + tid] = po; cfA[2*64 + tid] = no;
            }
            __syncthreads();
            for (int idx = tid; idx < 64 * NSW; idx += 256) {
                int bl = idx >> 7, k = idx & 127;
                int b = mb0 + bl;
                float s0 = __ldcg(&sold[(b * NSD + 0) * NSW + k]);
                float s1 = __ldcg(&sold[(b * NSD + 1) * NSW + k]);
                float dd = __ldcg(&g_dv[b * NSW + k]);
                StopT[k * 72 + bl] = cfA[2*64+bl] * s0 + cfA[0*64+bl] * dd + cfA[1*64+bl] * s1;
            }
            __syncthreads();

            const int jrow = (lr & 3) * NH + u0 + (lr >> 2);
            const float* __restrict__ wr = &Wih[jrow * (NIN + NSW) + NIN];

            unsigned long long acc[4][2];
#pragma unroll
            for (int i = 0; i < 4; i++) { acc[i][0] = 0ull; acc[i][1] = 0ull; }

            for (int k0 = 0; k0 < NSW; k0 += 16) {
                float4 bv = *(const float4*)&wr[k0 + lk];
                Bsh[(lk+0)*72 + lr] = bv.x; Bsh[(lk+1)*72 + lr] = bv.y;
                Bsh[(lk+2)*72 + lr] = bv.z; Bsh[(lk+3)*72 + lr] = bv.w;
                __syncthreads();
#pragma unroll
                for (int kk = 0; kk < 16; kk++) {
                    float4 a = *(const float4*)&StopT[(k0+kk)*72 + (tm << 2)];
                    ulonglong2 b2 = *(const ulonglong2*)&Bsh[kk*72 + (tn << 2)];
                    unsigned long long pa;
                    pa = pk2(a.x); fma2(acc[0][0], pa, b2.x); fma2(acc[0][1], pa, b2.y);
                    pa = pk2(a.y); fma2(acc[1][0], pa, b2.x); fma2(acc[1][1], pa, b2.y);
                    pa = pk2(a.z); fma2(acc[2][0], pa, b2.x); fma2(acc[2][1], pa, b2.y);
                    pa = pk2(a.w); fma2(acc[3][0], pa, b2.x); fma2(acc[3][1], pa, b2.y);
                }
                __syncthreads();
            }

            const int u = u0 + tn;
#pragma unroll
            for (int i = 0; i < 4; i++) {
                int b = mb0 + (tm << 2) + i;
                float2 vif = up2(acc[i][0]);
                float2 vgo = up2(acc[i][1]);
                float gi = vif.x + __ldcg(&g_G1[(size_t)b * NG + u]);
                float gf = vif.y + __ldcg(&g_G1[(size_t)b * NG + NH + u]);
                float gg = vgo.x + __ldcg(&g_G1[(size_t)b * NG + 2 * NH + u]);
                float go = vgo.y + __ldcg(&g_G1[(size_t)b * NG + 3 * NH + u]);
                float cn = sigf(gf) * g_c[b * NH + u] + sigf(gi) * tanhf(gg);
                float hh = sigf(go) * tanhf(cn);
                g_c[b * NH + u] = cn;
                ht[b * NH + u] = hh;
                store_zfrag(b, u, hh);
            }
        } else {
            // x conversion for t+1
            if (t + 1 < SEQT) {
                const float* __restrict__ xn = x + (size_t)(t + 1) * NB * NIN;
                for (int idx = (bx - 128) * 256 + tid; idx < NB * NIN; idx += 12 * 256) {
                    store_zfrag(idx >> 8, 512 + (idx & 255), xn[idx]);
                }
            }
        }

        // stack blend: flat float4 partition over all blocks
        {
            const long long TOTF4 = (long long)NB * NSD * (NSW / 4);
            int lo_ = (int)((long long)bx * TOTF4 / NBLK);
            int hi_ = (int)((long long)(bx + 1) * TOTF4 / NBLK);
            const float4 z4 = make_float4(0.f, 0.f, 0.f, 0.f);
            for (int idx = lo_ + tid; idx < hi_; idx += 256) {
                int b = idx >> 11;
                int rem = idx & 2047;
                int s = rem >> 5, ww = (rem & 31) << 2;
                float pu, po, no; softmax3(b, pu, po, no);
                const float* base = &sold[(b * NSD + s) * NSW + ww];
                float4 cur = __ldcg((const float4*)base);
                float4 up  = s ? __ldcg((const float4*)(base - NSW))
                               : __ldcg((const float4*)&g_dv[b * NSW + ww]);
                float4 dn  = (s < NSD - 1) ? __ldcg((const float4*)(base + NSW)) : z4;
                float4 o;
                o.x = no * cur.x + pu * up.x + po * dn.x;
                o.y = no * cur.y + pu * up.y + po * dn.y;
                o.z = no * cur.z + pu * up.z + po * dn.z;
                o.w = no * cur.w + pu * up.w + po * dn.w;
                *(float4*)&snew[(b * NSD + s) * NSW + ww] = o;
            }
        }
        grid_bar(ep); ep++;
    }
}

// ================= host =================
extern "C" void kernel_launch(void* const* d_in, const int* in_sizes, int n_in,
                              void* d_out, int out_size) {
    const float* x   = (const float*)d_in[0];
    const float* h0  = (const float*)d_in[1];
    const float* c0  = (const float*)d_in[2];
    const float* st0 = (const float*)d_in[3];
    const float* Aw  = (const float*)d_in[4];
    const float* Ab  = (const float*)d_in[5];
    const float* Dw  = (const float*)d_in[6];
    const float* Db  = (const float*)d_in[7];
    const float* Wih = (const float*)d_in[8];
    const float* Whh = (const float*)d_in[9];
    const float* bih = (const float*)d_in[10];
    const float* bhh = (const float*)d_in[11];

    float* outs  = (float*)d_out;
    float* h_out = outs + (size_t)SEQT * NB * NH;
    float* c_out = h_out + (size_t)NB * NH;
    float* s_out = c_out + (size_t)NB * NH;

    float* cbuf;  cudaGetSymbolAddress((void**)&cbuf, g_c);
    float* stbuf; cudaGetSymbolAddress((void**)&stbuf, g_stk);
    unsigned* barbuf; cudaGetSymbolAddress((void**)&barbuf, g_bar);

    cudaFuncSetAttribute(rnn_persist, cudaFuncAttributeMaxDynamicSharedMemorySize, SMTOTAL);

    build_w<<<1024, 256>>>(Whh, Wih, Dw, Aw, bih, bhh, Db, Ab);
    init_z<<<512, 256>>>(h0, x);
    cudaMemcpyAsync(cbuf,  c0,  (size_t)NB * NH * sizeof(float),        cudaMemcpyDeviceToDevice);
    cudaMemcpyAsync(stbuf, st0, (size_t)NB * NSD * NSW * sizeof(float), cudaMemcpyDeviceToDevice);
    cudaMemsetAsync(barbuf, 0, 2 * sizeof(unsigned));

    rnn_persist<<<NBLK, 256, SMTOTAL>>>(x, outs, Wih);

    const size_t SSZ = (size_t)NB * NSD * NSW;
    cudaMemcpyAsync(h_out, outs + (size_t)(SEQT - 1) * NB * NH,
                    (size_t)NB * NH * sizeof(float), cudaMemcpyDeviceToDevice);
    cudaMemcpyAsync(c_out, cbuf, (size_t)NB * NH * sizeof(float), cudaMemcpyDeviceToDevice);
    cudaMemcpyAsync(s_out, stbuf, SSZ * sizeof(float), cudaMemcpyDeviceToDevice);
}

// round 6
// speedup vs baseline: 2.7200x; 1.4266x over previous
#include <cuda_runtime.h>
#include <cuda_fp16.h>
#include <math.h>
#include <stdint.h>

#define SEQT 1024
#define NB   256
#define NIN  256
#define NH   512
#define NSW  128
#define NSD  64
#define NG   2048            // 4*NH
#define KZ   768             // NH + NIN
#define NROWS 2240
#define NTOT 2179
#define NBLK 140             // 70 N-tiles x 2 M-halves
#define NKC  48              // 768/16
#define NTHR 512
#define GSTRIDE (NBLK * NTHR)

// W fragment slice per nT: [kc(48)][nt(4)][lane(32)][hi(4)|lo(4) halfs] = 49152 halfs = 98304 B
#define WSLICE_H 49152
// Z fragment: [kc(48)][mtile(16)][lane(32)][8 halfs] = 196608 halfs
#define ZTOT_H  196608

// dynamic smem layout (bytes)
#define SMW     0             // 98304: resident W fragments
#define SMSTOP  98304         // float[128][72]
#define SMBSH   135168        // float[16][72]
#define SMCF    139776        // float[3][64]
#define SMTOTAL 140544

// ---- device scratch ----
__device__ __half g_Wfrag[70 * WSLICE_H];
__device__ __half g_Zfrag[ZTOT_H];
__device__ float g_bz[NROWS];
__device__ float g_G1[NB * NG];
__device__ float g_dv[NB * NSW];
__device__ float g_ctrl[NB * 3];
__device__ float g_c[NB * NH];
__device__ float g_stk[2][NB * NSD * NSW];
__device__ unsigned g_bar[2];

// ---- helpers ----
__device__ __forceinline__ float sigf(float x) { return 1.f / (1.f + expf(-x)); }
__device__ __forceinline__ void split_h(float v, __half& hi, __half& lo) {
    hi = __float2half(v);
    lo = __float2half(v - __half2float(hi));
}
__device__ __forceinline__ void fma2(unsigned long long& d, unsigned long long a, unsigned long long b) {
    asm("fma.rn.f32x2 %0, %1, %2, %0;" : "+l"(d) : "l"(a), "l"(b));
}
__device__ __forceinline__ unsigned long long pk2(float x) {
    unsigned long long r; asm("mov.b64 %0, {%1, %1};" : "=l"(r) : "f"(x)); return r;
}
__device__ __forceinline__ float2 up2(unsigned long long v) {
    float2 f; asm("mov.b64 {%0, %1}, %2;" : "=f"(f.x), "=f"(f.y) : "l"(v)); return f;
}
__device__ __forceinline__ void softmax3(int b, float& pu, float& po, float& no) {
    float l0 = __ldcg(&g_ctrl[b*3+0]), l1 = __ldcg(&g_ctrl[b*3+1]), l2 = __ldcg(&g_ctrl[b*3+2]);
    float mx = fmaxf(l0, fmaxf(l1, l2));
    float e0 = expf(l0-mx), e1 = expf(l1-mx), e2 = expf(l2-mx);
    float inv = 1.f / (e0+e1+e2);
    pu = e0*inv; po = e1*inv; no = e2*inv;
}
__device__ __forceinline__ void store_zfrag(int b, int kk, float v) {
    int kc = kk >> 4, ko = kk & 15;
    int t   = ((b & 7) << 2) | ((ko & 7) >> 1);
    int reg = ((b >> 3) & 1) | (((ko >> 3) & 1) << 1);
    int idx = ((kc * 16 + (b >> 4)) * 32 + t) * 8 + reg * 2 + (ko & 1);
    g_Zfrag[idx] = __float2half(v);
}

#define MMA_F16(acc, A, b0, b1) asm volatile( \
    "mma.sync.aligned.m16n8k16.row.col.f32.f16.f16.f32 " \
    "{%0,%1,%2,%3},{%4,%5,%6,%7},{%8,%9},{%0,%1,%2,%3};" \
    : "+f"(acc[0]), "+f"(acc[1]), "+f"(acc[2]), "+f"(acc[3]) \
    : "r"(A.x), "r"(A.y), "r"(A.z), "r"(A.w), "r"(b0), "r"(b1))

#define BAR1() asm volatile("bar.sync 1, 256;" ::: "memory")

// ---- software grid barrier ----
__device__ __forceinline__ void grid_bar(int epoch) {
    __syncthreads();
    if (threadIdx.x == 0) {
        unsigned tgt = (unsigned)(epoch + 1) * NBLK, old;
        asm volatile("atom.add.acq_rel.gpu.u32 %0, [%1], %2;" : "=r"(old) : "l"(&g_bar[0]), "r"(1u) : "memory");
        if (old == tgt - 1u) {
            asm volatile("st.release.gpu.u32 [%0], %1;" :: "l"(&g_bar[1]), "r"(tgt) : "memory");
        } else {
            unsigned g;
            do { asm volatile("ld.acquire.gpu.u32 %0, [%1];" : "=r"(g) : "l"(&g_bar[1]) : "memory"); } while (g < tgt);
        }
    }
    __syncthreads();
}

__device__ __forceinline__ float wval(int n, int k,
        const float* Whh, const float* Wih, const float* Dw, const float* Aw) {
    if (n < NG)        return (k < NH) ? Whh[n*NH + k] : Wih[n*(NIN+NSW) + (k-NH)];
    if (n < NG + NSW)  return (k < NH) ? Dw[(n-NG)*NH + k] : 0.f;
    if (n < NTOT)      return (k < NH) ? Aw[(n-NG-NSW)*NH + k] : 0.f;
    return 0.f;
}

// ================= persistent kernel (single kernel: setup + 1024 steps) ====
__global__ void __launch_bounds__(NTHR, 1) rnn_persist(
    const float* __restrict__ x, const float* __restrict__ h0,
    float* __restrict__ outs, const float* __restrict__ Wih,
    const float* __restrict__ Whh, const float* __restrict__ Dw,
    const float* __restrict__ Aw,  const float* __restrict__ bih,
    const float* __restrict__ bhh, const float* __restrict__ Db,
    const float* __restrict__ Ab) {
    extern __shared__ char smem[];
    const int tid = threadIdx.x, bx = blockIdx.x;
    const int lane = tid & 31, w = tid >> 5;
    const int gtid = bx * NTHR + tid;

    // ---------- setup: build W fragments (hi/lo interleaved), biases, init Z ----------
    {
        const long long WTOT = 70LL * WSLICE_H;
        for (long long i = gtid; i < WTOT; i += GSTRIDE) {
            int s = (int)(i / WSLICE_H);
            int j = (int)(i - (long long)s * WSLICE_H);
            int sub = j & 7, lane2 = (j >> 3) & 31, ntq = (j >> 8) & 3, kc = j >> 10;
            int nrow = s * 32 + ntq * 8 + (lane2 >> 2);
            int sl = sub & 3, hl = sub >> 2;
            int kk = kc * 16 + (lane2 & 3) * 2 + ((sl >> 1) << 3) + (sl & 1);
            float v = wval(nrow, kk, Whh, Wih, Dw, Aw);
            __half hi, lo; split_h(v, hi, lo);
            g_Wfrag[i] = hl ? lo : hi;
        }
        if (gtid < NROWS) {
            float b = 0.f;
            if (gtid < NG)          b = bih[gtid] + bhh[gtid];
            else if (gtid < NG+NSW) b = Db[gtid-NG];
            else if (gtid < NTOT)   b = Ab[gtid-NG-NSW];
            g_bz[gtid] = b;
        }
        for (int i = gtid; i < NB * NH; i += GSTRIDE)
            store_zfrag(i >> 9, i & 511, h0[i]);
        for (int i = gtid; i < NB * NIN; i += GSTRIDE)
            store_zfrag(i >> 8, 512 + (i & 255), x[i]);
    }
    grid_bar(0);

    const int nT = bx % 70, mT = bx / 70;
    const int n0 = nT * 32;
    const int wl = w & 7, nh = w >> 3;     // warp: mtile = mT*8+wl, nt pair = nh*2..nh*2+1
    const int mtile = mT * 8 + wl;

    // load resident W fragment slice
    {
        const uint4* src = (const uint4*)(g_Wfrag + (size_t)nT * WSLICE_H);
        uint4* dst = (uint4*)(smem + SMW);
#pragma unroll
        for (int i = 0; i < 12; i++) {
            uint4 v; const uint4* p = src + tid + i * NTHR;
            asm volatile("ld.global.cg.v4.u32 {%0,%1,%2,%3}, [%4];"
                         : "=r"(v.x), "=r"(v.y), "=r"(v.z), "=r"(v.w) : "l"(p));
            dst[tid + i * NTHR] = v;
        }
    }
    __syncthreads();

    const char* pB = smem + SMW + lane * 16;
    const char* pA = (const char*)g_Zfrag + mtile * 512 + lane * 16;
    float* StopT = (float*)(smem + SMSTOP);
    float* Bsh   = (float*)(smem + SMBSH);
    float* cfA   = (float*)(smem + SMCF);

    const int tm = tid >> 4, tn = tid & 15;
    const int lr = tid >> 2, lk = (tid & 3) << 2;

    // epilogue constants
    const int er = lane >> 2, ec2 = (lane & 3) << 1;
    const int eb0 = mT * 128 + wl * 16 + er;
    float bzv[2][2];
#pragma unroll
    for (int q = 0; q < 2; q++) {
        int col = n0 + (nh * 2 + q) * 8 + ec2;
        bzv[q][0] = g_bz[col]; bzv[q][1] = g_bz[col + 1];
    }

    int ep = 1;
    for (int t = 0; t < SEQT; t++) {
        // ======== phase A: Y = Z*Whi + Z*Wlo, warp handles 2 nt tiles ========
        {
            float acc[2][4];
#pragma unroll
            for (int q = 0; q < 2; q++)
#pragma unroll
                for (int r = 0; r < 4; r++) acc[q][r] = 0.f;

            uint4 ab[8];
#pragma unroll
            for (int p = 0; p < 8; p++)
                ab[p] = __ldcg((const uint4*)(pA + p * 8192));

            for (int kc = 0; kc < NKC; kc++) {
                uint4 A = ab[kc & 7];
                if (kc < NKC - 8)
                    ab[kc & 7] = __ldcg((const uint4*)(pA + (kc + 8) * 8192));
                const char* pk = pB + ((kc * 4 + nh * 2) << 9);
                uint4 wv0 = *(const uint4*)pk;
                uint4 wv1 = *(const uint4*)(pk + 512);
                MMA_F16(acc[0], A, wv0.x, wv0.y);
                MMA_F16(acc[1], A, wv1.x, wv1.y);
                MMA_F16(acc[0], A, wv0.z, wv0.w);
                MMA_F16(acc[1], A, wv1.z, wv1.w);
            }

            // ---- epilogue ----
            if (nT < 64) {
#pragma unroll
                for (int q = 0; q < 2; q++) {
                    int col = n0 + (nh * 2 + q) * 8 + ec2;
                    float2 v0 = make_float2(acc[q][0] + bzv[q][0], acc[q][1] + bzv[q][1]);
                    float2 v1 = make_float2(acc[q][2] + bzv[q][0], acc[q][3] + bzv[q][1]);
                    *(float2*)&g_G1[(size_t)eb0 * NG + col] = v0;
                    *(float2*)&g_G1[(size_t)(eb0 + 8) * NG + col] = v1;
                }
            } else if (nT < 68) {
#pragma unroll
                for (int q = 0; q < 2; q++) {
                    int dcol = n0 - NG + (nh * 2 + q) * 8 + ec2;
                    g_dv[eb0 * NSW + dcol]           = tanhf(acc[q][0] + bzv[q][0]);
                    g_dv[eb0 * NSW + dcol + 1]       = tanhf(acc[q][1] + bzv[q][1]);
                    g_dv[(eb0 + 8) * NSW + dcol]     = tanhf(acc[q][2] + bzv[q][0]);
                    g_dv[(eb0 + 8) * NSW + dcol + 1] = tanhf(acc[q][3] + bzv[q][1]);
                }
            } else if (nT == 68 && nh == 0) {
                if (ec2 < 3) {
                    g_ctrl[eb0 * 3 + ec2]       = acc[0][0] + bzv[0][0];
                    g_ctrl[(eb0 + 8) * 3 + ec2] = acc[0][2] + bzv[0][0];
                }
                if (ec2 + 1 < 3) {
                    g_ctrl[eb0 * 3 + ec2 + 1]       = acc[0][1] + bzv[0][1];
                    g_ctrl[(eb0 + 8) * 3 + ec2 + 1] = acc[0][3] + bzv[0][1];
                }
            }
        }
        grid_bar(ep); ep++;

        // ======== phase B (warp-specialized) ========
        const float* __restrict__ sold = g_stk[t & 1];
        float* __restrict__ snew = g_stk[(t + 1) & 1];
        float* __restrict__ ht = outs + (size_t)t * NB * NH;

        if (tid < 256) {
            if (bx < 128) {
                const int mb0 = (bx >> 5) << 6;
                const int u0  = (bx & 31) << 4;
                if (tid < 64) {
                    float pu, po, no; softmax3(mb0 + tid, pu, po, no);
                    cfA[0*64 + tid] = pu; cfA[1*64 + tid] = po; cfA[2*64 + tid] = no;
                }
                BAR1();
                for (int idx = tid; idx < 64 * NSW; idx += 256) {
                    int bl = idx >> 7, k = idx & 127;
                    int b = mb0 + bl;
                    float s0 = __ldcg(&sold[(b * NSD + 0) * NSW + k]);
                    float s1 = __ldcg(&sold[(b * NSD + 1) * NSW + k]);
                    float dd = __ldcg(&g_dv[b * NSW + k]);
                    StopT[k * 72 + bl] = cfA[2*64+bl] * s0 + cfA[0*64+bl] * dd + cfA[1*64+bl] * s1;
                }
                BAR1();

                const int jrow = (lr & 3) * NH + u0 + (lr >> 2);
                const float* __restrict__ wr = &Wih[jrow * (NIN + NSW) + NIN];

                unsigned long long acc[4][2];
#pragma unroll
                for (int i = 0; i < 4; i++) { acc[i][0] = 0ull; acc[i][1] = 0ull; }

                for (int k0 = 0; k0 < NSW; k0 += 16) {
                    float4 bv = *(const float4*)&wr[k0 + lk];
                    Bsh[(lk+0)*72 + lr] = bv.x; Bsh[(lk+1)*72 + lr] = bv.y;
                    Bsh[(lk+2)*72 + lr] = bv.z; Bsh[(lk+3)*72 + lr] = bv.w;
                    BAR1();
#pragma unroll
                    for (int kk = 0; kk < 16; kk++) {
                        float4 a = *(const float4*)&StopT[(k0+kk)*72 + (tm << 2)];
                        ulonglong2 b2 = *(const ulonglong2*)&Bsh[kk*72 + (tn << 2)];
                        unsigned long long pa;
                        pa = pk2(a.x); fma2(acc[0][0], pa, b2.x); fma2(acc[0][1], pa, b2.y);
                        pa = pk2(a.y); fma2(acc[1][0], pa, b2.x); fma2(acc[1][1], pa, b2.y);
                        pa = pk2(a.z); fma2(acc[2][0], pa, b2.x); fma2(acc[2][1], pa, b2.y);
                        pa = pk2(a.w); fma2(acc[3][0], pa, b2.x); fma2(acc[3][1], pa, b2.y);
                    }
                    BAR1();
                }

                const int u = u0 + tn;
#pragma unroll
                for (int i = 0; i < 4; i++) {
                    int b = mb0 + (tm << 2) + i;
                    float2 vif = up2(acc[i][0]);
                    float2 vgo = up2(acc[i][1]);
                    float gi = vif.x + __ldcg(&g_G1[(size_t)b * NG + u]);
                    float gf = vif.y + __ldcg(&g_G1[(size_t)b * NG + NH + u]);
                    float gg = vgo.x + __ldcg(&g_G1[(size_t)b * NG + 2 * NH + u]);
                    float go = vgo.y + __ldcg(&g_G1[(size_t)b * NG + 3 * NH + u]);
                    float cn = sigf(gf) * g_c[b * NH + u] + sigf(gi) * tanhf(gg);
                    float hh = sigf(go) * tanhf(cn);
                    g_c[b * NH + u] = cn;
                    ht[b * NH + u] = hh;
                    store_zfrag(b, u, hh);
                }
            } else {
                // x conversion for t+1 (blocks 128..139, lower half)
                if (t + 1 < SEQT) {
                    const float* __restrict__ xn = x + (size_t)(t + 1) * NB * NIN;
                    for (int idx = (bx - 128) * 256 + tid; idx < NB * NIN; idx += 12 * 256)
                        store_zfrag(idx >> 8, 512 + (idx & 255), xn[idx]);
                }
            }
        } else {
            // stack blend: upper 256 threads of every block
            const int ut = tid - 256;
            const long long TOTF4 = (long long)NB * NSD * (NSW / 4);
            int lo_ = (int)((long long)bx * TOTF4 / NBLK);
            int hi_ = (int)((long long)(bx + 1) * TOTF4 / NBLK);
            const float4 z4 = make_float4(0.f, 0.f, 0.f, 0.f);
            for (int idx = lo_ + ut; idx < hi_; idx += 256) {
                int b = idx >> 11;
                int rem = idx & 2047;
                int s = rem >> 5, ww = (rem & 31) << 2;
                float pu, po, no; softmax3(b, pu, po, no);
                const float* base = &sold[(b * NSD + s) * NSW + ww];
                float4 cur = __ldcg((const float4*)base);
                float4 up  = s ? __ldcg((const float4*)(base - NSW))
                               : __ldcg((const float4*)&g_dv[b * NSW + ww]);
                float4 dn  = (s < NSD - 1) ? __ldcg((const float4*)(base + NSW)) : z4;
                float4 o;
                o.x = no * cur.x + pu * up.x + po * dn.x;
                o.y = no * cur.y + pu * up.y + po * dn.y;
                o.z = no * cur.z + pu * up.z + po * dn.z;
                o.w = no * cur.w + pu * up.w + po * dn.w;
                *(float4*)&snew[(b * NSD + s) * NSW + ww] = o;
            }
        }
        grid_bar(ep); ep++;
    }
}

// ================= host =================
extern "C" void kernel_launch(void* const* d_in, const int* in_sizes, int n_in,
                              void* d_out, int out_size) {
    const float* x   = (const float*)d_in[0];
    const float* h0  = (const float*)d_in[1];
    const float* c0  = (const float*)d_in[2];
    const float* st0 = (const float*)d_in[3];
    const float* Aw  = (const float*)d_in[4];
    const float* Ab  = (const float*)d_in[5];
    const float* Dw  = (const float*)d_in[6];
    const float* Db  = (const float*)d_in[7];
    const float* Wih = (const float*)d_in[8];
    const float* Whh = (const float*)d_in[9];
    const float* bih = (const float*)d_in[10];
    const float* bhh = (const float*)d_in[11];

    float* outs  = (float*)d_out;
    float* h_out = outs + (size_t)SEQT * NB * NH;
    float* c_out = h_out + (size_t)NB * NH;
    float* s_out = c_out + (size_t)NB * NH;

    float* cbuf;  cudaGetSymbolAddress((void**)&cbuf, g_c);
    float* stbuf; cudaGetSymbolAddress((void**)&stbuf, g_stk);
    unsigned* barbuf; cudaGetSymbolAddress((void**)&barbuf, g_bar);

    cudaFuncSetAttribute(rnn_persist, cudaFuncAttributeMaxDynamicSharedMemorySize, SMTOTAL);

    cudaMemcpyAsync(cbuf,  c0,  (size_t)NB * NH * sizeof(float),        cudaMemcpyDeviceToDevice);
    cudaMemcpyAsync(stbuf, st0, (size_t)NB * NSD * NSW * sizeof(float), cudaMemcpyDeviceToDevice);
    cudaMemsetAsync(barbuf, 0, 2 * sizeof(unsigned));

    rnn_persist<<<NBLK, NTHR, SMTOTAL>>>(x, h0, outs, Wih, Whh, Dw, Aw, bih, bhh, Db, Ab);

    const size_t SSZ = (size_t)NB * NSD * NSW;
    cudaMemcpyAsync(h_out, outs + (size_t)(SEQT - 1) * NB * NH,
                    (size_t)NB * NH * sizeof(float), cudaMemcpyDeviceToDevice);
    cudaMemcpyAsync(c_out, cbuf, (size_t)NB * NH * sizeof(float), cudaMemcpyDeviceToDevice);
    cudaMemcpyAsync(s_out, stbuf, SSZ * sizeof(float), cudaMemcpyDeviceToDevice);
}

// round 7
// speedup vs baseline: 2.8864x; 1.0612x over previous
#include <cuda_runtime.h>
#include <cuda_fp16.h>
#include <math.h>
#include <stdint.h>

#define SEQT 1024
#define NB   256
#define NIN  256
#define NH   512
#define NSW  128
#define NSD  64
#define NG   2048            // 4*NH
#define KZ   768             // NH + NIN
#define NROWS 2240
#define NTOT 2179
#define NBLK 140             // 70 N-tiles x 2 M-halves
#define NKC  48              // 768/16
#define NTHR 512
#define GSTRIDE (NBLK * NTHR)

// phase A W fragment slice per nT: [kc(48)][nt(4)][lane(32)][hi(4)|lo(4)] = 49152 halfs
#define WSLICE_H 49152
// Z fragment: [kc(48)][mtile(16)][lane(32)][8 halfs] = 196608 halfs
#define ZTOT_H  196608
// phase B W_s fragment slice per u0: [kc(8)][nt(8)][lane(32)][hi(4)|lo(4)] = 16384 halfs
#define WS_H 16384

// dynamic smem layout (bytes)
#define SMW     0                  // 98304: phase A W fragments
#define SMWS    98304              // 32768: phase B W_s fragments
#define SMSF    131072             // 16384: stack_top fp16 A fragments
#define SMGT    147456             // 16384: gates f32 [64][64]
#define SMCF    163840             // 768:   cf[3][64]
#define SMTOTAL 164608

// ---- device scratch ----
__device__ __half g_Wfrag[70 * WSLICE_H];
__device__ __half g_WSfrag[32 * WS_H];
__device__ __half g_Zfrag[ZTOT_H];
__device__ float g_bz[NROWS];
__device__ float g_G1[NB * NG];
__device__ float g_dv[NB * NSW];
__device__ float g_ctrl[NB * 3];
__device__ float g_c[NB * NH];
__device__ float g_stk[2][NB * NSD * NSW];
__device__ unsigned g_bar[2];

// ---- helpers ----
__device__ __forceinline__ float sigf(float x) { return 1.f / (1.f + expf(-x)); }
__device__ __forceinline__ void split_h(float v, __half& hi, __half& lo) {
    hi = __float2half(v);
    lo = __float2half(v - __half2float(hi));
}
__device__ __forceinline__ void softmax3(int b, float& pu, float& po, float& no) {
    float l0 = __ldcg(&g_ctrl[b*3+0]), l1 = __ldcg(&g_ctrl[b*3+1]), l2 = __ldcg(&g_ctrl[b*3+2]);
    float mx = fmaxf(l0, fmaxf(l1, l2));
    float e0 = expf(l0-mx), e1 = expf(l1-mx), e2 = expf(l2-mx);
    float inv = 1.f / (e0+e1+e2);
    pu = e0*inv; po = e1*inv; no = e2*inv;
}
__device__ __forceinline__ void store_zfrag(int b, int kk, float v) {
    int kc = kk >> 4, ko = kk & 15;
    int t   = ((b & 7) << 2) | ((ko & 7) >> 1);
    int reg = ((b >> 3) & 1) | (((ko >> 3) & 1) << 1);
    int idx = ((kc * 16 + (b >> 4)) * 32 + t) * 8 + reg * 2 + (ko & 1);
    g_Zfrag[idx] = __float2half(v);
}
// stack_top fp16 A-fragment store (local 64 batches x 128 k)
__device__ __forceinline__ void store_sfrag(__half* base, int bl, int k, float v) {
    int kc = k >> 4, ko = k & 15;
    int mt = bl >> 4, bm = bl & 15;
    int t   = ((bm & 7) << 2) | ((ko & 7) >> 1);
    int reg = ((bm >> 3) & 1) | (((ko >> 3) & 1) << 1);
    int idx = ((kc * 4 + mt) * 32 + t) * 8 + reg * 2 + (ko & 1);
    base[idx] = __float2half(v);
}

#define MMA_F16(acc, A, b0, b1) asm volatile( \
    "mma.sync.aligned.m16n8k16.row.col.f32.f16.f16.f32 " \
    "{%0,%1,%2,%3},{%4,%5,%6,%7},{%8,%9},{%0,%1,%2,%3};" \
    : "+f"(acc[0]), "+f"(acc[1]), "+f"(acc[2]), "+f"(acc[3]) \
    : "r"(A.x), "r"(A.y), "r"(A.z), "r"(A.w), "r"(b0), "r"(b1))

#define BAR1() asm volatile("bar.sync 1, 256;" ::: "memory")

// ---- software grid barrier ----
__device__ __forceinline__ void grid_bar(int epoch) {
    __syncthreads();
    if (threadIdx.x == 0) {
        unsigned tgt = (unsigned)(epoch + 1) * NBLK, old;
        asm volatile("atom.add.acq_rel.gpu.u32 %0, [%1], %2;" : "=r"(old) : "l"(&g_bar[0]), "r"(1u) : "memory");
        if (old == tgt - 1u) {
            asm volatile("st.release.gpu.u32 [%0], %1;" :: "l"(&g_bar[1]), "r"(tgt) : "memory");
        } else {
            unsigned g;
            do { asm volatile("ld.acquire.gpu.u32 %0, [%1];" : "=r"(g) : "l"(&g_bar[1]) : "memory"); } while (g < tgt);
        }
    }
    __syncthreads();
}

__device__ __forceinline__ float wval(int n, int k,
        const float* Whh, const float* Wih, const float* Dw, const float* Aw) {
    if (n < NG)        return (k < NH) ? Whh[n*NH + k] : Wih[n*(NIN+NSW) + (k-NH)];
    if (n < NG + NSW)  return (k < NH) ? Dw[(n-NG)*NH + k] : 0.f;
    if (n < NTOT)      return (k < NH) ? Aw[(n-NG-NSW)*NH + k] : 0.f;
    return 0.f;
}

// ================= persistent kernel =================
__global__ void __launch_bounds__(NTHR, 1) rnn_persist(
    const float* __restrict__ x, const float* __restrict__ h0,
    float* __restrict__ outs, const float* __restrict__ Wih,
    const float* __restrict__ Whh, const float* __restrict__ Dw,
    const float* __restrict__ Aw,  const float* __restrict__ bih,
    const float* __restrict__ bhh, const float* __restrict__ Db,
    const float* __restrict__ Ab) {
    extern __shared__ char smem[];
    const int tid = threadIdx.x, bx = blockIdx.x;
    const int lane = tid & 31, w = tid >> 5;
    const int gtid = bx * NTHR + tid;

    // ---------- setup ----------
    {
        const long long WTOT = 70LL * WSLICE_H;
        for (long long i = gtid; i < WTOT; i += GSTRIDE) {
            int s = (int)(i / WSLICE_H);
            int j = (int)(i - (long long)s * WSLICE_H);
            int sub = j & 7, lane2 = (j >> 3) & 31, ntq = (j >> 8) & 3, kc = j >> 10;
            int nrow = s * 32 + ntq * 8 + (lane2 >> 2);
            int sl = sub & 3, hl = sub >> 2;
            int kk = kc * 16 + (lane2 & 3) * 2 + ((sl >> 1) << 3) + (sl & 1);
            float v = wval(nrow, kk, Whh, Wih, Dw, Aw);
            __half hi, lo; split_h(v, hi, lo);
            g_Wfrag[i] = hl ? lo : hi;
        }
        // W_s fragments: 32 slices x [kc(8)][nt(8)][lane(32)][hi4|lo4]
        for (int i = gtid; i < 32 * WS_H; i += GSTRIDE) {
            int s = i >> 14, j = i & (WS_H - 1);
            int sub = j & 7, lane2 = (j >> 3) & 31, nt = (j >> 8) & 7, kc = j >> 11;
            int col = nt * 8 + (lane2 >> 2);
            int g = col >> 4, uu = col & 15;
            int jrow = g * NH + s * 16 + uu;
            int hl = sub >> 2, jj = sub & 3;
            int kk = kc * 16 + (lane2 & 3) * 2 + ((jj >> 1) << 3) + (jj & 1);
            float v = Wih[jrow * (NIN + NSW) + NIN + kk];
            __half hi, lo; split_h(v, hi, lo);
            g_WSfrag[i] = hl ? lo : hi;
        }
        if (gtid < NROWS) {
            float b = 0.f;
            if (gtid < NG)          b = bih[gtid] + bhh[gtid];
            else if (gtid < NG+NSW) b = Db[gtid-NG];
            else if (gtid < NTOT)   b = Ab[gtid-NG-NSW];
            g_bz[gtid] = b;
        }
        for (int i = gtid; i < NB * NH; i += GSTRIDE)
            store_zfrag(i >> 9, i & 511, h0[i]);
        for (int i = gtid; i < NB * NIN; i += GSTRIDE)
            store_zfrag(i >> 8, 512 + (i & 255), x[i]);
    }
    grid_bar(0);

    const int nT = bx % 70, mT = bx / 70;
    const int n0 = nT * 32;
    const int wl = w & 7, nh = w >> 3;
    const int mtile = mT * 8 + wl;

    // load resident phase-A W slice
    {
        const uint4* src = (const uint4*)(g_Wfrag + (size_t)nT * WSLICE_H);
        uint4* dst = (uint4*)(smem + SMW);
#pragma unroll
        for (int i = 0; i < 12; i++) {
            uint4 v; const uint4* p = src + tid + i * NTHR;
            asm volatile("ld.global.cg.v4.u32 {%0,%1,%2,%3}, [%4];"
                         : "=r"(v.x), "=r"(v.y), "=r"(v.z), "=r"(v.w) : "l"(p));
            dst[tid + i * NTHR] = v;
        }
    }
    // gates CTAs: load resident W_s slice
    if (bx < 128) {
        const uint4* src = (const uint4*)(g_WSfrag + (size_t)(bx & 31) * WS_H);
        uint4* dst = (uint4*)(smem + SMWS);
#pragma unroll
        for (int i = 0; i < 4; i++) {
            uint4 v; const uint4* p = src + tid + i * NTHR;
            asm volatile("ld.global.cg.v4.u32 {%0,%1,%2,%3}, [%4];"
                         : "=r"(v.x), "=r"(v.y), "=r"(v.z), "=r"(v.w) : "l"(p));
            dst[tid + i * NTHR] = v;
        }
    }
    __syncthreads();

    const char* pB = smem + SMW + lane * 16;
    const char* pA = (const char*)g_Zfrag + mtile * 512 + lane * 16;
    __half* Sfrag  = (__half*)(smem + SMSF);
    float*  gates_s = (float*)(smem + SMGT);
    float*  cfA    = (float*)(smem + SMCF);

    // phase A epilogue constants
    const int er = lane >> 2, ec2 = (lane & 3) << 1;
    const int eb0 = mT * 128 + wl * 16 + er;
    float bzv[2][2];
#pragma unroll
    for (int q = 0; q < 2; q++) {
        int col = n0 + (nh * 2 + q) * 8 + ec2;
        bzv[q][0] = g_bz[col]; bzv[q][1] = g_bz[col + 1];
    }

    int ep = 1;
    for (int t = 0; t < SEQT; t++) {
        // ======== phase A ========
        {
            float acc[2][4];
#pragma unroll
            for (int q = 0; q < 2; q++)
#pragma unroll
                for (int r = 0; r < 4; r++) acc[q][r] = 0.f;

            uint4 ab[8];
#pragma unroll
            for (int p = 0; p < 8; p++)
                ab[p] = __ldcg((const uint4*)(pA + p * 8192));

            for (int kc = 0; kc < NKC; kc++) {
                uint4 A = ab[kc & 7];
                if (kc < NKC - 8)
                    ab[kc & 7] = __ldcg((const uint4*)(pA + (kc + 8) * 8192));
                const char* pk = pB + ((kc * 4 + nh * 2) << 9);
                uint4 wv0 = *(const uint4*)pk;
                uint4 wv1 = *(const uint4*)(pk + 512);
                MMA_F16(acc[0], A, wv0.x, wv0.y);
                MMA_F16(acc[1], A, wv1.x, wv1.y);
                MMA_F16(acc[0], A, wv0.z, wv0.w);
                MMA_F16(acc[1], A, wv1.z, wv1.w);
            }

            if (nT < 64) {
#pragma unroll
                for (int q = 0; q < 2; q++) {
                    int col = n0 + (nh * 2 + q) * 8 + ec2;
                    float2 v0 = make_float2(acc[q][0] + bzv[q][0], acc[q][1] + bzv[q][1]);
                    float2 v1 = make_float2(acc[q][2] + bzv[q][0], acc[q][3] + bzv[q][1]);
                    *(float2*)&g_G1[(size_t)eb0 * NG + col] = v0;
                    *(float2*)&g_G1[(size_t)(eb0 + 8) * NG + col] = v1;
                }
            } else if (nT < 68) {
#pragma unroll
                for (int q = 0; q < 2; q++) {
                    int dcol = n0 - NG + (nh * 2 + q) * 8 + ec2;
                    g_dv[eb0 * NSW + dcol]           = tanhf(acc[q][0] + bzv[q][0]);
                    g_dv[eb0 * NSW + dcol + 1]       = tanhf(acc[q][1] + bzv[q][1]);
                    g_dv[(eb0 + 8) * NSW + dcol]     = tanhf(acc[q][2] + bzv[q][0]);
                    g_dv[(eb0 + 8) * NSW + dcol + 1] = tanhf(acc[q][3] + bzv[q][1]);
                }
            } else if (nT == 68 && nh == 0) {
                if (ec2 < 3) {
                    g_ctrl[eb0 * 3 + ec2]       = acc[0][0] + bzv[0][0];
                    g_ctrl[(eb0 + 8) * 3 + ec2] = acc[0][2] + bzv[0][0];
                }
                if (ec2 + 1 < 3) {
                    g_ctrl[eb0 * 3 + ec2 + 1]       = acc[0][1] + bzv[0][1];
                    g_ctrl[(eb0 + 8) * 3 + ec2 + 1] = acc[0][3] + bzv[0][1];
                }
            }
        }
        grid_bar(ep); ep++;

        // ======== phase B ========
        const float* __restrict__ sold = g_stk[t & 1];
        float* __restrict__ snew = g_stk[(t + 1) & 1];
        float* __restrict__ ht = outs + (size_t)t * NB * NH;

        if (tid < 256) {
            if (bx < 128) {
                const int mb0 = (bx >> 5) << 6;
                const int u0  = (bx & 31) << 4;
                if (tid < 64) {
                    float pu, po, no; softmax3(mb0 + tid, pu, po, no);
                    cfA[0*64 + tid] = pu; cfA[1*64 + tid] = po; cfA[2*64 + tid] = no;
                }
                BAR1();
                // stack_top -> fp16 A fragments
                for (int idx = tid; idx < 64 * NSW; idx += 256) {
                    int bl = idx >> 7, k = idx & 127;
                    int b = mb0 + bl;
                    float s0 = __ldcg(&sold[(b * NSD + 0) * NSW + k]);
                    float s1 = __ldcg(&sold[(b * NSD + 1) * NSW + k]);
                    float dd = __ldcg(&g_dv[b * NSW + k]);
                    store_sfrag(Sfrag, bl, k,
                                cfA[2*64+bl] * s0 + cfA[0*64+bl] * dd + cfA[1*64+bl] * s1);
                }
                BAR1();

                // gates GEMM on tensor pipe: [64 x 64] = S[64x128] @ Ws^T
                {
                    const int w8 = tid >> 5;
                    const int mt = w8 & 3, ntb = (w8 >> 2) * 4;
                    float acc[4][4];
#pragma unroll
                    for (int q = 0; q < 4; q++)
#pragma unroll
                        for (int r = 0; r < 4; r++) acc[q][r] = 0.f;
#pragma unroll
                    for (int kc = 0; kc < 8; kc++) {
                        uint4 A = *(const uint4*)(smem + SMSF + ((kc * 4 + mt) << 9) + lane * 16);
#pragma unroll
                        for (int q = 0; q < 4; q++) {
                            uint4 wv = *(const uint4*)(smem + SMWS + (((kc * 8 + ntb + q) * 32 + lane) << 4));
                            MMA_F16(acc[q], A, wv.x, wv.y);
                            MMA_F16(acc[q], A, wv.z, wv.w);
                        }
                    }
                    const int r0 = mt * 16 + er;
#pragma unroll
                    for (int q = 0; q < 4; q++) {
                        int col = (ntb + q) * 8 + ec2;
                        *(float2*)&gates_s[r0 * 64 + col]       = make_float2(acc[q][0], acc[q][1]);
                        *(float2*)&gates_s[(r0 + 8) * 64 + col] = make_float2(acc[q][2], acc[q][3]);
                    }
                }
                BAR1();

                // LSTM pointwise: 4 (bl,uu) pairs per thread
#pragma unroll
                for (int j = 0; j < 4; j++) {
                    int p = tid + j * 256;
                    int bl = p >> 4, uu = p & 15;
                    int b = mb0 + bl, u = u0 + uu;
                    float gi = gates_s[bl * 64 + uu]      + __ldcg(&g_G1[(size_t)b * NG + u]);
                    float gf = gates_s[bl * 64 + 16 + uu] + __ldcg(&g_G1[(size_t)b * NG + NH + u]);
                    float gg = gates_s[bl * 64 + 32 + uu] + __ldcg(&g_G1[(size_t)b * NG + 2 * NH + u]);
                    float go = gates_s[bl * 64 + 48 + uu] + __ldcg(&g_G1[(size_t)b * NG + 3 * NH + u]);
                    float cn = sigf(gf) * g_c[b * NH + u] + sigf(gi) * tanhf(gg);
                    float hh = sigf(go) * tanhf(cn);
                    g_c[b * NH + u] = cn;
                    ht[b * NH + u] = hh;
                    store_zfrag(b, u, hh);
                }
            } else {
                if (t + 1 < SEQT) {
                    const float* __restrict__ xn = x + (size_t)(t + 1) * NB * NIN;
                    for (int idx = (bx - 128) * 256 + tid; idx < NB * NIN; idx += 12 * 256)
                        store_zfrag(idx >> 8, 512 + (idx & 255), xn[idx]);
                }
            }
        } else {
            // stack blend: upper 256 threads of every block
            const int ut = tid - 256;
            const long long TOTF4 = (long long)NB * NSD * (NSW / 4);
            int lo_ = (int)((long long)bx * TOTF4 / NBLK);
            int hi_ = (int)((long long)(bx + 1) * TOTF4 / NBLK);
            const float4 z4 = make_float4(0.f, 0.f, 0.f, 0.f);
            for (int idx = lo_ + ut; idx < hi_; idx += 256) {
                int b = idx >> 11;
                int rem = idx & 2047;
                int s = rem >> 5, ww = (rem & 31) << 2;
                float pu, po, no; softmax3(b, pu, po, no);
                const float* base = &sold[(b * NSD + s) * NSW + ww];
                float4 cur = __ldcg((const float4*)base);
                float4 up  = s ? __ldcg((const float4*)(base - NSW))
                               : __ldcg((const float4*)&g_dv[b * NSW + ww]);
                float4 dn  = (s < NSD - 1) ? __ldcg((const float4*)(base + NSW)) : z4;
                float4 o;
                o.x = no * cur.x + pu * up.x + po * dn.x;
                o.y = no * cur.y + pu * up.y + po * dn.y;
                o.z = no * cur.z + pu * up.z + po * dn.z;
                o.w = no * cur.w + pu * up.w + po * dn.w;
                *(float4*)&snew[(b * NSD + s) * NSW + ww] = o;
            }
        }
        grid_bar(ep); ep++;
    }
}

// ================= host =================
extern "C" void kernel_launch(void* const* d_in, const int* in_sizes, int n_in,
                              void* d_out, int out_size) {
    const float* x   = (const float*)d_in[0];
    const float* h0  = (const float*)d_in[1];
    const float* c0  = (const float*)d_in[2];
    const float* st0 = (const float*)d_in[3];
    const float* Aw  = (const float*)d_in[4];
    const float* Ab  = (const float*)d_in[5];
    const float* Dw  = (const float*)d_in[6];
    const float* Db  = (const float*)d_in[7];
    const float* Wih = (const float*)d_in[8];
    const float* Whh = (const float*)d_in[9];
    const float* bih = (const float*)d_in[10];
    const float* bhh = (const float*)d_in[11];

    float* outs  = (float*)d_out;
    float* h_out = outs + (size_t)SEQT * NB * NH;
    float* c_out = h_out + (size_t)NB * NH;
    float* s_out = c_out + (size_t)NB * NH;

    float* cbuf;  cudaGetSymbolAddress((void**)&cbuf, g_c);
    float* stbuf; cudaGetSymbolAddress((void**)&stbuf, g_stk);
    unsigned* barbuf; cudaGetSymbolAddress((void**)&barbuf, g_bar);

    cudaFuncSetAttribute(rnn_persist, cudaFuncAttributeMaxDynamicSharedMemorySize, SMTOTAL);

    cudaMemcpyAsync(cbuf,  c0,  (size_t)NB * NH * sizeof(float),        cudaMemcpyDeviceToDevice);
    cudaMemcpyAsync(stbuf, st0, (size_t)NB * NSD * NSW * sizeof(float), cudaMemcpyDeviceToDevice);
    cudaMemsetAsync(barbuf, 0, 2 * sizeof(unsigned));

    rnn_persist<<<NBLK, NTHR, SMTOTAL>>>(x, h0, outs, Wih, Whh, Dw, Aw, bih, bhh, Db, Ab);

    const size_t SSZ = (size_t)NB * NSD * NSW;
    cudaMemcpyAsync(h_out, outs + (size_t)(SEQT - 1) * NB * NH,
                    (size_t)NB * NH * sizeof(float), cudaMemcpyDeviceToDevice);
    cudaMemcpyAsync(c_out, cbuf, (size_t)NB * NH * sizeof(float), cudaMemcpyDeviceToDevice);
    cudaMemcpyAsync(s_out, stbuf, SSZ * sizeof(float), cudaMemcpyDeviceToDevice);
}

// round 8
// speedup vs baseline: 3.2154x; 1.1140x over previous
#include <cuda_runtime.h>
#include <cuda_fp16.h>
#include <math.h>
#include <stdint.h>

#define SEQT 1024
#define NB   256
#define NIN  256
#define NH   512
#define NSW  128
#define NSD  64
#define NG   2048            // 4*NH
#define KZ   768             // NH + NIN
#define NROWS 2240
#define NTOT 2179
#define NBLK 140             // 70 N-tiles x 2 M-halves
#define NKC  48              // 768/16
#define NTHR 512
#define GSTRIDE (NBLK * NTHR)

// phase A W fragment slice per nT (fp16, single): [kc(48)][nh(2)][lane(32)][8 halfs] = 24576 halfs = 49152 B
#define WSLICE_H 24576
// Z fragment: [kc(48)][mtile(16)][lane(32)][8 halfs] = 196608 halfs
#define ZTOT_H  196608
// phase B W_s fragment slice per u0: [kc(8)][ntp(4)][lane(32)][8 halfs] = 8192 halfs = 16384 B
#define WS_H 8192

// dynamic smem layout (bytes)
#define SMW     0                  // 49152: phase A W fragments
#define SMWS    49152              // 16384: phase B W_s fragments
#define SMSF    65536              // 16384: stack_top fp16 A fragments
#define SMGT    81920              // 16384: gates f32 [64][64]
#define SMCF    98304              // 768:   cf[3][64]
#define SMTOTAL 99072

// ---- device scratch ----
__device__ __half g_Wfrag[70 * WSLICE_H];
__device__ __half g_WSfrag[32 * WS_H];
__device__ __half g_Zfrag[ZTOT_H];
__device__ float g_bz[NROWS];
__device__ float g_G1[NB * NG];
__device__ float g_dv[NB * NSW];
__device__ float g_ctrl[NB * 3];
__device__ float g_c[NB * NH];
__device__ float g_stk[2][NB * NSD * NSW];
__device__ unsigned g_bar[2];

// ---- helpers ----
__device__ __forceinline__ float sigf(float x) { return 1.f / (1.f + expf(-x)); }
__device__ __forceinline__ void softmax3(int b, float& pu, float& po, float& no) {
    float l0 = __ldcg(&g_ctrl[b*3+0]), l1 = __ldcg(&g_ctrl[b*3+1]), l2 = __ldcg(&g_ctrl[b*3+2]);
    float mx = fmaxf(l0, fmaxf(l1, l2));
    float e0 = expf(l0-mx), e1 = expf(l1-mx), e2 = expf(l2-mx);
    float inv = 1.f / (e0+e1+e2);
    pu = e0*inv; po = e1*inv; no = e2*inv;
}
__device__ __forceinline__ void store_zfrag(int b, int kk, float v) {
    int kc = kk >> 4, ko = kk & 15;
    int t   = ((b & 7) << 2) | ((ko & 7) >> 1);
    int reg = ((b >> 3) & 1) | (((ko >> 3) & 1) << 1);
    int idx = ((kc * 16 + (b >> 4)) * 32 + t) * 8 + reg * 2 + (ko & 1);
    g_Zfrag[idx] = __float2half(v);
}
// stack_top fp16 A-fragment store (local 64 batches x 128 k)
__device__ __forceinline__ void store_sfrag(__half* base, int bl, int k, float v) {
    int kc = k >> 4, ko = k & 15;
    int mt = bl >> 4, bm = bl & 15;
    int t   = ((bm & 7) << 2) | ((ko & 7) >> 1);
    int reg = ((bm >> 3) & 1) | (((ko >> 3) & 1) << 1);
    int idx = ((kc * 4 + mt) * 32 + t) * 8 + reg * 2 + (ko & 1);
    base[idx] = __float2half(v);
}

#define MMA_F16(acc, A, b0, b1) asm volatile( \
    "mma.sync.aligned.m16n8k16.row.col.f32.f16.f16.f32 " \
    "{%0,%1,%2,%3},{%4,%5,%6,%7},{%8,%9},{%0,%1,%2,%3};" \
    : "+f"(acc[0]), "+f"(acc[1]), "+f"(acc[2]), "+f"(acc[3]) \
    : "r"(A.x), "r"(A.y), "r"(A.z), "r"(A.w), "r"(b0), "r"(b1))

#define BAR1() asm volatile("bar.sync 1, 256;" ::: "memory")

// ---- software grid barrier ----
__device__ __forceinline__ void grid_bar(int epoch) {
    __syncthreads();
    if (threadIdx.x == 0) {
        unsigned tgt = (unsigned)(epoch + 1) * NBLK, old;
        asm volatile("atom.add.acq_rel.gpu.u32 %0, [%1], %2;" : "=r"(old) : "l"(&g_bar[0]), "r"(1u) : "memory");
        if (old == tgt - 1u) {
            asm volatile("st.release.gpu.u32 [%0], %1;" :: "l"(&g_bar[1]), "r"(tgt) : "memory");
        } else {
            unsigned g;
            do { asm volatile("ld.acquire.gpu.u32 %0, [%1];" : "=r"(g) : "l"(&g_bar[1]) : "memory"); } while (g < tgt);
        }
    }
    __syncthreads();
}

__device__ __forceinline__ float wval(int n, int k,
        const float* Whh, const float* Wih, const float* Dw, const float* Aw) {
    if (n < NG)        return (k < NH) ? Whh[n*NH + k] : Wih[n*(NIN+NSW) + (k-NH)];
    if (n < NG + NSW)  return (k < NH) ? Dw[(n-NG)*NH + k] : 0.f;
    if (n < NTOT)      return (k < NH) ? Aw[(n-NG-NSW)*NH + k] : 0.f;
    return 0.f;
}

// ================= persistent kernel =================
__global__ void __launch_bounds__(NTHR, 1) rnn_persist(
    const float* __restrict__ x, const float* __restrict__ h0,
    float* __restrict__ outs, const float* __restrict__ Wih,
    const float* __restrict__ Whh, const float* __restrict__ Dw,
    const float* __restrict__ Aw,  const float* __restrict__ bih,
    const float* __restrict__ bhh, const float* __restrict__ Db,
    const float* __restrict__ Ab) {
    extern __shared__ char smem[];
    const int tid = threadIdx.x, bx = blockIdx.x;
    const int lane = tid & 31, w = tid >> 5;
    const int gtid = bx * NTHR + tid;

    // ---------- setup ----------
    {
        const long long WTOT = 70LL * WSLICE_H;
        for (long long i = gtid; i < WTOT; i += GSTRIDE) {
            int s = (int)(i / WSLICE_H);
            int j = (int)(i - (long long)s * WSLICE_H);
            int sub = j & 7, lane2 = (j >> 3) & 31, nh2 = (j >> 8) & 1, kc = j >> 9;
            int nt = nh2 * 2 + (sub >> 2);
            int jj = sub & 3;
            int nrow = s * 32 + nt * 8 + (lane2 >> 2);
            int kk = kc * 16 + (lane2 & 3) * 2 + ((jj >> 1) << 3) + (jj & 1);
            g_Wfrag[i] = __float2half(wval(nrow, kk, Whh, Wih, Dw, Aw));
        }
        // W_s fragments: 32 slices x [kc(8)][ntp(4)][lane(32)][8 halfs]
        for (int i = gtid; i < 32 * WS_H; i += GSTRIDE) {
            int s = i >> 13, j = i & (WS_H - 1);
            int sub = j & 7, lane2 = (j >> 3) & 31, ntp = (j >> 8) & 3, kc = j >> 10;
            int nt = ntp * 2 + (sub >> 2);
            int jj = sub & 3;
            int col = nt * 8 + (lane2 >> 2);
            int g = col >> 4, uu = col & 15;
            int jrow = g * NH + s * 16 + uu;
            int kk = kc * 16 + (lane2 & 3) * 2 + ((jj >> 1) << 3) + (jj & 1);
            g_WSfrag[i] = __float2half(Wih[jrow * (NIN + NSW) + NIN + kk]);
        }
        if (gtid < NROWS) {
            float b = 0.f;
            if (gtid < NG)          b = bih[gtid] + bhh[gtid];
            else if (gtid < NG+NSW) b = Db[gtid-NG];
            else if (gtid < NTOT)   b = Ab[gtid-NG-NSW];
            g_bz[gtid] = b;
        }
        for (int i = gtid; i < NB * NH; i += GSTRIDE)
            store_zfrag(i >> 9, i & 511, h0[i]);
        for (int i = gtid; i < NB * NIN; i += GSTRIDE)
            store_zfrag(i >> 8, 512 + (i & 255), x[i]);
    }
    grid_bar(0);

    const int nT = bx % 70, mT = bx / 70;
    const int n0 = nT * 32;
    const int wl = w & 7, nh = w >> 3;
    const int mtile = mT * 8 + wl;

    // load resident phase-A W slice (48 KB)
    {
        const uint4* src = (const uint4*)(g_Wfrag + (size_t)nT * WSLICE_H);
        uint4* dst = (uint4*)(smem + SMW);
#pragma unroll
        for (int i = 0; i < 6; i++) {
            uint4 v; const uint4* p = src + tid + i * NTHR;
            asm volatile("ld.global.cg.v4.u32 {%0,%1,%2,%3}, [%4];"
                         : "=r"(v.x), "=r"(v.y), "=r"(v.z), "=r"(v.w) : "l"(p));
            dst[tid + i * NTHR] = v;
        }
    }
    // gates CTAs: load resident W_s slice (16 KB)
    if (bx < 128) {
        const uint4* src = (const uint4*)(g_WSfrag + (size_t)(bx & 31) * WS_H);
        uint4* dst = (uint4*)(smem + SMWS);
#pragma unroll
        for (int i = 0; i < 2; i++) {
            uint4 v; const uint4* p = src + tid + i * NTHR;
            asm volatile("ld.global.cg.v4.u32 {%0,%1,%2,%3}, [%4];"
                         : "=r"(v.x), "=r"(v.y), "=r"(v.z), "=r"(v.w) : "l"(p));
            dst[tid + i * NTHR] = v;
        }
    }
    __syncthreads();

    const char* pB = smem + SMW + lane * 16;
    const char* pA = (const char*)g_Zfrag + mtile * 512 + lane * 16;
    __half* Sfrag  = (__half*)(smem + SMSF);
    float*  gates_s = (float*)(smem + SMGT);
    float*  cfA    = (float*)(smem + SMCF);

    // phase A epilogue constants
    const int er = lane >> 2, ec2 = (lane & 3) << 1;
    const int eb0 = mT * 128 + wl * 16 + er;
    float bzv[2][2];
#pragma unroll
    for (int q = 0; q < 2; q++) {
        int col = n0 + (nh * 2 + q) * 8 + ec2;
        bzv[q][0] = g_bz[col]; bzv[q][1] = g_bz[col + 1];
    }

    int ep = 1;
    for (int t = 0; t < SEQT; t++) {
        // ======== phase A: single-pass fp16 MMA ========
        {
            float acc[2][4];
#pragma unroll
            for (int q = 0; q < 2; q++)
#pragma unroll
                for (int r = 0; r < 4; r++) acc[q][r] = 0.f;

            uint4 ab[8];
#pragma unroll
            for (int p = 0; p < 8; p++)
                ab[p] = __ldcg((const uint4*)(pA + p * 8192));

            for (int kc = 0; kc < NKC; kc++) {
                uint4 A = ab[kc & 7];
                if (kc < NKC - 8)
                    ab[kc & 7] = __ldcg((const uint4*)(pA + (kc + 8) * 8192));
                uint4 wv = *(const uint4*)(pB + ((kc * 2 + nh) << 9));
                MMA_F16(acc[0], A, wv.x, wv.y);
                MMA_F16(acc[1], A, wv.z, wv.w);
            }

            if (nT < 64) {
#pragma unroll
                for (int q = 0; q < 2; q++) {
                    int col = n0 + (nh * 2 + q) * 8 + ec2;
                    float2 v0 = make_float2(acc[q][0] + bzv[q][0], acc[q][1] + bzv[q][1]);
                    float2 v1 = make_float2(acc[q][2] + bzv[q][0], acc[q][3] + bzv[q][1]);
                    *(float2*)&g_G1[(size_t)eb0 * NG + col] = v0;
                    *(float2*)&g_G1[(size_t)(eb0 + 8) * NG + col] = v1;
                }
            } else if (nT < 68) {
#pragma unroll
                for (int q = 0; q < 2; q++) {
                    int dcol = n0 - NG + (nh * 2 + q) * 8 + ec2;
                    g_dv[eb0 * NSW + dcol]           = tanhf(acc[q][0] + bzv[q][0]);
                    g_dv[eb0 * NSW + dcol + 1]       = tanhf(acc[q][1] + bzv[q][1]);
                    g_dv[(eb0 + 8) * NSW + dcol]     = tanhf(acc[q][2] + bzv[q][0]);
                    g_dv[(eb0 + 8) * NSW + dcol + 1] = tanhf(acc[q][3] + bzv[q][1]);
                }
            } else if (nT == 68 && nh == 0) {
                if (ec2 < 3) {
                    g_ctrl[eb0 * 3 + ec2]       = acc[0][0] + bzv[0][0];
                    g_ctrl[(eb0 + 8) * 3 + ec2] = acc[0][2] + bzv[0][0];
                }
                if (ec2 + 1 < 3) {
                    g_ctrl[eb0 * 3 + ec2 + 1]       = acc[0][1] + bzv[0][1];
                    g_ctrl[(eb0 + 8) * 3 + ec2 + 1] = acc[0][3] + bzv[0][1];
                }
            }
        }
        grid_bar(ep); ep++;

        // ======== phase B ========
        const float* __restrict__ sold = g_stk[t & 1];
        float* __restrict__ snew = g_stk[(t + 1) & 1];
        float* __restrict__ ht = outs + (size_t)t * NB * NH;

        if (tid < 256) {
            if (bx < 128) {
                const int mb0 = (bx >> 5) << 6;
                const int u0  = (bx & 31) << 4;
                if (tid < 64) {
                    float pu, po, no; softmax3(mb0 + tid, pu, po, no);
                    cfA[0*64 + tid] = pu; cfA[1*64 + tid] = po; cfA[2*64 + tid] = no;
                }
                BAR1();
                // stack_top -> fp16 A fragments
                for (int idx = tid; idx < 64 * NSW; idx += 256) {
                    int bl = idx >> 7, k = idx & 127;
                    int b = mb0 + bl;
                    float s0 = __ldcg(&sold[(b * NSD + 0) * NSW + k]);
                    float s1 = __ldcg(&sold[(b * NSD + 1) * NSW + k]);
                    float dd = __ldcg(&g_dv[b * NSW + k]);
                    store_sfrag(Sfrag, bl, k,
                                cfA[2*64+bl] * s0 + cfA[0*64+bl] * dd + cfA[1*64+bl] * s1);
                }
                BAR1();

                // gates GEMM on tensor pipe (single pass): [64x64] = S[64x128] @ Ws^T
                {
                    const int w8 = tid >> 5;
                    const int mt = w8 & 3, np = (w8 >> 2) * 2, ntb = (w8 >> 2) * 4;
                    float acc[4][4];
#pragma unroll
                    for (int q = 0; q < 4; q++)
#pragma unroll
                        for (int r = 0; r < 4; r++) acc[q][r] = 0.f;
#pragma unroll
                    for (int kc = 0; kc < 8; kc++) {
                        uint4 A = *(const uint4*)(smem + SMSF + ((kc * 4 + mt) << 9) + lane * 16);
                        uint4 wv0 = *(const uint4*)(smem + SMWS + (((kc * 4 + np) * 32 + lane) << 4));
                        uint4 wv1 = *(const uint4*)(smem + SMWS + (((kc * 4 + np + 1) * 32 + lane) << 4));
                        MMA_F16(acc[0], A, wv0.x, wv0.y);
                        MMA_F16(acc[1], A, wv0.z, wv0.w);
                        MMA_F16(acc[2], A, wv1.x, wv1.y);
                        MMA_F16(acc[3], A, wv1.z, wv1.w);
                    }
                    const int r0 = mt * 16 + er;
#pragma unroll
                    for (int q = 0; q < 4; q++) {
                        int col = (ntb + q) * 8 + ec2;
                        *(float2*)&gates_s[r0 * 64 + col]       = make_float2(acc[q][0], acc[q][1]);
                        *(float2*)&gates_s[(r0 + 8) * 64 + col] = make_float2(acc[q][2], acc[q][3]);
                    }
                }
                BAR1();

                // LSTM pointwise: 4 (bl,uu) pairs per thread
#pragma unroll
                for (int j = 0; j < 4; j++) {
                    int p = tid + j * 256;
                    int bl = p >> 4, uu = p & 15;
                    int b = mb0 + bl, u = u0 + uu;
                    float gi = gates_s[bl * 64 + uu]      + __ldcg(&g_G1[(size_t)b * NG + u]);
                    float gf = gates_s[bl * 64 + 16 + uu] + __ldcg(&g_G1[(size_t)b * NG + NH + u]);
                    float gg = gates_s[bl * 64 + 32 + uu] + __ldcg(&g_G1[(size_t)b * NG + 2 * NH + u]);
                    float go = gates_s[bl * 64 + 48 + uu] + __ldcg(&g_G1[(size_t)b * NG + 3 * NH + u]);
                    float cn = sigf(gf) * g_c[b * NH + u] + sigf(gi) * tanhf(gg);
                    float hh = sigf(go) * tanhf(cn);
                    g_c[b * NH + u] = cn;
                    ht[b * NH + u] = hh;
                    store_zfrag(b, u, hh);
                }
            } else {
                if (t + 1 < SEQT) {
                    const float* __restrict__ xn = x + (size_t)(t + 1) * NB * NIN;
                    for (int idx = (bx - 128) * 256 + tid; idx < NB * NIN; idx += 12 * 256)
                        store_zfrag(idx >> 8, 512 + (idx & 255), xn[idx]);
                }
            }
        } else {
            // stack blend: upper 256 threads of every block
            const int ut = tid - 256;
            const long long TOTF4 = (long long)NB * NSD * (NSW / 4);
            int lo_ = (int)((long long)bx * TOTF4 / NBLK);
            int hi_ = (int)((long long)(bx + 1) * TOTF4 / NBLK);
            const float4 z4 = make_float4(0.f, 0.f, 0.f, 0.f);
            for (int idx = lo_ + ut; idx < hi_; idx += 256) {
                int b = idx >> 11;
                int rem = idx & 2047;
                int s = rem >> 5, ww = (rem & 31) << 2;
                float pu, po, no; softmax3(b, pu, po, no);
                const float* base = &sold[(b * NSD + s) * NSW + ww];
                float4 cur = __ldcg((const float4*)base);
                float4 up  = s ? __ldcg((const float4*)(base - NSW))
                               : __ldcg((const float4*)&g_dv[b * NSW + ww]);
                float4 dn  = (s < NSD - 1) ? __ldcg((const float4*)(base + NSW)) : z4;
                float4 o;
                o.x = no * cur.x + pu * up.x + po * dn.x;
                o.y = no * cur.y + pu * up.y + po * dn.y;
                o.z = no * cur.z + pu * up.z + po * dn.z;
                o.w = no * cur.w + pu * up.w + po * dn.w;
                *(float4*)&snew[(b * NSD + s) * NSW + ww] = o;
            }
        }
        grid_bar(ep); ep++;
    }
}

// ================= host =================
extern "C" void kernel_launch(void* const* d_in, const int* in_sizes, int n_in,
                              void* d_out, int out_size) {
    const float* x   = (const float*)d_in[0];
    const float* h0  = (const float*)d_in[1];
    const float* c0  = (const float*)d_in[2];
    const float* st0 = (const float*)d_in[3];
    const float* Aw  = (const float*)d_in[4];
    const float* Ab  = (const float*)d_in[5];
    const float* Dw  = (const float*)d_in[6];
    const float* Db  = (const float*)d_in[7];
    const float* Wih = (const float*)d_in[8];
    const float* Whh = (const float*)d_in[9];
    const float* bih = (const float*)d_in[10];
    const float* bhh = (const float*)d_in[11];

    float* outs  = (float*)d_out;
    float* h_out = outs + (size_t)SEQT * NB * NH;
    float* c_out = h_out + (size_t)NB * NH;
    float* s_out = c_out + (size_t)NB * NH;

    float* cbuf;  cudaGetSymbolAddress((void**)&cbuf, g_c);
    float* stbuf; cudaGetSymbolAddress((void**)&stbuf, g_stk);
    unsigned* barbuf; cudaGetSymbolAddress((void**)&barbuf, g_bar);

    cudaFuncSetAttribute(rnn_persist, cudaFuncAttributeMaxDynamicSharedMemorySize, SMTOTAL);

    cudaMemcpyAsync(cbuf,  c0,  (size_t)NB * NH * sizeof(float),        cudaMemcpyDeviceToDevice);
    cudaMemcpyAsync(stbuf, st0, (size_t)NB * NSD * NSW * sizeof(float), cudaMemcpyDeviceToDevice);
    cudaMemsetAsync(barbuf, 0, 2 * sizeof(unsigned));

    rnn_persist<<<NBLK, NTHR, SMTOTAL>>>(x, h0, outs, Wih, Whh, Dw, Aw, bih, bhh, Db, Ab);

    const size_t SSZ = (size_t)NB * NSD * NSW;
    cudaMemcpyAsync(h_out, outs + (size_t)(SEQT - 1) * NB * NH,
                    (size_t)NB * NH * sizeof(float), cudaMemcpyDeviceToDevice);
    cudaMemcpyAsync(c_out, cbuf, (size_t)NB * NH * sizeof(float), cudaMemcpyDeviceToDevice);
    cudaMemcpyAsync(s_out, stbuf, SSZ * sizeof(float), cudaMemcpyDeviceToDevice);
}

// round 9
// speedup vs baseline: 3.3673x; 1.0472x over previous
#include <cuda_runtime.h>
#include <cuda_fp16.h>
#include <math.h>
#include <stdint.h>

#define SEQT 1024
#define NB   256
#define NIN  256
#define NH   512
#define NSW  128
#define NSD  64
#define NG   2048            // 4*NH
#define KZ   768             // NH + NIN
#define NROWS 2240
#define NTOT 2179
#define NBLK 140             // 70 N-tiles x 2 M-halves
#define NKC  48              // 768/16
#define NTHR 512
#define GSTRIDE (NBLK * NTHR)

// phase A W fragment slice per nT (fp16, single): [kc(48)][nh(2)][lane(32)][8 halfs] = 24576 halfs = 49152 B
#define WSLICE_H 24576
// Z fragment: [kc(48)][mtile(16)][lane(32)][8 halfs] = 196608 halfs
#define ZTOT_H  196608
// phase B W_s fragment slice per u0: [kc(8)][ntp(4)][lane(32)][8 halfs] = 8192 halfs = 16384 B
#define WS_H 8192

// dynamic smem layout (bytes)
#define SMW     0                  // 49152: phase A W fragments
#define SMWS    49152              // 16384: phase B W_s fragments
#define SMSF    65536              // 16384: stack_top fp16 A fragments
#define SMGT    81920              // 16384: gates f32 [64][64]
#define SMCF    98304              // 768:   cf[3][64]
#define SMTOTAL 99072

// ---- device scratch ----
__device__ __half g_Wfrag[70 * WSLICE_H];
__device__ __half g_WSfrag[32 * WS_H];
__device__ __half g_Zfrag[ZTOT_H];
__device__ float g_bz[NROWS];
__device__ float g_G1[NB * NG];
__device__ float g_dv[NB * NSW];
__device__ float g_ctrl[NB * 3];
__device__ float g_c[NB * NH];
__device__ float g_stk[2][NB * NSD * NSW];
__device__ unsigned g_flags[NBLK * 32];   // one flag per block, 128B apart

// ---- helpers ----
__device__ __forceinline__ float sigf(float x) { return 1.f / (1.f + expf(-x)); }
__device__ __forceinline__ void softmax3(int b, float& pu, float& po, float& no) {
    float l0 = __ldcg(&g_ctrl[b*3+0]), l1 = __ldcg(&g_ctrl[b*3+1]), l2 = __ldcg(&g_ctrl[b*3+2]);
    float mx = fmaxf(l0, fmaxf(l1, l2));
    float e0 = expf(l0-mx), e1 = expf(l1-mx), e2 = expf(l2-mx);
    float inv = 1.f / (e0+e1+e2);
    pu = e0*inv; po = e1*inv; no = e2*inv;
}
__device__ __forceinline__ void store_zfrag(int b, int kk, float v) {
    int kc = kk >> 4, ko = kk & 15;
    int t   = ((b & 7) << 2) | ((ko & 7) >> 1);
    int reg = ((b >> 3) & 1) | (((ko >> 3) & 1) << 1);
    int idx = ((kc * 16 + (b >> 4)) * 32 + t) * 8 + reg * 2 + (ko & 1);
    g_Zfrag[idx] = __float2half(v);
}
// stack_top fp16 A-fragment store (local 64 batches x 128 k)
__device__ __forceinline__ void store_sfrag(__half* base, int bl, int k, float v) {
    int kc = k >> 4, ko = k & 15;
    int mt = bl >> 4, bm = bl & 15;
    int t   = ((bm & 7) << 2) | ((ko & 7) >> 1);
    int reg = ((bm >> 3) & 1) | (((ko >> 3) & 1) << 1);
    int idx = ((kc * 4 + mt) * 32 + t) * 8 + reg * 2 + (ko & 1);
    base[idx] = __float2half(v);
}

#define MMA_F16(acc, A, b0, b1) asm volatile( \
    "mma.sync.aligned.m16n8k16.row.col.f32.f16.f16.f32 " \
    "{%0,%1,%2,%3},{%4,%5,%6,%7},{%8,%9},{%0,%1,%2,%3};" \
    : "+f"(acc[0]), "+f"(acc[1]), "+f"(acc[2]), "+f"(acc[3]) \
    : "r"(A.x), "r"(A.y), "r"(A.z), "r"(A.w), "r"(b0), "r"(b1))

#define BAR1() asm volatile("bar.sync 1, 256;" ::: "memory")

// ---- distributed-flag grid barrier ----
// each block publishes its epoch on its own 128B-strided flag; threads 0..139
// each poll one block's flag in parallel (no same-address atomic serialization).
__device__ __forceinline__ void grid_bar(int epoch) {
    const unsigned tgt = (unsigned)(epoch + 1);
    __syncthreads();
    if (threadIdx.x == 0) {
        asm volatile("st.release.gpu.u32 [%0], %1;"
                     :: "l"(&g_flags[blockIdx.x * 32]), "r"(tgt) : "memory");
    }
    if (threadIdx.x < NBLK) {
        unsigned v;
        do {
            asm volatile("ld.acquire.gpu.u32 %0, [%1];"
                         : "=r"(v) : "l"(&g_flags[threadIdx.x * 32]) : "memory");
        } while (v < tgt);
    }
    __syncthreads();
}

__device__ __forceinline__ float wval(int n, int k,
        const float* Whh, const float* Wih, const float* Dw, const float* Aw) {
    if (n < NG)        return (k < NH) ? Whh[n*NH + k] : Wih[n*(NIN+NSW) + (k-NH)];
    if (n < NG + NSW)  return (k < NH) ? Dw[(n-NG)*NH + k] : 0.f;
    if (n < NTOT)      return (k < NH) ? Aw[(n-NG-NSW)*NH + k] : 0.f;
    return 0.f;
}

// ================= persistent kernel =================
__global__ void __launch_bounds__(NTHR, 1) rnn_persist(
    const float* __restrict__ x, const float* __restrict__ h0,
    float* __restrict__ outs, const float* __restrict__ Wih,
    const float* __restrict__ Whh, const float* __restrict__ Dw,
    const float* __restrict__ Aw,  const float* __restrict__ bih,
    const float* __restrict__ bhh, const float* __restrict__ Db,
    const float* __restrict__ Ab) {
    extern __shared__ char smem[];
    const int tid = threadIdx.x, bx = blockIdx.x;
    const int lane = tid & 31, w = tid >> 5;
    const int gtid = bx * NTHR + tid;

    // ---------- setup ----------
    {
        const long long WTOT = 70LL * WSLICE_H;
        for (long long i = gtid; i < WTOT; i += GSTRIDE) {
            int s = (int)(i / WSLICE_H);
            int j = (int)(i - (long long)s * WSLICE_H);
            int sub = j & 7, lane2 = (j >> 3) & 31, nh2 = (j >> 8) & 1, kc = j >> 9;
            int nt = nh2 * 2 + (sub >> 2);
            int jj = sub & 3;
            int nrow = s * 32 + nt * 8 + (lane2 >> 2);
            int kk = kc * 16 + (lane2 & 3) * 2 + ((jj >> 1) << 3) + (jj & 1);
            g_Wfrag[i] = __float2half(wval(nrow, kk, Whh, Wih, Dw, Aw));
        }
        for (int i = gtid; i < 32 * WS_H; i += GSTRIDE) {
            int s = i >> 13, j = i & (WS_H - 1);
            int sub = j & 7, lane2 = (j >> 3) & 31, ntp = (j >> 8) & 3, kc = j >> 10;
            int nt = ntp * 2 + (sub >> 2);
            int jj = sub & 3;
            int col = nt * 8 + (lane2 >> 2);
            int g = col >> 4, uu = col & 15;
            int jrow = g * NH + s * 16 + uu;
            int kk = kc * 16 + (lane2 & 3) * 2 + ((jj >> 1) << 3) + (jj & 1);
            g_WSfrag[i] = __float2half(Wih[jrow * (NIN + NSW) + NIN + kk]);
        }
        if (gtid < NROWS) {
            float b = 0.f;
            if (gtid < NG)          b = bih[gtid] + bhh[gtid];
            else if (gtid < NG+NSW) b = Db[gtid-NG];
            else if (gtid < NTOT)   b = Ab[gtid-NG-NSW];
            g_bz[gtid] = b;
        }
        for (int i = gtid; i < NB * NH; i += GSTRIDE)
            store_zfrag(i >> 9, i & 511, h0[i]);
        for (int i = gtid; i < NB * NIN; i += GSTRIDE)
            store_zfrag(i >> 8, 512 + (i & 255), x[i]);
    }
    grid_bar(0);

    const int nT = bx % 70, mT = bx / 70;
    const int n0 = nT * 32;
    const int wl = w & 7, nh = w >> 3;
    const int mtile = mT * 8 + wl;

    // load resident phase-A W slice (48 KB)
    {
        const uint4* src = (const uint4*)(g_Wfrag + (size_t)nT * WSLICE_H);
        uint4* dst = (uint4*)(smem + SMW);
#pragma unroll
        for (int i = 0; i < 6; i++) {
            uint4 v; const uint4* p = src + tid + i * NTHR;
            asm volatile("ld.global.cg.v4.u32 {%0,%1,%2,%3}, [%4];"
                         : "=r"(v.x), "=r"(v.y), "=r"(v.z), "=r"(v.w) : "l"(p));
            dst[tid + i * NTHR] = v;
        }
    }
    // gates CTAs: load resident W_s slice (16 KB)
    if (bx < 128) {
        const uint4* src = (const uint4*)(g_WSfrag + (size_t)(bx & 31) * WS_H);
        uint4* dst = (uint4*)(smem + SMWS);
#pragma unroll
        for (int i = 0; i < 2; i++) {
            uint4 v; const uint4* p = src + tid + i * NTHR;
            asm volatile("ld.global.cg.v4.u32 {%0,%1,%2,%3}, [%4];"
                         : "=r"(v.x), "=r"(v.y), "=r"(v.z), "=r"(v.w) : "l"(p));
            dst[tid + i * NTHR] = v;
        }
    }
    __syncthreads();

    const char* pB = smem + SMW + lane * 16;
    const char* pA = (const char*)g_Zfrag + mtile * 512 + lane * 16;
    __half* Sfrag  = (__half*)(smem + SMSF);
    float*  gates_s = (float*)(smem + SMGT);
    float*  cfA    = (float*)(smem + SMCF);

    // phase A epilogue constants
    const int er = lane >> 2, ec2 = (lane & 3) << 1;
    const int eb0 = mT * 128 + wl * 16 + er;
    float bzv[2][2];
#pragma unroll
    for (int q = 0; q < 2; q++) {
        int col = n0 + (nh * 2 + q) * 8 + ec2;
        bzv[q][0] = g_bz[col]; bzv[q][1] = g_bz[col + 1];
    }

    int ep = 1;
    for (int t = 0; t < SEQT; t++) {
        // ======== phase A: single-pass fp16 MMA ========
        {
            float acc[2][4];
#pragma unroll
            for (int q = 0; q < 2; q++)
#pragma unroll
                for (int r = 0; r < 4; r++) acc[q][r] = 0.f;

            uint4 ab[8];
#pragma unroll
            for (int p = 0; p < 8; p++)
                ab[p] = __ldcg((const uint4*)(pA + p * 8192));

            for (int kc = 0; kc < NKC; kc++) {
                uint4 A = ab[kc & 7];
                if (kc < NKC - 8)
                    ab[kc & 7] = __ldcg((const uint4*)(pA + (kc + 8) * 8192));
                uint4 wv = *(const uint4*)(pB + ((kc * 2 + nh) << 9));
                MMA_F16(acc[0], A, wv.x, wv.y);
                MMA_F16(acc[1], A, wv.z, wv.w);
            }

            if (nT < 64) {
#pragma unroll
                for (int q = 0; q < 2; q++) {
                    int col = n0 + (nh * 2 + q) * 8 + ec2;
                    float2 v0 = make_float2(acc[q][0] + bzv[q][0], acc[q][1] + bzv[q][1]);
                    float2 v1 = make_float2(acc[q][2] + bzv[q][0], acc[q][3] + bzv[q][1]);
                    *(float2*)&g_G1[(size_t)eb0 * NG + col] = v0;
                    *(float2*)&g_G1[(size_t)(eb0 + 8) * NG + col] = v1;
                }
            } else if (nT < 68) {
#pragma unroll
                for (int q = 0; q < 2; q++) {
                    int dcol = n0 - NG + (nh * 2 + q) * 8 + ec2;
                    g_dv[eb0 * NSW + dcol]           = tanhf(acc[q][0] + bzv[q][0]);
                    g_dv[eb0 * NSW + dcol + 1]       = tanhf(acc[q][1] + bzv[q][1]);
                    g_dv[(eb0 + 8) * NSW + dcol]     = tanhf(acc[q][2] + bzv[q][0]);
                    g_dv[(eb0 + 8) * NSW + dcol + 1] = tanhf(acc[q][3] + bzv[q][1]);
                }
            } else if (nT == 68 && nh == 0) {
                if (ec2 < 3) {
                    g_ctrl[eb0 * 3 + ec2]       = acc[0][0] + bzv[0][0];
                    g_ctrl[(eb0 + 8) * 3 + ec2] = acc[0][2] + bzv[0][0];
                }
                if (ec2 + 1 < 3) {
                    g_ctrl[eb0 * 3 + ec2 + 1]       = acc[0][1] + bzv[0][1];
                    g_ctrl[(eb0 + 8) * 3 + ec2 + 1] = acc[0][3] + bzv[0][1];
                }
            }
        }
        grid_bar(ep); ep++;

        // ======== phase B ========
        const float* __restrict__ sold = g_stk[t & 1];
        float* __restrict__ snew = g_stk[(t + 1) & 1];
        float* __restrict__ ht = outs + (size_t)t * NB * NH;

        if (tid < 256) {
            if (bx < 128) {
                const int mb0 = (bx >> 5) << 6;
                const int u0  = (bx & 31) << 4;
                if (tid < 64) {
                    float pu, po, no; softmax3(mb0 + tid, pu, po, no);
                    cfA[0*64 + tid] = pu; cfA[1*64 + tid] = po; cfA[2*64 + tid] = no;
                }
                BAR1();
                // stack_top -> fp16 A fragments
                for (int idx = tid; idx < 64 * NSW; idx += 256) {
                    int bl = idx >> 7, k = idx & 127;
                    int b = mb0 + bl;
                    float s0 = __ldcg(&sold[(b * NSD + 0) * NSW + k]);
                    float s1 = __ldcg(&sold[(b * NSD + 1) * NSW + k]);
                    float dd = __ldcg(&g_dv[b * NSW + k]);
                    store_sfrag(Sfrag, bl, k,
                                cfA[2*64+bl] * s0 + cfA[0*64+bl] * dd + cfA[1*64+bl] * s1);
                }
                BAR1();

                // gates GEMM on tensor pipe (single pass): [64x64] = S[64x128] @ Ws^T
                {
                    const int w8 = tid >> 5;
                    const int mt = w8 & 3, np = (w8 >> 2) * 2, ntb = (w8 >> 2) * 4;
                    float acc[4][4];
#pragma unroll
                    for (int q = 0; q < 4; q++)
#pragma unroll
                        for (int r = 0; r < 4; r++) acc[q][r] = 0.f;
#pragma unroll
                    for (int kc = 0; kc < 8; kc++) {
                        uint4 A = *(const uint4*)(smem + SMSF + ((kc * 4 + mt) << 9) + lane * 16);
                        uint4 wv0 = *(const uint4*)(smem + SMWS + (((kc * 4 + np) * 32 + lane) << 4));
                        uint4 wv1 = *(const uint4*)(smem + SMWS + (((kc * 4 + np + 1) * 32 + lane) << 4));
                        MMA_F16(acc[0], A, wv0.x, wv0.y);
                        MMA_F16(acc[1], A, wv0.z, wv0.w);
                        MMA_F16(acc[2], A, wv1.x, wv1.y);
                        MMA_F16(acc[3], A, wv1.z, wv1.w);
                    }
                    const int r0 = mt * 16 + er;
#pragma unroll
                    for (int q = 0; q < 4; q++) {
                        int col = (ntb + q) * 8 + ec2;
                        *(float2*)&gates_s[r0 * 64 + col]       = make_float2(acc[q][0], acc[q][1]);
                        *(float2*)&gates_s[(r0 + 8) * 64 + col] = make_float2(acc[q][2], acc[q][3]);
                    }
                }
                BAR1();

                // LSTM pointwise: 4 (bl,uu) pairs per thread
#pragma unroll
                for (int j = 0; j < 4; j++) {
                    int p = tid + j * 256;
                    int bl = p >> 4, uu = p & 15;
                    int b = mb0 + bl, u = u0 + uu;
                    float gi = gates_s[bl * 64 + uu]      + __ldcg(&g_G1[(size_t)b * NG + u]);
                    float gf = gates_s[bl * 64 + 16 + uu] + __ldcg(&g_G1[(size_t)b * NG + NH + u]);
                    float gg = gates_s[bl * 64 + 32 + uu] + __ldcg(&g_G1[(size_t)b * NG + 2 * NH + u]);
                    float go = gates_s[bl * 64 + 48 + uu] + __ldcg(&g_G1[(size_t)b * NG + 3 * NH + u]);
                    float cn = sigf(gf) * g_c[b * NH + u] + sigf(gi) * tanhf(gg);
                    float hh = sigf(go) * tanhf(cn);
                    g_c[b * NH + u] = cn;
                    ht[b * NH + u] = hh;
                    store_zfrag(b, u, hh);
                }
            } else {
                if (t + 1 < SEQT) {
                    const float* __restrict__ xn = x + (size_t)(t + 1) * NB * NIN;
                    for (int idx = (bx - 128) * 256 + tid; idx < NB * NIN; idx += 12 * 256)
                        store_zfrag(idx >> 8, 512 + (idx & 255), xn[idx]);
                }
            }
        } else {
            // stack blend: upper 256 threads of every block
            const int ut = tid - 256;
            const long long TOTF4 = (long long)NB * NSD * (NSW / 4);
            int lo_ = (int)((long long)bx * TOTF4 / NBLK);
            int hi_ = (int)((long long)(bx + 1) * TOTF4 / NBLK);
            const float4 z4 = make_float4(0.f, 0.f, 0.f, 0.f);
            for (int idx = lo_ + ut; idx < hi_; idx += 256) {
                int b = idx >> 11;
                int rem = idx & 2047;
                int s = rem >> 5, ww = (rem & 31) << 2;
                float pu, po, no; softmax3(b, pu, po, no);
                const float* base = &sold[(b * NSD + s) * NSW + ww];
                float4 cur = __ldcg((const float4*)base);
                float4 up  = s ? __ldcg((const float4*)(base - NSW))
                               : __ldcg((const float4*)&g_dv[b * NSW + ww]);
                float4 dn  = (s < NSD - 1) ? __ldcg((const float4*)(base + NSW)) : z4;
                float4 o;
                o.x = no * cur.x + pu * up.x + po * dn.x;
                o.y = no * cur.y + pu * up.y + po * dn.y;
                o.z = no * cur.z + pu * up.z + po * dn.z;
                o.w = no * cur.w + pu * up.w + po * dn.w;
                *(float4*)&snew[(b * NSD + s) * NSW + ww] = o;
            }
        }
        grid_bar(ep); ep++;
    }
}

// ================= host =================
extern "C" void kernel_launch(void* const* d_in, const int* in_sizes, int n_in,
                              void* d_out, int out_size) {
    const float* x   = (const float*)d_in[0];
    const float* h0  = (const float*)d_in[1];
    const float* c0  = (const float*)d_in[2];
    const float* st0 = (const float*)d_in[3];
    const float* Aw  = (const float*)d_in[4];
    const float* Ab  = (const float*)d_in[5];
    const float* Dw  = (const float*)d_in[6];
    const float* Db  = (const float*)d_in[7];
    const float* Wih = (const float*)d_in[8];
    const float* Whh = (const float*)d_in[9];
    const float* bih = (const float*)d_in[10];
    const float* bhh = (const float*)d_in[11];

    float* outs  = (float*)d_out;
    float* h_out = outs + (size_t)SEQT * NB * NH;
    float* c_out = h_out + (size_t)NB * NH;
    float* s_out = c_out + (size_t)NB * NH;

    float* cbuf;  cudaGetSymbolAddress((void**)&cbuf, g_c);
    float* stbuf; cudaGetSymbolAddress((void**)&stbuf, g_stk);
    unsigned* flagbuf; cudaGetSymbolAddress((void**)&flagbuf, g_flags);

    cudaFuncSetAttribute(rnn_persist, cudaFuncAttributeMaxDynamicSharedMemorySize, SMTOTAL);

    cudaMemcpyAsync(cbuf,  c0,  (size_t)NB * NH * sizeof(float),        cudaMemcpyDeviceToDevice);
    cudaMemcpyAsync(stbuf, st0, (size_t)NB * NSD * NSW * sizeof(float), cudaMemcpyDeviceToDevice);
    cudaMemsetAsync(flagbuf, 0, NBLK * 32 * sizeof(unsigned));

    rnn_persist<<<NBLK, NTHR, SMTOTAL>>>(x, h0, outs, Wih, Whh, Dw, Aw, bih, bhh, Db, Ab);

    const size_t SSZ = (size_t)NB * NSD * NSW;
    cudaMemcpyAsync(h_out, outs + (size_t)(SEQT - 1) * NB * NH,
                    (size_t)NB * NH * sizeof(float), cudaMemcpyDeviceToDevice);
    cudaMemcpyAsync(c_out, cbuf, (size_t)NB * NH * sizeof(float), cudaMemcpyDeviceToDevice);
    cudaMemcpyAsync(s_out, stbuf, SSZ * sizeof(float), cudaMemcpyDeviceToDevice);
}

// round 10
// speedup vs baseline: 4.3661x; 1.2966x over previous
#include <cuda_runtime.h>
#include <cuda_fp16.h>
#include <math.h>
#include <stdint.h>

#define SEQT 1024
#define NB   256
#define NIN  256
#define NH   512
#define NSW  128
#define NSD  64
#define NG   2048            // 4*NH
#define KZ   768             // NH + NIN
#define NROWS 2240
#define NTOT 2179
#define NBLK 140             // 70 N-tiles x 2 M-halves
#define NKC  48              // 768/16
#define NTHR 512
#define GSTRIDE (NBLK * NTHR)

// phase A W fragment slice per nT (fp16): [kc(48)][nh(2)][lane(32)][8 halfs] = 24576 halfs
#define WSLICE_H 24576
// Z fragment: [kc(48)][mtile(16)][lane(32)][8 halfs]
#define ZTOT_H  196608
// phase B W_s fragment slice per u0: [kc(8)][ntp(4)][lane(32)][8 halfs]
#define WS_H 8192

// dynamic smem layout (bytes)
#define SMW     0                  // 49152: phase A W fragments
#define SMWS    49152              // 16384: phase B W_s fragments
#define SMSF    65536              // 16384: stack_top fp16 A fragments
#define SMGT    81920              // 16384: gates f32 [64][64]
#define SMCF    98304              // 3072:  cf[3][256]
#define SMTOTAL 101376

// ---- device scratch ----
__device__ __half g_Wfrag[70 * WSLICE_H];
__device__ __half g_WSfrag[32 * WS_H];
__device__ __half g_Zfrag[ZTOT_H];
__device__ float g_bz[NROWS];
__device__ float g_G1[NB * NG];
__device__ float g_dv[NB * NSW];
__device__ float g_ctrl[NB * 3];
__device__ float g_c[NB * NH];
__device__ float g_stk[2][NB * NSD * NSW];
__device__ unsigned g_flags[NBLK * 32];   // one flag per block, 128B apart

// ---- helpers ----
__device__ __forceinline__ float sigf(float x) { return 1.f / (1.f + expf(-x)); }
__device__ __forceinline__ void store_zfrag(int b, int kk, float v) {
    int kc = kk >> 4, ko = kk & 15;
    int t   = ((b & 7) << 2) | ((ko & 7) >> 1);
    int reg = ((b >> 3) & 1) | (((ko >> 3) & 1) << 1);
    int idx = ((kc * 16 + (b >> 4)) * 32 + t) * 8 + reg * 2 + (ko & 1);
    g_Zfrag[idx] = __float2half(v);
}
// stack_top fp16 A-fragment store (local 64 batches x 128 k)
__device__ __forceinline__ void store_sfrag(__half* base, int bl, int k, float v) {
    int kc = k >> 4, ko = k & 15;
    int mt = bl >> 4, bm = bl & 15;
    int t   = ((bm & 7) << 2) | ((ko & 7) >> 1);
    int reg = ((bm >> 3) & 1) | (((ko >> 3) & 1) << 1);
    int idx = ((kc * 4 + mt) * 32 + t) * 8 + reg * 2 + (ko & 1);
    base[idx] = __float2half(v);
}

#define MMA_F16(acc, A, b0, b1) asm volatile( \
    "mma.sync.aligned.m16n8k16.row.col.f32.f16.f16.f32 " \
    "{%0,%1,%2,%3},{%4,%5,%6,%7},{%8,%9},{%0,%1,%2,%3};" \
    : "+f"(acc[0]), "+f"(acc[1]), "+f"(acc[2]), "+f"(acc[3]) \
    : "r"(A.x), "r"(A.y), "r"(A.z), "r"(A.w), "r"(b0), "r"(b1))

#define BAR1() asm volatile("bar.sync 1, 256;" ::: "memory")

// ---- distributed-flag grid barrier ----
__device__ __forceinline__ void grid_bar(int epoch) {
    const unsigned tgt = (unsigned)(epoch + 1);
    __syncthreads();
    if (threadIdx.x == 0) {
        asm volatile("st.release.gpu.u32 [%0], %1;"
                     :: "l"(&g_flags[blockIdx.x * 32]), "r"(tgt) : "memory");
    }
    if (threadIdx.x < NBLK) {
        unsigned v;
        do {
            asm volatile("ld.acquire.gpu.u32 %0, [%1];"
                         : "=r"(v) : "l"(&g_flags[threadIdx.x * 32]) : "memory");
        } while (v < tgt);
    }
    __syncthreads();
}

__device__ __forceinline__ float wval(int n, int k,
        const float* Whh, const float* Wih, const float* Dw, const float* Aw) {
    if (n < NG)        return (k < NH) ? Whh[n*NH + k] : Wih[n*(NIN+NSW) + (k-NH)];
    if (n < NG + NSW)  return (k < NH) ? Dw[(n-NG)*NH + k] : 0.f;
    if (n < NTOT)      return (k < NH) ? Aw[(n-NG-NSW)*NH + k] : 0.f;
    return 0.f;
}

// ================= persistent kernel =================
__global__ void __launch_bounds__(NTHR, 1) rnn_persist(
    const float* __restrict__ x, const float* __restrict__ h0,
    float* __restrict__ outs, const float* __restrict__ Wih,
    const float* __restrict__ Whh, const float* __restrict__ Dw,
    const float* __restrict__ Aw,  const float* __restrict__ bih,
    const float* __restrict__ bhh, const float* __restrict__ Db,
    const float* __restrict__ Ab) {
    extern __shared__ char smem[];
    const int tid = threadIdx.x, bx = blockIdx.x;
    const int lane = tid & 31, w = tid >> 5;
    const int gtid = bx * NTHR + tid;

    // ---------- setup ----------
    {
        const long long WTOT = 70LL * WSLICE_H;
        for (long long i = gtid; i < WTOT; i += GSTRIDE) {
            int s = (int)(i / WSLICE_H);
            int j = (int)(i - (long long)s * WSLICE_H);
            int sub = j & 7, lane2 = (j >> 3) & 31, nh2 = (j >> 8) & 1, kc = j >> 9;
            int nt = nh2 * 2 + (sub >> 2);
            int jj = sub & 3;
            int nrow = s * 32 + nt * 8 + (lane2 >> 2);
            int kk = kc * 16 + (lane2 & 3) * 2 + ((jj >> 1) << 3) + (jj & 1);
            g_Wfrag[i] = __float2half(wval(nrow, kk, Whh, Wih, Dw, Aw));
        }
        for (int i = gtid; i < 32 * WS_H; i += GSTRIDE) {
            int s = i >> 13, j = i & (WS_H - 1);
            int sub = j & 7, lane2 = (j >> 3) & 31, ntp = (j >> 8) & 3, kc = j >> 10;
            int nt = ntp * 2 + (sub >> 2);
            int jj = sub & 3;
            int col = nt * 8 + (lane2 >> 2);
            int g = col >> 4, uu = col & 15;
            int jrow = g * NH + s * 16 + uu;
            int kk = kc * 16 + (lane2 & 3) * 2 + ((jj >> 1) << 3) + (jj & 1);
            g_WSfrag[i] = __float2half(Wih[jrow * (NIN + NSW) + NIN + kk]);
        }
        if (gtid < NROWS) {
            float b = 0.f;
            if (gtid < NG)          b = bih[gtid] + bhh[gtid];
            else if (gtid < NG+NSW) b = Db[gtid-NG];
            else if (gtid < NTOT)   b = Ab[gtid-NG-NSW];
            g_bz[gtid] = b;
        }
        for (int i = gtid; i < NB * NH; i += GSTRIDE)
            store_zfrag(i >> 9, i & 511, h0[i]);
        for (int i = gtid; i < NB * NIN; i += GSTRIDE)
            store_zfrag(i >> 8, 512 + (i & 255), x[i]);
    }
    grid_bar(0);

    const int nT = bx % 70, mT = bx / 70;
    const int n0 = nT * 32;
    const int wl = w & 7, nh = w >> 3;
    const int mtile = mT * 8 + wl;

    // load resident phase-A W slice (48 KB)
    {
        const uint4* src = (const uint4*)(g_Wfrag + (size_t)nT * WSLICE_H);
        uint4* dst = (uint4*)(smem + SMW);
#pragma unroll
        for (int i = 0; i < 6; i++) {
            uint4 v; const uint4* p = src + tid + i * NTHR;
            asm volatile("ld.global.cg.v4.u32 {%0,%1,%2,%3}, [%4];"
                         : "=r"(v.x), "=r"(v.y), "=r"(v.z), "=r"(v.w) : "l"(p));
            dst[tid + i * NTHR] = v;
        }
    }
    if (bx < 128) {
        const uint4* src = (const uint4*)(g_WSfrag + (size_t)(bx & 31) * WS_H);
        uint4* dst = (uint4*)(smem + SMWS);
#pragma unroll
        for (int i = 0; i < 2; i++) {
            uint4 v; const uint4* p = src + tid + i * NTHR;
            asm volatile("ld.global.cg.v4.u32 {%0,%1,%2,%3}, [%4];"
                         : "=r"(v.x), "=r"(v.y), "=r"(v.z), "=r"(v.w) : "l"(p));
            dst[tid + i * NTHR] = v;
        }
    }
    __syncthreads();

    const char* pB = smem + SMW + lane * 16;
    const char* pA = (const char*)g_Zfrag + mtile * 512 + lane * 16;
    __half* Sfrag  = (__half*)(smem + SMSF);
    float*  gates_s = (float*)(smem + SMGT);
    float*  cfs    = (float*)(smem + SMCF);   // [3][256]

    // phase A epilogue constants
    const int er = lane >> 2, ec2 = (lane & 3) << 1;
    const int eb0 = mT * 128 + wl * 16 + er;
    float bzv[2][2];
#pragma unroll
    for (int q = 0; q < 2; q++) {
        int col = n0 + (nh * 2 + q) * 8 + ec2;
        bzv[q][0] = g_bz[col]; bzv[q][1] = g_bz[col + 1];
    }

    int ep = 1;
    for (int t = 0; t < SEQT; t++) {
        // ======== phase A: single-pass fp16 MMA, even/odd accumulator chains ========
        {
            float acc[2][4], acc2[2][4];
#pragma unroll
            for (int q = 0; q < 2; q++)
#pragma unroll
                for (int r = 0; r < 4; r++) { acc[q][r] = 0.f; acc2[q][r] = 0.f; }

            uint4 ab[8];
#pragma unroll
            for (int p = 0; p < 8; p++)
                ab[p] = __ldcg((const uint4*)(pA + p * 8192));

            for (int kc = 0; kc < NKC; kc += 2) {
                uint4 A0 = ab[kc & 7];
                if (kc < NKC - 8)
                    ab[kc & 7] = __ldcg((const uint4*)(pA + (kc + 8) * 8192));
                uint4 wv0 = *(const uint4*)(pB + ((kc * 2 + nh) << 9));
                MMA_F16(acc[0], A0, wv0.x, wv0.y);
                MMA_F16(acc[1], A0, wv0.z, wv0.w);

                uint4 A1 = ab[(kc + 1) & 7];
                if (kc + 1 < NKC - 8)
                    ab[(kc + 1) & 7] = __ldcg((const uint4*)(pA + (kc + 9) * 8192));
                uint4 wv1 = *(const uint4*)(pB + (((kc + 1) * 2 + nh) << 9));
                MMA_F16(acc2[0], A1, wv1.x, wv1.y);
                MMA_F16(acc2[1], A1, wv1.z, wv1.w);
            }
#pragma unroll
            for (int q = 0; q < 2; q++)
#pragma unroll
                for (int r = 0; r < 4; r++) acc[q][r] += acc2[q][r];

            if (nT < 64) {
#pragma unroll
                for (int q = 0; q < 2; q++) {
                    int col = n0 + (nh * 2 + q) * 8 + ec2;
                    float2 v0 = make_float2(acc[q][0] + bzv[q][0], acc[q][1] + bzv[q][1]);
                    float2 v1 = make_float2(acc[q][2] + bzv[q][0], acc[q][3] + bzv[q][1]);
                    *(float2*)&g_G1[(size_t)eb0 * NG + col] = v0;
                    *(float2*)&g_G1[(size_t)(eb0 + 8) * NG + col] = v1;
                }
            } else if (nT < 68) {
#pragma unroll
                for (int q = 0; q < 2; q++) {
                    int dcol = n0 - NG + (nh * 2 + q) * 8 + ec2;
                    g_dv[eb0 * NSW + dcol]           = tanhf(acc[q][0] + bzv[q][0]);
                    g_dv[eb0 * NSW + dcol + 1]       = tanhf(acc[q][1] + bzv[q][1]);
                    g_dv[(eb0 + 8) * NSW + dcol]     = tanhf(acc[q][2] + bzv[q][0]);
                    g_dv[(eb0 + 8) * NSW + dcol + 1] = tanhf(acc[q][3] + bzv[q][1]);
                }
            } else if (nT == 68 && nh == 0) {
                if (ec2 < 3) {
                    g_ctrl[eb0 * 3 + ec2]       = acc[0][0] + bzv[0][0];
                    g_ctrl[(eb0 + 8) * 3 + ec2] = acc[0][2] + bzv[0][0];
                }
                if (ec2 + 1 < 3) {
                    g_ctrl[eb0 * 3 + ec2 + 1]       = acc[0][1] + bzv[0][1];
                    g_ctrl[(eb0 + 8) * 3 + ec2 + 1] = acc[0][3] + bzv[0][1];
                }
            }
        }
        grid_bar(ep); ep++;

        // ======== phase B ========
        const float* __restrict__ sold = g_stk[t & 1];
        float* __restrict__ snew = g_stk[(t + 1) & 1];
        float* __restrict__ ht = outs + (size_t)t * NB * NH;

        // memoized softmax: cf[3][256] once per CTA per step
        if (tid < 256) {
            float l0 = __ldcg(&g_ctrl[tid*3+0]), l1 = __ldcg(&g_ctrl[tid*3+1]), l2 = __ldcg(&g_ctrl[tid*3+2]);
            float mx = fmaxf(l0, fmaxf(l1, l2));
            float e0 = expf(l0-mx), e1 = expf(l1-mx), e2 = expf(l2-mx);
            float inv = 1.f / (e0+e1+e2);
            cfs[tid] = e0*inv; cfs[256+tid] = e1*inv; cfs[512+tid] = e2*inv;
        }
        __syncthreads();

        if (tid < 256) {
            if (bx < 128) {
                const int mb0 = (bx >> 5) << 6;
                const int u0  = (bx & 31) << 4;
                // stack_top -> fp16 A fragments
                for (int idx = tid; idx < 64 * NSW; idx += 256) {
                    int bl = idx >> 7, k = idx & 127;
                    int b = mb0 + bl;
                    float s0 = __ldcg(&sold[(b * NSD + 0) * NSW + k]);
                    float s1 = __ldcg(&sold[(b * NSD + 1) * NSW + k]);
                    float dd = __ldcg(&g_dv[b * NSW + k]);
                    store_sfrag(Sfrag, bl, k,
                                cfs[512+b] * s0 + cfs[b] * dd + cfs[256+b] * s1);
                }
                // hoist LSTM inputs: 16 G1 + 4 c loads in flight during gates GEMM
                float g1v[4][4], cv[4];
#pragma unroll
                for (int j = 0; j < 4; j++) {
                    int p = tid + j * 256;
                    int bl = p >> 4, uu = p & 15;
                    int b = mb0 + bl, u = u0 + uu;
                    g1v[j][0] = __ldcg(&g_G1[(size_t)b * NG + u]);
                    g1v[j][1] = __ldcg(&g_G1[(size_t)b * NG + NH + u]);
                    g1v[j][2] = __ldcg(&g_G1[(size_t)b * NG + 2 * NH + u]);
                    g1v[j][3] = __ldcg(&g_G1[(size_t)b * NG + 3 * NH + u]);
                    cv[j] = g_c[b * NH + u];
                }
                BAR1();

                // gates GEMM on tensor pipe: [64x64] = S[64x128] @ Ws^T
                {
                    const int w8 = tid >> 5;
                    const int mt = w8 & 3, np = (w8 >> 2) * 2, ntb = (w8 >> 2) * 4;
                    float acc[4][4];
#pragma unroll
                    for (int q = 0; q < 4; q++)
#pragma unroll
                        for (int r = 0; r < 4; r++) acc[q][r] = 0.f;
#pragma unroll
                    for (int kc = 0; kc < 8; kc++) {
                        uint4 A = *(const uint4*)(smem + SMSF + ((kc * 4 + mt) << 9) + lane * 16);
                        uint4 wv0 = *(const uint4*)(smem + SMWS + (((kc * 4 + np) * 32 + lane) << 4));
                        uint4 wv1 = *(const uint4*)(smem + SMWS + (((kc * 4 + np + 1) * 32 + lane) << 4));
                        MMA_F16(acc[0], A, wv0.x, wv0.y);
                        MMA_F16(acc[1], A, wv0.z, wv0.w);
                        MMA_F16(acc[2], A, wv1.x, wv1.y);
                        MMA_F16(acc[3], A, wv1.z, wv1.w);
                    }
                    const int r0 = mt * 16 + er;
#pragma unroll
                    for (int q = 0; q < 4; q++) {
                        int col = (ntb + q) * 8 + ec2;
                        *(float2*)&gates_s[r0 * 64 + col]       = make_float2(acc[q][0], acc[q][1]);
                        *(float2*)&gates_s[(r0 + 8) * 64 + col] = make_float2(acc[q][2], acc[q][3]);
                    }
                }
                BAR1();

                // LSTM pointwise
#pragma unroll
                for (int j = 0; j < 4; j++) {
                    int p = tid + j * 256;
                    int bl = p >> 4, uu = p & 15;
                    int b = mb0 + bl, u = u0 + uu;
                    float gi = gates_s[bl * 64 + uu]      + g1v[j][0];
                    float gf = gates_s[bl * 64 + 16 + uu] + g1v[j][1];
                    float gg = gates_s[bl * 64 + 32 + uu] + g1v[j][2];
                    float go = gates_s[bl * 64 + 48 + uu] + g1v[j][3];
                    float cn = sigf(gf) * cv[j] + sigf(gi) * tanhf(gg);
                    float hh = sigf(go) * tanhf(cn);
                    g_c[b * NH + u] = cn;
                    ht[b * NH + u] = hh;
                    store_zfrag(b, u, hh);
                }
            } else {
                if (t + 1 < SEQT) {
                    const float* __restrict__ xn = x + (size_t)(t + 1) * NB * NIN;
                    for (int idx = (bx - 128) * 256 + tid; idx < NB * NIN; idx += 12 * 256)
                        store_zfrag(idx >> 8, 512 + (idx & 255), xn[idx]);
                }
            }
        } else {
            // stack blend: upper 256 threads of every block
            const int ut = tid - 256;
            const long long TOTF4 = (long long)NB * NSD * (NSW / 4);
            int lo_ = (int)((long long)bx * TOTF4 / NBLK);
            int hi_ = (int)((long long)(bx + 1) * TOTF4 / NBLK);
            const float4 z4 = make_float4(0.f, 0.f, 0.f, 0.f);
#pragma unroll 2
            for (int idx = lo_ + ut; idx < hi_; idx += 256) {
                int b = idx >> 11;
                int rem = idx & 2047;
                int s = rem >> 5, ww = (rem & 31) << 2;
                float pu = cfs[b], po = cfs[256+b], no = cfs[512+b];
                const float* base = &sold[(b * NSD + s) * NSW + ww];
                float4 cur = __ldcg((const float4*)base);
                float4 up  = s ? __ldcg((const float4*)(base - NSW))
                               : __ldcg((const float4*)&g_dv[b * NSW + ww]);
                float4 dn  = (s < NSD - 1) ? __ldcg((const float4*)(base + NSW)) : z4;
                float4 o;
                o.x = no * cur.x + pu * up.x + po * dn.x;
                o.y = no * cur.y + pu * up.y + po * dn.y;
                o.z = no * cur.z + pu * up.z + po * dn.z;
                o.w = no * cur.w + pu * up.w + po * dn.w;
                *(float4*)&snew[(b * NSD + s) * NSW + ww] = o;
            }
        }
        grid_bar(ep); ep++;
    }
}

// ================= host =================
extern "C" void kernel_launch(void* const* d_in, const int* in_sizes, int n_in,
                              void* d_out, int out_size) {
    const float* x   = (const float*)d_in[0];
    const float* h0  = (const float*)d_in[1];
    const float* c0  = (const float*)d_in[2];
    const float* st0 = (const float*)d_in[3];
    const float* Aw  = (const float*)d_in[4];
    const float* Ab  = (const float*)d_in[5];
    const float* Dw  = (const float*)d_in[6];
    const float* Db  = (const float*)d_in[7];
    const float* Wih = (const float*)d_in[8];
    const float* Whh = (const float*)d_in[9];
    const float* bih = (const float*)d_in[10];
    const float* bhh = (const float*)d_in[11];

    float* outs  = (float*)d_out;
    float* h_out = outs + (size_t)SEQT * NB * NH;
    float* c_out = h_out + (size_t)NB * NH;
    float* s_out = c_out + (size_t)NB * NH;

    float* cbuf;  cudaGetSymbolAddress((void**)&cbuf, g_c);
    float* stbuf; cudaGetSymbolAddress((void**)&stbuf, g_stk);
    unsigned* flagbuf; cudaGetSymbolAddress((void**)&flagbuf, g_flags);

    cudaFuncSetAttribute(rnn_persist, cudaFuncAttributeMaxDynamicSharedMemorySize, SMTOTAL);

    cudaMemcpyAsync(cbuf,  c0,  (size_t)NB * NH * sizeof(float),        cudaMemcpyDeviceToDevice);
    cudaMemcpyAsync(stbuf, st0, (size_t)NB * NSD * NSW * sizeof(float), cudaMemcpyDeviceToDevice);
    cudaMemsetAsync(flagbuf, 0, NBLK * 32 * sizeof(unsigned));

    rnn_persist<<<NBLK, NTHR, SMTOTAL>>>(x, h0, outs, Wih, Whh, Dw, Aw, bih, bhh, Db, Ab);

    const size_t SSZ = (size_t)NB * NSD * NSW;
    cudaMemcpyAsync(h_out, outs + (size_t)(SEQT - 1) * NB * NH,
                    (size_t)NB * NH * sizeof(float), cudaMemcpyDeviceToDevice);
    cudaMemcpyAsync(c_out, cbuf, (size_t)NB * NH * sizeof(float), cudaMemcpyDeviceToDevice);
    cudaMemcpyAsync(s_out, stbuf, SSZ * sizeof(float), cudaMemcpyDeviceToDevice);
}

// round 11
// speedup vs baseline: 4.4471x; 1.0186x over previous
#include <cuda_runtime.h>
#include <cuda_fp16.h>
#include <math.h>
#include <stdint.h>

#define SEQT 1024
#define NB   256
#define NIN  256
#define NH   512
#define NSW  128
#define NSD  64
#define NG   2048            // 4*NH
#define KZ   768             // NH + NIN
#define NROWS 2240
#define NTOT 2179
#define NBLK 140             // 70 N-tiles x 2 M-halves
#define NKC  48              // 768/16
#define NTHR 512
#define GSTRIDE (NBLK * NTHR)

// phase A W fragment slice per nT (fp16): [kc(48)][nh(2)][lane(32)][8 halfs] = 24576 halfs
#define WSLICE_H 24576
// Z fragment: [kc(48)][mtile(16)][lane(32)][8 halfs]
#define ZTOT_H  196608
// phase B W_s fragment slice per u0: [kc(8)][ntp(4)][lane(32)][8 halfs]
#define WS_H 8192

// dynamic smem layout (bytes)
#define SMW     0                  // 49152: phase A W fragments
#define SMWS    49152              // 16384: phase B W_s fragments
#define SMSF    65536              // 16384: stack_top fp16 A fragments
#define SMGT    81920              // 16384: gates f32 [64][64]
#define SMCF    98304              // 3072:  cf[3][256]
#define SMTOTAL 101376

// ---- device scratch ----
__device__ __half g_Wfrag[70 * WSLICE_H];
__device__ __half g_WSfrag[32 * WS_H];
__device__ __half g_Zfrag[ZTOT_H];
__device__ float g_bz[NROWS];
__device__ float g_G1[NB * NG];
__device__ float g_dv[NB * NSW];
__device__ float g_ctrl[NB * 3];
__device__ float g_c[NB * NH];
__device__ float g_stk[2][NB * NSD * NSW];
__device__ unsigned g_flags[NBLK * 32];   // one flag per block, 128B apart

// ---- helpers ----
__device__ __forceinline__ float sigf(float x) { return 1.f / (1.f + expf(-x)); }
__device__ __forceinline__ void store_zfrag(int b, int kk, float v) {
    int kc = kk >> 4, ko = kk & 15;
    int t   = ((b & 7) << 2) | ((ko & 7) >> 1);
    int reg = ((b >> 3) & 1) | (((ko >> 3) & 1) << 1);
    int idx = ((kc * 16 + (b >> 4)) * 32 + t) * 8 + reg * 2 + (ko & 1);
    g_Zfrag[idx] = __float2half(v);
}
// paired store: kk even, writes (kk, kk+1) as one __half2 (4B aligned)
__device__ __forceinline__ void store_zfrag2(int b, int kk, float v0, float v1) {
    int kc = kk >> 4, ko = kk & 15;
    int t   = ((b & 7) << 2) | ((ko & 7) >> 1);
    int reg = ((b >> 3) & 1) | (((ko >> 3) & 1) << 1);
    int idx = ((kc * 16 + (b >> 4)) * 32 + t) * 8 + reg * 2;
    *(__half2*)&g_Zfrag[idx] = __floats2half2_rn(v0, v1);
}
// stack_top fp16 A-fragment store (local 64 batches x 128 k)
__device__ __forceinline__ void store_sfrag(__half* base, int bl, int k, float v) {
    int kc = k >> 4, ko = k & 15;
    int mt = bl >> 4, bm = bl & 15;
    int t   = ((bm & 7) << 2) | ((ko & 7) >> 1);
    int reg = ((bm >> 3) & 1) | (((ko >> 3) & 1) << 1);
    int idx = ((kc * 4 + mt) * 32 + t) * 8 + reg * 2 + (ko & 1);
    base[idx] = __float2half(v);
}

#define MMA_F16(acc, A, b0, b1) asm volatile( \
    "mma.sync.aligned.m16n8k16.row.col.f32.f16.f16.f32 " \
    "{%0,%1,%2,%3},{%4,%5,%6,%7},{%8,%9},{%0,%1,%2,%3};" \
    : "+f"(acc[0]), "+f"(acc[1]), "+f"(acc[2]), "+f"(acc[3]) \
    : "r"(A.x), "r"(A.y), "r"(A.z), "r"(A.w), "r"(b0), "r"(b1))

#define BAR1() asm volatile("bar.sync 1, 256;" ::: "memory")

// ---- distributed-flag grid barrier ----
__device__ __forceinline__ void grid_bar(int epoch) {
    const unsigned tgt = (unsigned)(epoch + 1);
    __syncthreads();
    if (threadIdx.x == 0) {
        asm volatile("st.release.gpu.u32 [%0], %1;"
                     :: "l"(&g_flags[blockIdx.x * 32]), "r"(tgt) : "memory");
    }
    if (threadIdx.x < NBLK) {
        unsigned v;
        do {
            asm volatile("ld.acquire.gpu.u32 %0, [%1];"
                         : "=r"(v) : "l"(&g_flags[threadIdx.x * 32]) : "memory");
        } while (v < tgt);
    }
    __syncthreads();
}

__device__ __forceinline__ float wval(int n, int k,
        const float* Whh, const float* Wih, const float* Dw, const float* Aw) {
    if (n < NG)        return (k < NH) ? Whh[n*NH + k] : Wih[n*(NIN+NSW) + (k-NH)];
    if (n < NG + NSW)  return (k < NH) ? Dw[(n-NG)*NH + k] : 0.f;
    if (n < NTOT)      return (k < NH) ? Aw[(n-NG-NSW)*NH + k] : 0.f;
    return 0.f;
}

// ================= persistent kernel =================
__global__ void __launch_bounds__(NTHR, 1) rnn_persist(
    const float* __restrict__ x, const float* __restrict__ h0,
    float* __restrict__ outs, const float* __restrict__ Wih,
    const float* __restrict__ Whh, const float* __restrict__ Dw,
    const float* __restrict__ Aw,  const float* __restrict__ bih,
    const float* __restrict__ bhh, const float* __restrict__ Db,
    const float* __restrict__ Ab) {
    extern __shared__ char smem[];
    const int tid = threadIdx.x, bx = blockIdx.x;
    const int lane = tid & 31, w = tid >> 5;
    const int gtid = bx * NTHR + tid;

    // ---------- setup ----------
    {
        const long long WTOT = 70LL * WSLICE_H;
        for (long long i = gtid; i < WTOT; i += GSTRIDE) {
            int s = (int)(i / WSLICE_H);
            int j = (int)(i - (long long)s * WSLICE_H);
            int sub = j & 7, lane2 = (j >> 3) & 31, nh2 = (j >> 8) & 1, kc = j >> 9;
            int nt = nh2 * 2 + (sub >> 2);
            int jj = sub & 3;
            int nrow = s * 32 + nt * 8 + (lane2 >> 2);
            int kk = kc * 16 + (lane2 & 3) * 2 + ((jj >> 1) << 3) + (jj & 1);
            g_Wfrag[i] = __float2half(wval(nrow, kk, Whh, Wih, Dw, Aw));
        }
        for (int i = gtid; i < 32 * WS_H; i += GSTRIDE) {
            int s = i >> 13, j = i & (WS_H - 1);
            int sub = j & 7, lane2 = (j >> 3) & 31, ntp = (j >> 8) & 3, kc = j >> 10;
            int nt = ntp * 2 + (sub >> 2);
            int jj = sub & 3;
            int col = nt * 8 + (lane2 >> 2);
            int g = col >> 4, uu = col & 15;
            int jrow = g * NH + s * 16 + uu;
            int kk = kc * 16 + (lane2 & 3) * 2 + ((jj >> 1) << 3) + (jj & 1);
            g_WSfrag[i] = __float2half(Wih[jrow * (NIN + NSW) + NIN + kk]);
        }
        if (gtid < NROWS) {
            float b = 0.f;
            if (gtid < NG)          b = bih[gtid] + bhh[gtid];
            else if (gtid < NG+NSW) b = Db[gtid-NG];
            else if (gtid < NTOT)   b = Ab[gtid-NG-NSW];
            g_bz[gtid] = b;
        }
        for (int i = gtid; i < NB * NH; i += GSTRIDE)
            store_zfrag(i >> 9, i & 511, h0[i]);
        for (int i = gtid; i < NB * NIN; i += GSTRIDE)
            store_zfrag(i >> 8, 512 + (i & 255), x[i]);
    }
    grid_bar(0);

    const int nT = bx % 70, mT = bx / 70;
    const int n0 = nT * 32;
    const int wl = w & 7, nh = w >> 3;
    const int mtile = mT * 8 + wl;

    // load resident phase-A W slice (48 KB)
    {
        const uint4* src = (const uint4*)(g_Wfrag + (size_t)nT * WSLICE_H);
        uint4* dst = (uint4*)(smem + SMW);
#pragma unroll
        for (int i = 0; i < 6; i++) {
            uint4 v; const uint4* p = src + tid + i * NTHR;
            asm volatile("ld.global.cg.v4.u32 {%0,%1,%2,%3}, [%4];"
                         : "=r"(v.x), "=r"(v.y), "=r"(v.z), "=r"(v.w) : "l"(p));
            dst[tid + i * NTHR] = v;
        }
    }
    if (bx < 128) {
        const uint4* src = (const uint4*)(g_WSfrag + (size_t)(bx & 31) * WS_H);
        uint4* dst = (uint4*)(smem + SMWS);
#pragma unroll
        for (int i = 0; i < 2; i++) {
            uint4 v; const uint4* p = src + tid + i * NTHR;
            asm volatile("ld.global.cg.v4.u32 {%0,%1,%2,%3}, [%4];"
                         : "=r"(v.x), "=r"(v.y), "=r"(v.z), "=r"(v.w) : "l"(p));
            dst[tid + i * NTHR] = v;
        }
    }
    __syncthreads();

    const char* pB = smem + SMW + lane * 16;
    const char* pA = (const char*)g_Zfrag + mtile * 512 + lane * 16;
    __half* Sfrag  = (__half*)(smem + SMSF);
    float*  gates_s = (float*)(smem + SMGT);
    float*  cfs    = (float*)(smem + SMCF);   // [3][256]

    // phase A epilogue constants
    const int er = lane >> 2, ec2 = (lane & 3) << 1;
    const int eb0 = mT * 128 + wl * 16 + er;
    float bzv[2][2];
#pragma unroll
    for (int q = 0; q < 2; q++) {
        int col = n0 + (nh * 2 + q) * 8 + ec2;
        bzv[q][0] = g_bz[col]; bzv[q][1] = g_bz[col + 1];
    }

    int ep = 1;
    for (int t = 0; t < SEQT; t++) {
        // ======== phase A: single-pass fp16 MMA, even/odd accumulator chains ========
        {
            float acc[2][4], acc2[2][4];
#pragma unroll
            for (int q = 0; q < 2; q++)
#pragma unroll
                for (int r = 0; r < 4; r++) { acc[q][r] = 0.f; acc2[q][r] = 0.f; }

            uint4 ab[8];
#pragma unroll
            for (int p = 0; p < 8; p++)
                ab[p] = __ldcg((const uint4*)(pA + p * 8192));

            for (int kc = 0; kc < NKC; kc += 2) {
                uint4 A0 = ab[kc & 7];
                if (kc < NKC - 8)
                    ab[kc & 7] = __ldcg((const uint4*)(pA + (kc + 8) * 8192));
                uint4 wv0 = *(const uint4*)(pB + ((kc * 2 + nh) << 9));
                MMA_F16(acc[0], A0, wv0.x, wv0.y);
                MMA_F16(acc[1], A0, wv0.z, wv0.w);

                uint4 A1 = ab[(kc + 1) & 7];
                if (kc + 1 < NKC - 8)
                    ab[(kc + 1) & 7] = __ldcg((const uint4*)(pA + (kc + 9) * 8192));
                uint4 wv1 = *(const uint4*)(pB + (((kc + 1) * 2 + nh) << 9));
                MMA_F16(acc2[0], A1, wv1.x, wv1.y);
                MMA_F16(acc2[1], A1, wv1.z, wv1.w);
            }
#pragma unroll
            for (int q = 0; q < 2; q++)
#pragma unroll
                for (int r = 0; r < 4; r++) acc[q][r] += acc2[q][r];

            if (nT < 64) {
#pragma unroll
                for (int q = 0; q < 2; q++) {
                    int col = n0 + (nh * 2 + q) * 8 + ec2;
                    float2 v0 = make_float2(acc[q][0] + bzv[q][0], acc[q][1] + bzv[q][1]);
                    float2 v1 = make_float2(acc[q][2] + bzv[q][0], acc[q][3] + bzv[q][1]);
                    *(float2*)&g_G1[(size_t)eb0 * NG + col] = v0;
                    *(float2*)&g_G1[(size_t)(eb0 + 8) * NG + col] = v1;
                }
            } else if (nT < 68) {
#pragma unroll
                for (int q = 0; q < 2; q++) {
                    int dcol = n0 - NG + (nh * 2 + q) * 8 + ec2;
                    g_dv[eb0 * NSW + dcol]           = tanhf(acc[q][0] + bzv[q][0]);
                    g_dv[eb0 * NSW + dcol + 1]       = tanhf(acc[q][1] + bzv[q][1]);
                    g_dv[(eb0 + 8) * NSW + dcol]     = tanhf(acc[q][2] + bzv[q][0]);
                    g_dv[(eb0 + 8) * NSW + dcol + 1] = tanhf(acc[q][3] + bzv[q][1]);
                }
            } else if (nT == 68 && nh == 0) {
                if (ec2 < 3) {
                    g_ctrl[eb0 * 3 + ec2]       = acc[0][0] + bzv[0][0];
                    g_ctrl[(eb0 + 8) * 3 + ec2] = acc[0][2] + bzv[0][0];
                }
                if (ec2 + 1 < 3) {
                    g_ctrl[eb0 * 3 + ec2 + 1]       = acc[0][1] + bzv[0][1];
                    g_ctrl[(eb0 + 8) * 3 + ec2 + 1] = acc[0][3] + bzv[0][1];
                }
            }
        }
        grid_bar(ep); ep++;

        // ======== phase B ========
        const float* __restrict__ sold = g_stk[t & 1];
        float* __restrict__ snew = g_stk[(t + 1) & 1];
        float* __restrict__ ht = outs + (size_t)t * NB * NH;

        // memoized softmax: cf[3][256] once per CTA per step
        if (tid < 256) {
            float l0 = __ldcg(&g_ctrl[tid*3+0]), l1 = __ldcg(&g_ctrl[tid*3+1]), l2 = __ldcg(&g_ctrl[tid*3+2]);
            float mx = fmaxf(l0, fmaxf(l1, l2));
            float e0 = expf(l0-mx), e1 = expf(l1-mx), e2 = expf(l2-mx);
            float inv = 1.f / (e0+e1+e2);
            cfs[tid] = e0*inv; cfs[256+tid] = e1*inv; cfs[512+tid] = e2*inv;
        }
        __syncthreads();

        if (tid < 256) {
            if (bx < 128) {
                const int mb0 = (bx >> 5) << 6;
                const int u0  = (bx & 31) << 4;
                // stack_top -> fp16 A fragments
                for (int idx = tid; idx < 64 * NSW; idx += 256) {
                    int bl = idx >> 7, k = idx & 127;
                    int b = mb0 + bl;
                    float s0 = __ldcg(&sold[(b * NSD + 0) * NSW + k]);
                    float s1 = __ldcg(&sold[(b * NSD + 1) * NSW + k]);
                    float dd = __ldcg(&g_dv[b * NSW + k]);
                    store_sfrag(Sfrag, bl, k,
                                cfs[512+b] * s0 + cfs[b] * dd + cfs[256+b] * s1);
                }
                // hoist LSTM inputs (paired units -> float2): in flight during gates GEMM
                float2 hg[2][4], hc[2];
#pragma unroll
                for (int j = 0; j < 2; j++) {
                    int p = tid + j * 256;
                    int bl = p >> 3, uu2 = p & 7;
                    int b = mb0 + bl, u = u0 + uu2 * 2;
                    hg[j][0] = __ldcg((const float2*)&g_G1[(size_t)b * NG + u]);
                    hg[j][1] = __ldcg((const float2*)&g_G1[(size_t)b * NG + NH + u]);
                    hg[j][2] = __ldcg((const float2*)&g_G1[(size_t)b * NG + 2 * NH + u]);
                    hg[j][3] = __ldcg((const float2*)&g_G1[(size_t)b * NG + 3 * NH + u]);
                    hc[j] = *(const float2*)&g_c[b * NH + u];
                }
                BAR1();

                // gates GEMM on tensor pipe: [64x64] = S[64x128] @ Ws^T
                {
                    const int w8 = tid >> 5;
                    const int mt = w8 & 3, np = (w8 >> 2) * 2, ntb = (w8 >> 2) * 4;
                    float acc[4][4];
#pragma unroll
                    for (int q = 0; q < 4; q++)
#pragma unroll
                        for (int r = 0; r < 4; r++) acc[q][r] = 0.f;
#pragma unroll
                    for (int kc = 0; kc < 8; kc++) {
                        uint4 A = *(const uint4*)(smem + SMSF + ((kc * 4 + mt) << 9) + lane * 16);
                        uint4 wv0 = *(const uint4*)(smem + SMWS + (((kc * 4 + np) * 32 + lane) << 4));
                        uint4 wv1 = *(const uint4*)(smem + SMWS + (((kc * 4 + np + 1) * 32 + lane) << 4));
                        MMA_F16(acc[0], A, wv0.x, wv0.y);
                        MMA_F16(acc[1], A, wv0.z, wv0.w);
                        MMA_F16(acc[2], A, wv1.x, wv1.y);
                        MMA_F16(acc[3], A, wv1.z, wv1.w);
                    }
                    const int r0 = mt * 16 + er;
#pragma unroll
                    for (int q = 0; q < 4; q++) {
                        int col = (ntb + q) * 8 + ec2;
                        *(float2*)&gates_s[r0 * 64 + col]       = make_float2(acc[q][0], acc[q][1]);
                        *(float2*)&gates_s[(r0 + 8) * 64 + col] = make_float2(acc[q][2], acc[q][3]);
                    }
                }
                BAR1();

                // LSTM pointwise (paired units)
#pragma unroll
                for (int j = 0; j < 2; j++) {
                    int p = tid + j * 256;
                    int bl = p >> 3, uu2 = p & 7;
                    int b = mb0 + bl, u = u0 + uu2 * 2;
                    float2 gsi = *(const float2*)&gates_s[bl * 64 + uu2 * 2];
                    float2 gsf = *(const float2*)&gates_s[bl * 64 + 16 + uu2 * 2];
                    float2 gsg = *(const float2*)&gates_s[bl * 64 + 32 + uu2 * 2];
                    float2 gso = *(const float2*)&gates_s[bl * 64 + 48 + uu2 * 2];
                    float gi0 = gsi.x + hg[j][0].x, gi1 = gsi.y + hg[j][0].y;
                    float gf0 = gsf.x + hg[j][1].x, gf1 = gsf.y + hg[j][1].y;
                    float gg0 = gsg.x + hg[j][2].x, gg1 = gsg.y + hg[j][2].y;
                    float go0 = gso.x + hg[j][3].x, go1 = gso.y + hg[j][3].y;
                    float cn0 = sigf(gf0) * hc[j].x + sigf(gi0) * tanhf(gg0);
                    float cn1 = sigf(gf1) * hc[j].y + sigf(gi1) * tanhf(gg1);
                    float hh0 = sigf(go0) * tanhf(cn0);
                    float hh1 = sigf(go1) * tanhf(cn1);
                    *(float2*)&g_c[b * NH + u] = make_float2(cn0, cn1);
                    *(float2*)&ht[b * NH + u]  = make_float2(hh0, hh1);
                    store_zfrag2(b, u, hh0, hh1);
                }
            } else {
                if (t + 1 < SEQT) {
                    const float* __restrict__ xn = x + (size_t)(t + 1) * NB * NIN;
                    for (int idx = (bx - 128) * 256 + tid; idx < NB * NIN / 2; idx += 12 * 256) {
                        int b = idx >> 7, k2 = idx & 127;
                        float2 xv = __ldcg((const float2*)&xn[b * NIN + k2 * 2]);
                        store_zfrag2(b, 512 + k2 * 2, xv.x, xv.y);
                    }
                }
            }
        } else {
            // stack blend: depth-run scheme, upper 256 threads of every block
            const int ut = tid - 256;
            const int TOTR = NB * 8 * 32;   // 65536 runs of 8 depths
            int lo_ = (int)((long long)bx * TOTR / NBLK);
            int hi_ = (int)((long long)(bx + 1) * TOTR / NBLK);
            const float4 z4 = make_float4(0.f, 0.f, 0.f, 0.f);
            for (int run = lo_ + ut; run < hi_; run += 256) {
                int ww = run & 31;
                int q = run >> 5;
                int b = q >> 3, dr = q & 7;
                int d0 = dr << 3;
                float pu = cfs[b], po = cfs[256 + b], no = cfs[512 + b];
                const float* cb = &sold[b * NSD * NSW + ww * 4];
                float* ob = &snew[(b * NSD + d0) * NSW + ww * 4];
                float4 v[6];
                v[0] = d0 ? __ldcg((const float4*)(cb + (d0 - 1) * NSW))
                          : __ldcg((const float4*)&g_dv[b * NSW + ww * 4]);
#pragma unroll
                for (int i = 0; i < 5; i++)
                    v[i + 1] = __ldcg((const float4*)(cb + (d0 + i) * NSW));
#pragma unroll
                for (int i = 0; i < 4; i++) {
                    float4 o;
                    o.x = no * v[i+1].x + pu * v[i].x + po * v[i+2].x;
                    o.y = no * v[i+1].y + pu * v[i].y + po * v[i+2].y;
                    o.z = no * v[i+1].z + pu * v[i].z + po * v[i+2].z;
                    o.w = no * v[i+1].w + pu * v[i].w + po * v[i+2].w;
                    *(float4*)(ob + i * NSW) = o;
                }
                v[0] = v[4]; v[1] = v[5];
#pragma unroll
                for (int i = 0; i < 3; i++)
                    v[i + 2] = __ldcg((const float4*)(cb + (d0 + 5 + i) * NSW));
                v[5] = (d0 + 8 < NSD) ? __ldcg((const float4*)(cb + (d0 + 8) * NSW)) : z4;
#pragma unroll
                for (int i = 0; i < 4; i++) {
                    float4 o;
                    o.x = no * v[i+1].x + pu * v[i].x + po * v[i+2].x;
                    o.y = no * v[i+1].y + pu * v[i].y + po * v[i+2].y;
                    o.z = no * v[i+1].z + pu * v[i].z + po * v[i+2].z;
                    o.w = no * v[i+1].w + pu * v[i].w + po * v[i+2].w;
                    *(float4*)(ob + (4 + i) * NSW) = o;
                }
            }
        }
        grid_bar(ep); ep++;
    }
}

// ================= host =================
extern "C" void kernel_launch(void* const* d_in, const int* in_sizes, int n_in,
                              void* d_out, int out_size) {
    const float* x   = (const float*)d_in[0];
    const float* h0  = (const float*)d_in[1];
    const float* c0  = (const float*)d_in[2];
    const float* st0 = (const float*)d_in[3];
    const float* Aw  = (const float*)d_in[4];
    const float* Ab  = (const float*)d_in[5];
    const float* Dw  = (const float*)d_in[6];
    const float* Db  = (const float*)d_in[7];
    const float* Wih = (const float*)d_in[8];
    const float* Whh = (const float*)d_in[9];
    const float* bih = (const float*)d_in[10];
    const float* bhh = (const float*)d_in[11];

    float* outs  = (float*)d_out;
    float* h_out = outs + (size_t)SEQT * NB * NH;
    float* c_out = h_out + (size_t)NB * NH;
    float* s_out = c_out + (size_t)NB * NH;

    float* cbuf;  cudaGetSymbolAddress((void**)&cbuf, g_c);
    float* stbuf; cudaGetSymbolAddress((void**)&stbuf, g_stk);
    unsigned* flagbuf; cudaGetSymbolAddress((void**)&flagbuf, g_flags);

    cudaFuncSetAttribute(rnn_persist, cudaFuncAttributeMaxDynamicSharedMemorySize, SMTOTAL);

    cudaMemcpyAsync(cbuf,  c0,  (size_t)NB * NH * sizeof(float),        cudaMemcpyDeviceToDevice);
    cudaMemcpyAsync(stbuf, st0, (size_t)NB * NSD * NSW * sizeof(float), cudaMemcpyDeviceToDevice);
    cudaMemsetAsync(flagbuf, 0, NBLK * 32 * sizeof(unsigned));

    rnn_persist<<<NBLK, NTHR, SMTOTAL>>>(x, h0, outs, Wih, Whh, Dw, Aw, bih, bhh, Db, Ab);

    const size_t SSZ = (size_t)NB * NSD * NSW;
    cudaMemcpyAsync(h_out, outs + (size_t)(SEQT - 1) * NB * NH,
                    (size_t)NB * NH * sizeof(float), cudaMemcpyDeviceToDevice);
    cudaMemcpyAsync(c_out, cbuf, (size_t)NB * NH * sizeof(float), cudaMemcpyDeviceToDevice);
    cudaMemcpyAsync(s_out, stbuf, SSZ * sizeof(float), cudaMemcpyDeviceToDevice);
}

// round 12
// speedup vs baseline: 4.7570x; 1.0697x over previous
#include <cuda_runtime.h>
#include <cuda_fp16.h>
#include <math.h>
#include <stdint.h>

#define SEQT 1024
#define NB   256
#define NIN  256
#define NH   512
#define NSW  128
#define NSD  64
#define NG   2048            // 4*NH
#define KZ   768             // NH + NIN
#define NROWS 2240
#define NTOT 2179
#define NBLK 140             // 70 N-tiles x 2 M-halves
#define NKC  48              // 768/16
#define NTHR 512
#define GSTRIDE (NBLK * NTHR)

// phase A W fragment slice per nT (fp16): [kc(48)][nh(2)][lane(32)][8 halfs] = 24576 halfs
#define WSLICE_H 24576
// Z fragment: [kc(48)][mtile(16)][lane(32)][8 halfs]
#define ZTOT_H  196608
// phase B W_s fragment slice per u0: [kc(8)][ntp(4)][lane(32)][8 halfs]
#define WS_H 8192

// dynamic smem layout (bytes)
#define SMW     0                  // 49152: phase A W fragments
#define SMWS    49152              // 16384: phase B W_s fragments
#define SMSF    65536              // 16384: stack_top fp16 A fragments
#define SMGT    81920              // 16384: gates f32 [64][64]
#define SMCF    98304              // 3072:  cf[3][256]
#define SMTOTAL 101376

// ---- device scratch ----
__device__ __half g_Wfrag[70 * WSLICE_H];
__device__ __half g_WSfrag[32 * WS_H];
__device__ __half g_Zfrag[ZTOT_H];
__device__ float g_bz[NROWS];
__device__ float g_G1[NB * NG];
__device__ float g_dv[NB * NSW];
__device__ float g_ctrl[NB * 3];
__device__ float g_cf[3 * NB];        // producer-computed softmax (push/pop/noop)
__device__ float g_c[NB * NH];
__device__ float g_stk[2][NB * NSD * NSW];
__device__ unsigned g_flags[NBLK * 32];   // one flag per block, 128B apart

// ---- helpers ----
__device__ __forceinline__ float sigf(float x) { return 1.f / (1.f + expf(-x)); }
__device__ __forceinline__ void store_zfrag(int b, int kk, float v) {
    int kc = kk >> 4, ko = kk & 15;
    int t   = ((b & 7) << 2) | ((ko & 7) >> 1);
    int reg = ((b >> 3) & 1) | (((ko >> 3) & 1) << 1);
    int idx = ((kc * 16 + (b >> 4)) * 32 + t) * 8 + reg * 2 + (ko & 1);
    g_Zfrag[idx] = __float2half(v);
}
// paired store: kk even, writes (kk, kk+1) as one __half2 (4B aligned)
__device__ __forceinline__ void store_zfrag2(int b, int kk, float v0, float v1) {
    int kc = kk >> 4, ko = kk & 15;
    int t   = ((b & 7) << 2) | ((ko & 7) >> 1);
    int reg = ((b >> 3) & 1) | (((ko >> 3) & 1) << 1);
    int idx = ((kc * 16 + (b >> 4)) * 32 + t) * 8 + reg * 2;
    *(__half2*)&g_Zfrag[idx] = __floats2half2_rn(v0, v1);
}
// stack_top paired fp16 A-fragment store (k even)
__device__ __forceinline__ void store_sfrag2(__half* base, int bl, int k, float v0, float v1) {
    int kc = k >> 4, ko = k & 15;
    int mt = bl >> 4, bm = bl & 15;
    int t   = ((bm & 7) << 2) | ((ko & 7) >> 1);
    int reg = ((bm >> 3) & 1) | (((ko >> 3) & 1) << 1);
    int idx = ((kc * 4 + mt) * 32 + t) * 8 + reg * 2;
    *(__half2*)&base[idx] = __floats2half2_rn(v0, v1);
}

#define MMA_F16(acc, A, b0, b1) asm volatile( \
    "mma.sync.aligned.m16n8k16.row.col.f32.f16.f16.f32 " \
    "{%0,%1,%2,%3},{%4,%5,%6,%7},{%8,%9},{%0,%1,%2,%3};" \
    : "+f"(acc[0]), "+f"(acc[1]), "+f"(acc[2]), "+f"(acc[3]) \
    : "r"(A.x), "r"(A.y), "r"(A.z), "r"(A.w), "r"(b0), "r"(b1))

#define BAR1() asm volatile("bar.sync 1, 256;" ::: "memory")

// ---- distributed-flag grid barrier ----
__device__ __forceinline__ void grid_bar(int epoch) {
    const unsigned tgt = (unsigned)(epoch + 1);
    __syncthreads();
    if (threadIdx.x == 0) {
        asm volatile("st.release.gpu.u32 [%0], %1;"
                     :: "l"(&g_flags[blockIdx.x * 32]), "r"(tgt) : "memory");
    }
    if (threadIdx.x < NBLK) {
        unsigned v;
        do {
            asm volatile("ld.acquire.gpu.u32 %0, [%1];"
                         : "=r"(v) : "l"(&g_flags[threadIdx.x * 32]) : "memory");
        } while (v < tgt);
    }
    __syncthreads();
}

__device__ __forceinline__ float wval(int n, int k,
        const float* Whh, const float* Wih, const float* Dw, const float* Aw) {
    if (n < NG)        return (k < NH) ? Whh[n*NH + k] : Wih[n*(NIN+NSW) + (k-NH)];
    if (n < NG + NSW)  return (k < NH) ? Dw[(n-NG)*NH + k] : 0.f;
    if (n < NTOT)      return (k < NH) ? Aw[(n-NG-NSW)*NH + k] : 0.f;
    return 0.f;
}

// ================= persistent kernel =================
__global__ void __launch_bounds__(NTHR, 1) rnn_persist(
    const float* __restrict__ x, const float* __restrict__ h0,
    float* __restrict__ outs, const float* __restrict__ Wih,
    const float* __restrict__ Whh, const float* __restrict__ Dw,
    const float* __restrict__ Aw,  const float* __restrict__ bih,
    const float* __restrict__ bhh, const float* __restrict__ Db,
    const float* __restrict__ Ab) {
    extern __shared__ char smem[];
    const int tid = threadIdx.x, bx = blockIdx.x;
    const int lane = tid & 31, w = tid >> 5;
    const int gtid = bx * NTHR + tid;

    // ---------- setup ----------
    {
        const long long WTOT = 70LL * WSLICE_H;
        for (long long i = gtid; i < WTOT; i += GSTRIDE) {
            int s = (int)(i / WSLICE_H);
            int j = (int)(i - (long long)s * WSLICE_H);
            int sub = j & 7, lane2 = (j >> 3) & 31, nh2 = (j >> 8) & 1, kc = j >> 9;
            int nt = nh2 * 2 + (sub >> 2);
            int jj = sub & 3;
            int nrow = s * 32 + nt * 8 + (lane2 >> 2);
            int kk = kc * 16 + (lane2 & 3) * 2 + ((jj >> 1) << 3) + (jj & 1);
            g_Wfrag[i] = __float2half(wval(nrow, kk, Whh, Wih, Dw, Aw));
        }
        for (int i = gtid; i < 32 * WS_H; i += GSTRIDE) {
            int s = i >> 13, j = i & (WS_H - 1);
            int sub = j & 7, lane2 = (j >> 3) & 31, ntp = (j >> 8) & 3, kc = j >> 10;
            int nt = ntp * 2 + (sub >> 2);
            int jj = sub & 3;
            int col = nt * 8 + (lane2 >> 2);
            int g = col >> 4, uu = col & 15;
            int jrow = g * NH + s * 16 + uu;
            int kk = kc * 16 + (lane2 & 3) * 2 + ((jj >> 1) << 3) + (jj & 1);
            g_WSfrag[i] = __float2half(Wih[jrow * (NIN + NSW) + NIN + kk]);
        }
        if (gtid < NROWS) {
            float b = 0.f;
            if (gtid < NG)          b = bih[gtid] + bhh[gtid];
            else if (gtid < NG+NSW) b = Db[gtid-NG];
            else if (gtid < NTOT)   b = Ab[gtid-NG-NSW];
            g_bz[gtid] = b;
        }
        for (int i = gtid; i < NB * NH; i += GSTRIDE)
            store_zfrag(i >> 9, i & 511, h0[i]);
        for (int i = gtid; i < NB * NIN; i += GSTRIDE)
            store_zfrag(i >> 8, 512 + (i & 255), x[i]);
    }
    grid_bar(0);

    const int nT = bx % 70, mT = bx / 70;
    const int n0 = nT * 32;
    const int wl = w & 7, nh = w >> 3;
    const int mtile = mT * 8 + wl;

    // load resident phase-A W slice (48 KB)
    {
        const uint4* src = (const uint4*)(g_Wfrag + (size_t)nT * WSLICE_H);
        uint4* dst = (uint4*)(smem + SMW);
#pragma unroll
        for (int i = 0; i < 6; i++) {
            uint4 v; const uint4* p = src + tid + i * NTHR;
            asm volatile("ld.global.cg.v4.u32 {%0,%1,%2,%3}, [%4];"
                         : "=r"(v.x), "=r"(v.y), "=r"(v.z), "=r"(v.w) : "l"(p));
            dst[tid + i * NTHR] = v;
        }
    }
    if (bx < 128) {
        const uint4* src = (const uint4*)(g_WSfrag + (size_t)(bx & 31) * WS_H);
        uint4* dst = (uint4*)(smem + SMWS);
#pragma unroll
        for (int i = 0; i < 2; i++) {
            uint4 v; const uint4* p = src + tid + i * NTHR;
            asm volatile("ld.global.cg.v4.u32 {%0,%1,%2,%3}, [%4];"
                         : "=r"(v.x), "=r"(v.y), "=r"(v.z), "=r"(v.w) : "l"(p));
            dst[tid + i * NTHR] = v;
        }
    }
    __syncthreads();

    const char* pB = smem + SMW + lane * 16;
    const char* pA = (const char*)g_Zfrag + mtile * 512 + lane * 16;
    __half* Sfrag  = (__half*)(smem + SMSF);
    float*  gates_s = (float*)(smem + SMGT);
    float*  cfs    = (float*)(smem + SMCF);   // [3][256]

    // phase A epilogue constants
    const int er = lane >> 2, ec2 = (lane & 3) << 1;
    const int eb0 = mT * 128 + wl * 16 + er;
    float bzv[2][2];
#pragma unroll
    for (int q = 0; q < 2; q++) {
        int col = n0 + (nh * 2 + q) * 8 + ec2;
        bzv[q][0] = g_bz[col]; bzv[q][1] = g_bz[col + 1];
    }

    int ep = 1;
    for (int t = 0; t < SEQT; t++) {
        // ======== phase A: single-pass fp16 MMA, even/odd accumulator chains ========
        {
            float acc[2][4], acc2[2][4];
#pragma unroll
            for (int q = 0; q < 2; q++)
#pragma unroll
                for (int r = 0; r < 4; r++) { acc[q][r] = 0.f; acc2[q][r] = 0.f; }

            uint4 ab[8];
#pragma unroll
            for (int p = 0; p < 8; p++)
                ab[p] = __ldcg((const uint4*)(pA + p * 8192));

            for (int kc = 0; kc < NKC; kc += 2) {
                uint4 A0 = ab[kc & 7];
                if (kc < NKC - 8)
                    ab[kc & 7] = __ldcg((const uint4*)(pA + (kc + 8) * 8192));
                uint4 wv0 = *(const uint4*)(pB + ((kc * 2 + nh) << 9));
                MMA_F16(acc[0], A0, wv0.x, wv0.y);
                MMA_F16(acc[1], A0, wv0.z, wv0.w);

                uint4 A1 = ab[(kc + 1) & 7];
                if (kc + 1 < NKC - 8)
                    ab[(kc + 1) & 7] = __ldcg((const uint4*)(pA + (kc + 9) * 8192));
                uint4 wv1 = *(const uint4*)(pB + (((kc + 1) * 2 + nh) << 9));
                MMA_F16(acc2[0], A1, wv1.x, wv1.y);
                MMA_F16(acc2[1], A1, wv1.z, wv1.w);
            }
#pragma unroll
            for (int q = 0; q < 2; q++)
#pragma unroll
                for (int r = 0; r < 4; r++) acc[q][r] += acc2[q][r];

            if (nT < 64) {
#pragma unroll
                for (int q = 0; q < 2; q++) {
                    int col = n0 + (nh * 2 + q) * 8 + ec2;
                    float2 v0 = make_float2(acc[q][0] + bzv[q][0], acc[q][1] + bzv[q][1]);
                    float2 v1 = make_float2(acc[q][2] + bzv[q][0], acc[q][3] + bzv[q][1]);
                    *(float2*)&g_G1[(size_t)eb0 * NG + col] = v0;
                    *(float2*)&g_G1[(size_t)(eb0 + 8) * NG + col] = v1;
                }
            } else if (nT < 68) {
#pragma unroll
                for (int q = 0; q < 2; q++) {
                    int dcol = n0 - NG + (nh * 2 + q) * 8 + ec2;
                    g_dv[eb0 * NSW + dcol]           = tanhf(acc[q][0] + bzv[q][0]);
                    g_dv[eb0 * NSW + dcol + 1]       = tanhf(acc[q][1] + bzv[q][1]);
                    g_dv[(eb0 + 8) * NSW + dcol]     = tanhf(acc[q][2] + bzv[q][0]);
                    g_dv[(eb0 + 8) * NSW + dcol + 1] = tanhf(acc[q][3] + bzv[q][1]);
                }
            } else if (nT == 68) {
                if (nh == 0) {
                    if (ec2 < 3) {
                        g_ctrl[eb0 * 3 + ec2]       = acc[0][0] + bzv[0][0];
                        g_ctrl[(eb0 + 8) * 3 + ec2] = acc[0][2] + bzv[0][0];
                    }
                    if (ec2 + 1 < 3) {
                        g_ctrl[eb0 * 3 + ec2 + 1]       = acc[0][1] + bzv[0][1];
                        g_ctrl[(eb0 + 8) * 3 + ec2 + 1] = acc[0][3] + bzv[0][1];
                    }
                }
                // producer-side softmax: ctrl -> g_cf (visible intra-block after syncthreads)
                __syncthreads();
                if (tid < 128) {
                    int b = mT * 128 + tid;
                    float l0 = g_ctrl[b*3+0], l1 = g_ctrl[b*3+1], l2 = g_ctrl[b*3+2];
                    float mx = fmaxf(l0, fmaxf(l1, l2));
                    float e0 = expf(l0-mx), e1 = expf(l1-mx), e2 = expf(l2-mx);
                    float inv = 1.f / (e0+e1+e2);
                    g_cf[b] = e0*inv; g_cf[256+b] = e1*inv; g_cf[512+b] = e2*inv;
                }
            }
        }
        grid_bar(ep); ep++;

        // ======== phase B ========
        const float* __restrict__ sold = g_stk[t & 1];
        float* __restrict__ snew = g_stk[(t + 1) & 1];
        float* __restrict__ ht = outs + (size_t)t * NB * NH;

        // load precomputed softmax coefficients (coalesced)
        if (tid < 256) {
            cfs[tid]       = __ldcg(&g_cf[tid]);
            cfs[256 + tid] = __ldcg(&g_cf[256 + tid]);
            cfs[512 + tid] = __ldcg(&g_cf[512 + tid]);
        }
        __syncthreads();

        if (tid < 256) {
            if (bx < 128) {
                const int mb0 = (bx >> 5) << 6;
                const int u0  = (bx & 31) << 4;
                // stack_top -> fp16 A fragments (vectorized: 4 k per thread)
#pragma unroll
                for (int it = 0; it < 8; it++) {
                    int idx = tid + it * 256;
                    int bl = idx >> 5, k4 = (idx & 31) * 4;
                    int b = mb0 + bl;
                    float4 s0 = __ldcg((const float4*)&sold[(b * NSD + 0) * NSW + k4]);
                    float4 s1 = __ldcg((const float4*)&sold[(b * NSD + 1) * NSW + k4]);
                    float4 dd = __ldcg((const float4*)&g_dv[b * NSW + k4]);
                    float no = cfs[512+b], pu = cfs[b], po = cfs[256+b];
                    store_sfrag2(Sfrag, bl, k4,
                                 no * s0.x + pu * dd.x + po * s1.x,
                                 no * s0.y + pu * dd.y + po * s1.y);
                    store_sfrag2(Sfrag, bl, k4 + 2,
                                 no * s0.z + pu * dd.z + po * s1.z,
                                 no * s0.w + pu * dd.w + po * s1.w);
                }
                // hoist LSTM inputs (paired units -> float2): in flight during gates GEMM
                float2 hg[2][4], hc[2];
#pragma unroll
                for (int j = 0; j < 2; j++) {
                    int p = tid + j * 256;
                    int bl = p >> 3, uu2 = p & 7;
                    int b = mb0 + bl, u = u0 + uu2 * 2;
                    hg[j][0] = __ldcg((const float2*)&g_G1[(size_t)b * NG + u]);
                    hg[j][1] = __ldcg((const float2*)&g_G1[(size_t)b * NG + NH + u]);
                    hg[j][2] = __ldcg((const float2*)&g_G1[(size_t)b * NG + 2 * NH + u]);
                    hg[j][3] = __ldcg((const float2*)&g_G1[(size_t)b * NG + 3 * NH + u]);
                    hc[j] = *(const float2*)&g_c[b * NH + u];
                }
                BAR1();

                // gates GEMM on tensor pipe: [64x64] = S[64x128] @ Ws^T
                {
                    const int w8 = tid >> 5;
                    const int mt = w8 & 3, np = (w8 >> 2) * 2, ntb = (w8 >> 2) * 4;
                    float acc[4][4];
#pragma unroll
                    for (int q = 0; q < 4; q++)
#pragma unroll
                        for (int r = 0; r < 4; r++) acc[q][r] = 0.f;
#pragma unroll
                    for (int kc = 0; kc < 8; kc++) {
                        uint4 A = *(const uint4*)(smem + SMSF + ((kc * 4 + mt) << 9) + lane * 16);
                        uint4 wv0 = *(const uint4*)(smem + SMWS + (((kc * 4 + np) * 32 + lane) << 4));
                        uint4 wv1 = *(const uint4*)(smem + SMWS + (((kc * 4 + np + 1) * 32 + lane) << 4));
                        MMA_F16(acc[0], A, wv0.x, wv0.y);
                        MMA_F16(acc[1], A, wv0.z, wv0.w);
                        MMA_F16(acc[2], A, wv1.x, wv1.y);
                        MMA_F16(acc[3], A, wv1.z, wv1.w);
                    }
                    const int r0 = mt * 16 + er;
#pragma unroll
                    for (int q = 0; q < 4; q++) {
                        int col = (ntb + q) * 8 + ec2;
                        *(float2*)&gates_s[r0 * 64 + col]       = make_float2(acc[q][0], acc[q][1]);
                        *(float2*)&gates_s[(r0 + 8) * 64 + col] = make_float2(acc[q][2], acc[q][3]);
                    }
                }
                BAR1();

                // LSTM pointwise (paired units)
#pragma unroll
                for (int j = 0; j < 2; j++) {
                    int p = tid + j * 256;
                    int bl = p >> 3, uu2 = p & 7;
                    int b = mb0 + bl, u = u0 + uu2 * 2;
                    float2 gsi = *(const float2*)&gates_s[bl * 64 + uu2 * 2];
                    float2 gsf = *(const float2*)&gates_s[bl * 64 + 16 + uu2 * 2];
                    float2 gsg = *(const float2*)&gates_s[bl * 64 + 32 + uu2 * 2];
                    float2 gso = *(const float2*)&gates_s[bl * 64 + 48 + uu2 * 2];
                    float gi0 = gsi.x + hg[j][0].x, gi1 = gsi.y + hg[j][0].y;
                    float gf0 = gsf.x + hg[j][1].x, gf1 = gsf.y + hg[j][1].y;
                    float gg0 = gsg.x + hg[j][2].x, gg1 = gsg.y + hg[j][2].y;
                    float go0 = gso.x + hg[j][3].x, go1 = gso.y + hg[j][3].y;
                    float cn0 = sigf(gf0) * hc[j].x + sigf(gi0) * tanhf(gg0);
                    float cn1 = sigf(gf1) * hc[j].y + sigf(gi1) * tanhf(gg1);
                    float hh0 = sigf(go0) * tanhf(cn0);
                    float hh1 = sigf(go1) * tanhf(cn1);
                    *(float2*)&g_c[b * NH + u] = make_float2(cn0, cn1);
                    *(float2*)&ht[b * NH + u]  = make_float2(hh0, hh1);
                    store_zfrag2(b, u, hh0, hh1);
                }
            } else {
                if (t + 1 < SEQT) {
                    const float* __restrict__ xn = x + (size_t)(t + 1) * NB * NIN;
                    for (int idx = (bx - 128) * 256 + tid; idx < NB * NIN / 2; idx += 12 * 256) {
                        int b = idx >> 7, k2 = idx & 127;
                        float2 xv = __ldcg((const float2*)&xn[b * NIN + k2 * 2]);
                        store_zfrag2(b, 512 + k2 * 2, xv.x, xv.y);
                    }
                }
            }
        } else {
            // stack blend: depth-run scheme, upper 256 threads of every block
            const int ut = tid - 256;
            const int TOTR = NB * 8 * 32;   // 65536 runs of 8 depths
            int lo_ = (int)((long long)bx * TOTR / NBLK);
            int hi_ = (int)((long long)(bx + 1) * TOTR / NBLK);
            const float4 z4 = make_float4(0.f, 0.f, 0.f, 0.f);
            for (int run = lo_ + ut; run < hi_; run += 256) {
                int ww = run & 31;
                int q = run >> 5;
                int b = q >> 3, dr = q & 7;
                int d0 = dr << 3;
                float pu = cfs[b], po = cfs[256 + b], no = cfs[512 + b];
                const float* cb = &sold[b * NSD * NSW + ww * 4];
                float* ob = &snew[(b * NSD + d0) * NSW + ww * 4];
                float4 v[6];
                v[0] = d0 ? __ldcg((const float4*)(cb + (d0 - 1) * NSW))
                          : __ldcg((const float4*)&g_dv[b * NSW + ww * 4]);
#pragma unroll
                for (int i = 0; i < 5; i++)
                    v[i + 1] = __ldcg((const float4*)(cb + (d0 + i) * NSW));
#pragma unroll
                for (int i = 0; i < 4; i++) {
                    float4 o;
                    o.x = no * v[i+1].x + pu * v[i].x + po * v[i+2].x;
                    o.y = no * v[i+1].y + pu * v[i].y + po * v[i+2].y;
                    o.z = no * v[i+1].z + pu * v[i].z + po * v[i+2].z;
                    o.w = no * v[i+1].w + pu * v[i].w + po * v[i+2].w;
                    *(float4*)(ob + i * NSW) = o;
                }
                v[0] = v[4]; v[1] = v[5];
#pragma unroll
                for (int i = 0; i < 3; i++)
                    v[i + 2] = __ldcg((const float4*)(cb + (d0 + 5 + i) * NSW));
                v[5] = (d0 + 8 < NSD) ? __ldcg((const float4*)(cb + (d0 + 8) * NSW)) : z4;
#pragma unroll
                for (int i = 0; i < 4; i++) {
                    float4 o;
                    o.x = no * v[i+1].x + pu * v[i].x + po * v[i+2].x;
                    o.y = no * v[i+1].y + pu * v[i].y + po * v[i+2].y;
                    o.z = no * v[i+1].z + pu * v[i].z + po * v[i+2].z;
                    o.w = no * v[i+1].w + pu * v[i].w + po * v[i+2].w;
                    *(float4*)(ob + (4 + i) * NSW) = o;
                }
            }
        }
        grid_bar(ep); ep++;
    }
}

// ================= host =================
extern "C" void kernel_launch(void* const* d_in, const int* in_sizes, int n_in,
                              void* d_out, int out_size) {
    const float* x   = (const float*)d_in[0];
    const float* h0  = (const float*)d_in[1];
    const float* c0  = (const float*)d_in[2];
    const float* st0 = (const float*)d_in[3];
    const float* Aw  = (const float*)d_in[4];
    const float* Ab  = (const float*)d_in[5];
    const float* Dw  = (const float*)d_in[6];
    const float* Db  = (const float*)d_in[7];
    const float* Wih = (const float*)d_in[8];
    const float* Whh = (const float*)d_in[9];
    const float* bih = (const float*)d_in[10];
    const float* bhh = (const float*)d_in[11];

    float* outs  = (float*)d_out;
    float* h_out = outs + (size_t)SEQT * NB * NH;
    float* c_out = h_out + (size_t)NB * NH;
    float* s_out = c_out + (size_t)NB * NH;

    float* cbuf;  cudaGetSymbolAddress((void**)&cbuf, g_c);
    float* stbuf; cudaGetSymbolAddress((void**)&stbuf, g_stk);
    unsigned* flagbuf; cudaGetSymbolAddress((void**)&flagbuf, g_flags);

    cudaFuncSetAttribute(rnn_persist, cudaFuncAttributeMaxDynamicSharedMemorySize, SMTOTAL);

    cudaMemcpyAsync(cbuf,  c0,  (size_t)NB * NH * sizeof(float),        cudaMemcpyDeviceToDevice);
    cudaMemcpyAsync(stbuf, st0, (size_t)NB * NSD * NSW * sizeof(float), cudaMemcpyDeviceToDevice);
    cudaMemsetAsync(flagbuf, 0, NBLK * 32 * sizeof(unsigned));

    rnn_persist<<<NBLK, NTHR, SMTOTAL>>>(x, h0, outs, Wih, Whh, Dw, Aw, bih, bhh, Db, Ab);

    const size_t SSZ = (size_t)NB * NSD * NSW;
    cudaMemcpyAsync(h_out, outs + (size_t)(SEQT - 1) * NB * NH,
                    (size_t)NB * NH * sizeof(float), cudaMemcpyDeviceToDevice);
    cudaMemcpyAsync(c_out, cbuf, (size_t)NB * NH * sizeof(float), cudaMemcpyDeviceToDevice);
    cudaMemcpyAsync(s_out, stbuf, SSZ * sizeof(float), cudaMemcpyDeviceToDevice);
}

// round 13
// speedup vs baseline: 5.3994x; 1.1350x over previous
#include <cuda_runtime.h>
#include <cuda_fp16.h>
#include <math.h>
#include <stdint.h>

#define SEQT 1024
#define NB   256
#define NIN  256
#define NH   512
#define NSW  128
#define NSD  64
#define NG   2048            // 4*NH
#define KZ   768             // NH + NIN
#define NROWS 2240
#define NTOT 2179
#define NBLK 140             // 70 N-tiles x 2 M-halves
#define NKC  48              // 768/16
#define NTHR 512
#define GSTRIDE (NBLK * NTHR)

// phase A W fragment slice per nT (fp16): [kc(48)][nh(2)][lane(32)][8 halfs] = 24576 halfs
#define WSLICE_H 24576
// Z fragment: [kc(48)][mtile(16)][lane(32)][8 halfs]
#define ZTOT_H  196608
// phase B W_s fragment slice per u0: [kc(8)][ntp(4)][lane(32)][8 halfs]
#define WS_H 8192

// dynamic smem layout (bytes)
#define SMW     0                  // 49152: phase A W fragments
#define SMWS    49152              // 16384: phase B W_s fragments
#define SMSF    65536              // 16384: stack_top fp16 A fragments
#define SMGT    81920              // 16384: gates f32 [64][64]
#define SMCF    98304              // 3072:  cf[3][256] current step
#define SMCFO   101376             // 3072:  cf[3][256] previous step (blend)
#define SMTOTAL 104448

// ---- device scratch ----
__device__ __half g_Wfrag[70 * WSLICE_H];
__device__ __half g_WSfrag[32 * WS_H];
__device__ __half g_Zfrag[ZTOT_H];
__device__ float g_bz[NROWS];
__device__ float g_G1[NB * NG];
__device__ float g_dv[2][NB * NSW];   // double-buffered (blend lags one step)
__device__ float g_ctrl[NB * 3];
__device__ float g_cf[2][3 * NB];     // double-buffered softmax coefficients
__device__ float g_c[NB * NH];
__device__ float g_stk[2][NB * NSD * NSW];
__device__ unsigned g_flags[NBLK * 32];

// ---- helpers ----
__device__ __forceinline__ float sigf(float x) { return 1.f / (1.f + expf(-x)); }
__device__ __forceinline__ void store_zfrag(int b, int kk, float v) {
    int kc = kk >> 4, ko = kk & 15;
    int t   = ((b & 7) << 2) | ((ko & 7) >> 1);
    int reg = ((b >> 3) & 1) | (((ko >> 3) & 1) << 1);
    int idx = ((kc * 16 + (b >> 4)) * 32 + t) * 8 + reg * 2 + (ko & 1);
    g_Zfrag[idx] = __float2half(v);
}
__device__ __forceinline__ void store_zfrag2(int b, int kk, float v0, float v1) {
    int kc = kk >> 4, ko = kk & 15;
    int t   = ((b & 7) << 2) | ((ko & 7) >> 1);
    int reg = ((b >> 3) & 1) | (((ko >> 3) & 1) << 1);
    int idx = ((kc * 16 + (b >> 4)) * 32 + t) * 8 + reg * 2;
    *(__half2*)&g_Zfrag[idx] = __floats2half2_rn(v0, v1);
}
__device__ __forceinline__ void store_sfrag2(__half* base, int bl, int k, float v0, float v1) {
    int kc = k >> 4, ko = k & 15;
    int mt = bl >> 4, bm = bl & 15;
    int t   = ((bm & 7) << 2) | ((ko & 7) >> 1);
    int reg = ((bm >> 3) & 1) | (((ko >> 3) & 1) << 1);
    int idx = ((kc * 4 + mt) * 32 + t) * 8 + reg * 2;
    *(__half2*)&base[idx] = __floats2half2_rn(v0, v1);
}

#define MMA_F16(acc, A, b0, b1) asm volatile( \
    "mma.sync.aligned.m16n8k16.row.col.f32.f16.f16.f32 " \
    "{%0,%1,%2,%3},{%4,%5,%6,%7},{%8,%9},{%0,%1,%2,%3};" \
    : "+f"(acc[0]), "+f"(acc[1]), "+f"(acc[2]), "+f"(acc[3]) \
    : "r"(A.x), "r"(A.y), "r"(A.z), "r"(A.w), "r"(b0), "r"(b1))

#define BAR1() asm volatile("bar.sync 1, 256;" ::: "memory")   // lower 256
#define BAR2() asm volatile("bar.sync 2, 256;" ::: "memory")   // lower 256 (ctrl)
#define BAR3() asm volatile("bar.sync 3, 256;" ::: "memory")   // upper 256 (blend cf)

// ---- distributed-flag grid barrier ----
__device__ __forceinline__ void grid_bar(int epoch) {
    const unsigned tgt = (unsigned)(epoch + 1);
    __syncthreads();
    if (threadIdx.x == 0) {
        asm volatile("st.release.gpu.u32 [%0], %1;"
                     :: "l"(&g_flags[blockIdx.x * 32]), "r"(tgt) : "memory");
    }
    if (threadIdx.x < NBLK) {
        unsigned v;
        do {
            asm volatile("ld.acquire.gpu.u32 %0, [%1];"
                         : "=r"(v) : "l"(&g_flags[threadIdx.x * 32]) : "memory");
        } while (v < tgt);
    }
    __syncthreads();
}

__device__ __forceinline__ float wval(int n, int k,
        const float* Whh, const float* Wih, const float* Dw, const float* Aw) {
    if (n < NG)        return (k < NH) ? Whh[n*NH + k] : Wih[n*(NIN+NSW) + (k-NH)];
    if (n < NG + NSW)  return (k < NH) ? Dw[(n-NG)*NH + k] : 0.f;
    if (n < NTOT)      return (k < NH) ? Aw[(n-NG-NSW)*NH + k] : 0.f;
    return 0.f;
}

// blend(tb): stk[tb&1] -> stk[(tb+1)&1] using cf(tb), dv(tb). Upper 256 threads.
__device__ __forceinline__ void run_blend(int tb, int bx, int ut, const float* cfo) {
    const float* __restrict__ sold = g_stk[tb & 1];
    float* __restrict__ snew = g_stk[(tb + 1) & 1];
    const float* __restrict__ dvO = g_dv[tb & 1];
    const int TOTR = NB * 8 * 32;
    int lo_ = (int)((long long)bx * TOTR / NBLK);
    int hi_ = (int)((long long)(bx + 1) * TOTR / NBLK);
    const float4 z4 = make_float4(0.f, 0.f, 0.f, 0.f);
    for (int run = lo_ + ut; run < hi_; run += 256) {
        int ww = run & 31;
        int q = run >> 5;
        int b = q >> 3, dr = q & 7;
        int d0 = dr << 3;
        float pu = cfo[b], po = cfo[256 + b], no = cfo[512 + b];
        const float* cb = &sold[b * NSD * NSW + ww * 4];
        float* ob = &snew[(b * NSD + d0) * NSW + ww * 4];
        float4 v[6];
        v[0] = d0 ? __ldcg((const float4*)(cb + (d0 - 1) * NSW))
                  : __ldcg((const float4*)&dvO[b * NSW + ww * 4]);
#pragma unroll
        for (int i = 0; i < 5; i++)
            v[i + 1] = __ldcg((const float4*)(cb + (d0 + i) * NSW));
#pragma unroll
        for (int i = 0; i < 4; i++) {
            float4 o;
            o.x = no * v[i+1].x + pu * v[i].x + po * v[i+2].x;
            o.y = no * v[i+1].y + pu * v[i].y + po * v[i+2].y;
            o.z = no * v[i+1].z + pu * v[i].z + po * v[i+2].z;
            o.w = no * v[i+1].w + pu * v[i].w + po * v[i+2].w;
            *(float4*)(ob + i * NSW) = o;
        }
        v[0] = v[4]; v[1] = v[5];
#pragma unroll
        for (int i = 0; i < 3; i++)
            v[i + 2] = __ldcg((const float4*)(cb + (d0 + 5 + i) * NSW));
        v[5] = (d0 + 8 < NSD) ? __ldcg((const float4*)(cb + (d0 + 8) * NSW)) : z4;
#pragma unroll
        for (int i = 0; i < 4; i++) {
            float4 o;
            o.x = no * v[i+1].x + pu * v[i].x + po * v[i+2].x;
            o.y = no * v[i+1].y + pu * v[i].y + po * v[i+2].y;
            o.z = no * v[i+1].z + pu * v[i].z + po * v[i+2].z;
            o.w = no * v[i+1].w + pu * v[i].w + po * v[i+2].w;
            *(float4*)(ob + (4 + i) * NSW) = o;
        }
    }
}

// ================= persistent kernel =================
__global__ void __launch_bounds__(NTHR, 1) rnn_persist(
    const float* __restrict__ x, const float* __restrict__ h0,
    float* __restrict__ outs, const float* __restrict__ Wih,
    const float* __restrict__ Whh, const float* __restrict__ Dw,
    const float* __restrict__ Aw,  const float* __restrict__ bih,
    const float* __restrict__ bhh, const float* __restrict__ Db,
    const float* __restrict__ Ab) {
    extern __shared__ char smem[];
    const int tid = threadIdx.x, bx = blockIdx.x;
    const int lane = tid & 31, w = tid >> 5;
    const int gtid = bx * NTHR + tid;

    // ---------- setup ----------
    {
        const long long WTOT = 70LL * WSLICE_H;
        for (long long i = gtid; i < WTOT; i += GSTRIDE) {
            int s = (int)(i / WSLICE_H);
            int j = (int)(i - (long long)s * WSLICE_H);
            int sub = j & 7, lane2 = (j >> 3) & 31, nh2 = (j >> 8) & 1, kc = j >> 9;
            int nt = nh2 * 2 + (sub >> 2);
            int jj = sub & 3;
            int nrow = s * 32 + nt * 8 + (lane2 >> 2);
            int kk = kc * 16 + (lane2 & 3) * 2 + ((jj >> 1) << 3) + (jj & 1);
            g_Wfrag[i] = __float2half(wval(nrow, kk, Whh, Wih, Dw, Aw));
        }
        for (int i = gtid; i < 32 * WS_H; i += GSTRIDE) {
            int s = i >> 13, j = i & (WS_H - 1);
            int sub = j & 7, lane2 = (j >> 3) & 31, ntp = (j >> 8) & 3, kc = j >> 10;
            int nt = ntp * 2 + (sub >> 2);
            int jj = sub & 3;
            int col = nt * 8 + (lane2 >> 2);
            int g = col >> 4, uu = col & 15;
            int jrow = g * NH + s * 16 + uu;
            int kk = kc * 16 + (lane2 & 3) * 2 + ((jj >> 1) << 3) + (jj & 1);
            g_WSfrag[i] = __float2half(Wih[jrow * (NIN + NSW) + NIN + kk]);
        }
        if (gtid < NROWS) {
            float b = 0.f;
            if (gtid < NG)          b = bih[gtid] + bhh[gtid];
            else if (gtid < NG+NSW) b = Db[gtid-NG];
            else if (gtid < NTOT)   b = Ab[gtid-NG-NSW];
            g_bz[gtid] = b;
        }
        for (int i = gtid; i < NB * NH; i += GSTRIDE)
            store_zfrag(i >> 9, i & 511, h0[i]);
        for (int i = gtid; i < NB * NIN; i += GSTRIDE)
            store_zfrag(i >> 8, 512 + (i & 255), x[i]);
    }
    grid_bar(0);

    const int nT = bx % 70, mT = bx / 70;
    const int n0 = nT * 32;
    const int mtile = mT * 8 + (w & 7);

    // load resident phase-A W slice (48 KB)
    {
        const uint4* src = (const uint4*)(g_Wfrag + (size_t)nT * WSLICE_H);
        uint4* dst = (uint4*)(smem + SMW);
#pragma unroll
        for (int i = 0; i < 6; i++) {
            uint4 v; const uint4* p = src + tid + i * NTHR;
            asm volatile("ld.global.cg.v4.u32 {%0,%1,%2,%3}, [%4];"
                         : "=r"(v.x), "=r"(v.y), "=r"(v.z), "=r"(v.w) : "l"(p));
            dst[tid + i * NTHR] = v;
        }
    }
    if (bx < 128) {
        const uint4* src = (const uint4*)(g_WSfrag + (size_t)(bx & 31) * WS_H);
        uint4* dst = (uint4*)(smem + SMWS);
#pragma unroll
        for (int i = 0; i < 2; i++) {
            uint4 v; const uint4* p = src + tid + i * NTHR;
            asm volatile("ld.global.cg.v4.u32 {%0,%1,%2,%3}, [%4];"
                         : "=r"(v.x), "=r"(v.y), "=r"(v.z), "=r"(v.w) : "l"(p));
            dst[tid + i * NTHR] = v;
        }
    }
    __syncthreads();

    const char* pB = smem + SMW + lane * 16;
    const char* pA = (const char*)g_Zfrag + mtile * 512 + lane * 16;
    __half* Sfrag  = (__half*)(smem + SMSF);
    float*  gates_s = (float*)(smem + SMGT);
    float*  cfs    = (float*)(smem + SMCF);    // current step (gates path)
    float*  cfo    = (float*)(smem + SMCFO);   // previous step (blend path)

    // phase A epilogue constants
    const int er = lane >> 2, ec2 = (lane & 3) << 1;
    const int eb0 = mT * 128 + (w & 7) * 16 + er;
    float bzv[4][2];
#pragma unroll
    for (int q = 0; q < 4; q++) {
        int col = n0 + q * 8 + ec2;
        bzv[q][0] = g_bz[col]; bzv[q][1] = g_bz[col + 1];
    }

    int ep = 1;
    for (int t = 0; t < SEQT; t++) {
        // ======== phase A window: warps 0-7 MMA(t) || warps 8-15 blend(t-1) ========
        if (w < 8) {
            float acc[4][4];
#pragma unroll
            for (int q = 0; q < 4; q++)
#pragma unroll
                for (int r = 0; r < 4; r++) acc[q][r] = 0.f;

            uint4 ab[8];
#pragma unroll
            for (int p = 0; p < 8; p++)
                ab[p] = __ldcg((const uint4*)(pA + p * 8192));

            for (int kc = 0; kc < NKC; kc++) {
                uint4 A = ab[kc & 7];
                if (kc < NKC - 8)
                    ab[kc & 7] = __ldcg((const uint4*)(pA + (kc + 8) * 8192));
                uint4 wv0 = *(const uint4*)(pB + ((kc * 2 + 0) << 9));
                uint4 wv1 = *(const uint4*)(pB + ((kc * 2 + 1) << 9));
                MMA_F16(acc[0], A, wv0.x, wv0.y);
                MMA_F16(acc[1], A, wv0.z, wv0.w);
                MMA_F16(acc[2], A, wv1.x, wv1.y);
                MMA_F16(acc[3], A, wv1.z, wv1.w);
            }

            if (nT < 64) {
#pragma unroll
                for (int q = 0; q < 4; q++) {
                    int col = n0 + q * 8 + ec2;
                    float2 v0 = make_float2(acc[q][0] + bzv[q][0], acc[q][1] + bzv[q][1]);
                    float2 v1 = make_float2(acc[q][2] + bzv[q][0], acc[q][3] + bzv[q][1]);
                    *(float2*)&g_G1[(size_t)eb0 * NG + col] = v0;
                    *(float2*)&g_G1[(size_t)(eb0 + 8) * NG + col] = v1;
                }
            } else if (nT < 68) {
                float* dvC = g_dv[t & 1];
#pragma unroll
                for (int q = 0; q < 4; q++) {
                    int dcol = n0 - NG + q * 8 + ec2;
                    dvC[eb0 * NSW + dcol]           = tanhf(acc[q][0] + bzv[q][0]);
                    dvC[eb0 * NSW + dcol + 1]       = tanhf(acc[q][1] + bzv[q][1]);
                    dvC[(eb0 + 8) * NSW + dcol]     = tanhf(acc[q][2] + bzv[q][0]);
                    dvC[(eb0 + 8) * NSW + dcol + 1] = tanhf(acc[q][3] + bzv[q][1]);
                }
            } else if (nT == 68) {
                if (ec2 < 3) {
                    g_ctrl[eb0 * 3 + ec2]       = acc[0][0] + bzv[0][0];
                    g_ctrl[(eb0 + 8) * 3 + ec2] = acc[0][2] + bzv[0][0];
                }
                if (ec2 + 1 < 3) {
                    g_ctrl[eb0 * 3 + ec2 + 1]       = acc[0][1] + bzv[0][1];
                    g_ctrl[(eb0 + 8) * 3 + ec2 + 1] = acc[0][3] + bzv[0][1];
                }
                BAR2();
                if (tid < 128) {
                    int b = mT * 128 + tid;
                    float l0 = g_ctrl[b*3+0], l1 = g_ctrl[b*3+1], l2 = g_ctrl[b*3+2];
                    float mx = fmaxf(l0, fmaxf(l1, l2));
                    float e0 = expf(l0-mx), e1 = expf(l1-mx), e2 = expf(l2-mx);
                    float inv = 1.f / (e0+e1+e2);
                    float* cfC = g_cf[t & 1];
                    cfC[b] = e0*inv; cfC[256+b] = e1*inv; cfC[512+b] = e2*inv;
                }
            }
        } else if (t > 0) {
            // blend(t-1), overlapped with MMA(t)
            const int ut = tid - 256;
            const float* cfP = g_cf[(t - 1) & 1];
            cfo[ut]       = __ldcg(&cfP[ut]);
            cfo[256 + ut] = __ldcg(&cfP[256 + ut]);
            cfo[512 + ut] = __ldcg(&cfP[512 + ut]);
            BAR3();
            run_blend(t - 1, bx, ut, cfo);
        }
        grid_bar(ep); ep++;

        // ======== phase B: gates path (lower) || x-convert(t+1) (upper) ========
        float* __restrict__ ht = outs + (size_t)t * NB * NH;

        if (tid < 256) {
            if (bx < 128) {
                const float* __restrict__ sold = g_stk[t & 1];
                const float* __restrict__ dvC = g_dv[t & 1];
                const float* __restrict__ cfC = g_cf[t & 1];
                const int mb0 = (bx >> 5) << 6;
                const int u0  = (bx & 31) << 4;
                cfs[tid]       = __ldcg(&cfC[tid]);
                cfs[256 + tid] = __ldcg(&cfC[256 + tid]);
                cfs[512 + tid] = __ldcg(&cfC[512 + tid]);
                BAR1();
                // stack_top -> fp16 A fragments (4 k per thread)
#pragma unroll
                for (int it = 0; it < 8; it++) {
                    int idx = tid + it * 256;
                    int bl = idx >> 5, k4 = (idx & 31) * 4;
                    int b = mb0 + bl;
                    float4 s0 = __ldcg((const float4*)&sold[(b * NSD + 0) * NSW + k4]);
                    float4 s1 = __ldcg((const float4*)&sold[(b * NSD + 1) * NSW + k4]);
                    float4 dd = __ldcg((const float4*)&dvC[b * NSW + k4]);
                    float no = cfs[512+b], pu = cfs[b], po = cfs[256+b];
                    store_sfrag2(Sfrag, bl, k4,
                                 no * s0.x + pu * dd.x + po * s1.x,
                                 no * s0.y + pu * dd.y + po * s1.y);
                    store_sfrag2(Sfrag, bl, k4 + 2,
                                 no * s0.z + pu * dd.z + po * s1.z,
                                 no * s0.w + pu * dd.w + po * s1.w);
                }
                // hoist LSTM inputs
                float2 hg[2][4], hc[2];
#pragma unroll
                for (int j = 0; j < 2; j++) {
                    int p = tid + j * 256;
                    int bl = p >> 3, uu2 = p & 7;
                    int b = mb0 + bl, u = u0 + uu2 * 2;
                    hg[j][0] = __ldcg((const float2*)&g_G1[(size_t)b * NG + u]);
                    hg[j][1] = __ldcg((const float2*)&g_G1[(size_t)b * NG + NH + u]);
                    hg[j][2] = __ldcg((const float2*)&g_G1[(size_t)b * NG + 2 * NH + u]);
                    hg[j][3] = __ldcg((const float2*)&g_G1[(size_t)b * NG + 3 * NH + u]);
                    hc[j] = *(const float2*)&g_c[b * NH + u];
                }
                BAR1();

                // gates GEMM on tensor pipe
                {
                    const int w8 = tid >> 5;
                    const int mt = w8 & 3, np = (w8 >> 2) * 2, ntb = (w8 >> 2) * 4;
                    float acc[4][4];
#pragma unroll
                    for (int q = 0; q < 4; q++)
#pragma unroll
                        for (int r = 0; r < 4; r++) acc[q][r] = 0.f;
#pragma unroll
                    for (int kc = 0; kc < 8; kc++) {
                        uint4 A = *(const uint4*)(smem + SMSF + ((kc * 4 + mt) << 9) + lane * 16);
                        uint4 wv0 = *(const uint4*)(smem + SMWS + (((kc * 4 + np) * 32 + lane) << 4));
                        uint4 wv1 = *(const uint4*)(smem + SMWS + (((kc * 4 + np + 1) * 32 + lane) << 4));
                        MMA_F16(acc[0], A, wv0.x, wv0.y);
                        MMA_F16(acc[1], A, wv0.z, wv0.w);
                        MMA_F16(acc[2], A, wv1.x, wv1.y);
                        MMA_F16(acc[3], A, wv1.z, wv1.w);
                    }
                    const int r0 = mt * 16 + er;
#pragma unroll
                    for (int q = 0; q < 4; q++) {
                        int col = (ntb + q) * 8 + ec2;
                        *(float2*)&gates_s[r0 * 64 + col]       = make_float2(acc[q][0], acc[q][1]);
                        *(float2*)&gates_s[(r0 + 8) * 64 + col] = make_float2(acc[q][2], acc[q][3]);
                    }
                }
                BAR1();

                // LSTM pointwise (paired units)
#pragma unroll
                for (int j = 0; j < 2; j++) {
                    int p = tid + j * 256;
                    int bl = p >> 3, uu2 = p & 7;
                    int b = mb0 + bl, u = u0 + uu2 * 2;
                    float2 gsi = *(const float2*)&gates_s[bl * 64 + uu2 * 2];
                    float2 gsf = *(const float2*)&gates_s[bl * 64 + 16 + uu2 * 2];
                    float2 gsg = *(const float2*)&gates_s[bl * 64 + 32 + uu2 * 2];
                    float2 gso = *(const float2*)&gates_s[bl * 64 + 48 + uu2 * 2];
                    float gi0 = gsi.x + hg[j][0].x, gi1 = gsi.y + hg[j][0].y;
                    float gf0 = gsf.x + hg[j][1].x, gf1 = gsf.y + hg[j][1].y;
                    float gg0 = gsg.x + hg[j][2].x, gg1 = gsg.y + hg[j][2].y;
                    float go0 = gso.x + hg[j][3].x, go1 = gso.y + hg[j][3].y;
                    float cn0 = sigf(gf0) * hc[j].x + sigf(gi0) * tanhf(gg0);
                    float cn1 = sigf(gf1) * hc[j].y + sigf(gi1) * tanhf(gg1);
                    float hh0 = sigf(go0) * tanhf(cn0);
                    float hh1 = sigf(go1) * tanhf(cn1);
                    *(float2*)&g_c[b * NH + u] = make_float2(cn0, cn1);
                    *(float2*)&ht[b * NH + u]  = make_float2(hh0, hh1);
                    store_zfrag2(b, u, hh0, hh1);
                }
            }
        } else {
            // x conversion for t+1, spread across all blocks' upper halves
            if (t + 1 < SEQT) {
                int idx = bx * 256 + (tid - 256);
                if (idx < NB * NIN / 2) {
                    const float* __restrict__ xn = x + (size_t)(t + 1) * NB * NIN;
                    int b = idx >> 7, k2 = idx & 127;
                    float2 xv = __ldcg((const float2*)&xn[b * NIN + k2 * 2]);
                    store_zfrag2(b, 512 + k2 * 2, xv.x, xv.y);
                }
            }
        }
        grid_bar(ep); ep++;
    }

    // final blend(SEQT-1): stk[1] -> stk[0]
    if (tid >= 256) {
        const int ut = tid - 256;
        const float* cfP = g_cf[(SEQT - 1) & 1];
        cfo[ut]       = __ldcg(&cfP[ut]);
        cfo[256 + ut] = __ldcg(&cfP[256 + ut]);
        cfo[512 + ut] = __ldcg(&cfP[512 + ut]);
        BAR3();
        run_blend(SEQT - 1, bx, ut, cfo);
    }
}

// ================= host =================
extern "C" void kernel_launch(void* const* d_in, const int* in_sizes, int n_in,
                              void* d_out, int out_size) {
    const float* x   = (const float*)d_in[0];
    const float* h0  = (const float*)d_in[1];
    const float* c0  = (const float*)d_in[2];
    const float* st0 = (const float*)d_in[3];
    const float* Aw  = (const float*)d_in[4];
    const float* Ab  = (const float*)d_in[5];
    const float* Dw  = (const float*)d_in[6];
    const float* Db  = (const float*)d_in[7];
    const float* Wih = (const float*)d_in[8];
    const float* Whh = (const float*)d_in[9];
    const float* bih = (const float*)d_in[10];
    const float* bhh = (const float*)d_in[11];

    float* outs  = (float*)d_out;
    float* h_out = outs + (size_t)SEQT * NB * NH;
    float* c_out = h_out + (size_t)NB * NH;
    float* s_out = c_out + (size_t)NB * NH;

    float* cbuf;  cudaGetSymbolAddress((void**)&cbuf, g_c);
    float* stbuf; cudaGetSymbolAddress((void**)&stbuf, g_stk);
    unsigned* flagbuf; cudaGetSymbolAddress((void**)&flagbuf, g_flags);

    cudaFuncSetAttribute(rnn_persist, cudaFuncAttributeMaxDynamicSharedMemorySize, SMTOTAL);

    cudaMemcpyAsync(cbuf,  c0,  (size_t)NB * NH * sizeof(float),        cudaMemcpyDeviceToDevice);
    cudaMemcpyAsync(stbuf, st0, (size_t)NB * NSD * NSW * sizeof(float), cudaMemcpyDeviceToDevice);
    cudaMemsetAsync(flagbuf, 0, NBLK * 32 * sizeof(unsigned));

    rnn_persist<<<NBLK, NTHR, SMTOTAL>>>(x, h0, outs, Wih, Whh, Dw, Aw, bih, bhh, Db, Ab);

    const size_t SSZ = (size_t)NB * NSD * NSW;
    cudaMemcpyAsync(h_out, outs + (size_t)(SEQT - 1) * NB * NH,
                    (size_t)NB * NH * sizeof(float), cudaMemcpyDeviceToDevice);
    cudaMemcpyAsync(c_out, cbuf, (size_t)NB * NH * sizeof(float), cudaMemcpyDeviceToDevice);
    cudaMemcpyAsync(s_out, stbuf, SSZ * sizeof(float), cudaMemcpyDeviceToDevice);
}